// round 1
// baseline (speedup 1.0000x reference)
#include <cuda_runtime.h>
#include <cuda_bf16.h>
#include <cstdint>

#define N_NODES 50000
#define E_RAW   800000
#define E_TOT   (E_RAW + N_NODES)   // 850000 with self loops
#define MAXH    4
#define MAXHC   256

// ---------------- device scratch (static, allocation-free) ----------------
__device__ float g_xp[(size_t)N_NODES * MAXHC];  // per-layer transformed features
__device__ float g_h [(size_t)N_NODES * MAXHC];  // layer output / next input
__device__ float g_s [(size_t)N_NODES * MAXH];
__device__ float g_d [(size_t)N_NODES * MAXH];
__device__ float g_m [(size_t)N_NODES * MAXH];
__device__ float g_z [(size_t)N_NODES * MAXH];
__device__ float g_e [(size_t)E_TOT   * MAXH];   // edge scores -> exp weights

// ---------------- helpers ----------------
__device__ __forceinline__ void atomicMaxFloat(float* addr, float value) {
    if (value >= 0.f)
        atomicMax((int*)addr, __float_as_int(value));
    else
        atomicMin((unsigned int*)addr, __float_as_uint(value));
}

// ---------------- GEMM: C = A(MxK) * B(KxN), all row-major fp32 ----------------
// BM=128, BN=64, BK=16, 256 threads, 8x4 per-thread tile.
__global__ void gemm_kernel(const float* __restrict__ A, const float* __restrict__ B,
                            float* __restrict__ C, int M, int N, int K) {
    const int BM = 128, BN = 64, BK = 16, TM = 8, TN = 4;
    __shared__ float As[BK][BM + 4];
    __shared__ float Bs[BK][BN];
    int tid = threadIdx.x;
    int block_row = blockIdx.y * BM;
    int block_col = blockIdx.x * BN;
    int tcol = tid & 15;   // 0..15  (BN/TN = 16)
    int trow = tid >> 4;   // 0..15  (BM/TM = 16)

    float acc[TM][TN];
    #pragma unroll
    for (int i = 0; i < TM; i++)
        #pragma unroll
        for (int j = 0; j < TN; j++) acc[i][j] = 0.f;

    for (int k0 = 0; k0 < K; k0 += BK) {
        // Load A tile: 128x16 floats = 512 float4, 2 per thread, transposed store
        #pragma unroll
        for (int it = 0; it < 2; ++it) {
            int r = (tid >> 2) + it * 64;       // row in tile 0..127
            int c = (tid & 3) * 4;              // k offset 0,4,8,12
            int gr = block_row + r;
            float4 v = make_float4(0.f, 0.f, 0.f, 0.f);
            if (gr < M) v = *(const float4*)&A[(size_t)gr * K + k0 + c];
            As[c + 0][r] = v.x; As[c + 1][r] = v.y;
            As[c + 2][r] = v.z; As[c + 3][r] = v.w;
        }
        // Load B tile: 16x64 floats = 256 float4, 1 per thread
        {
            int r = tid >> 4;             // 0..15
            int c = (tid & 15) * 4;       // 0..60
            float4 v = *(const float4*)&B[(size_t)(k0 + r) * N + block_col + c];
            *(float4*)&Bs[r][c] = v;
        }
        __syncthreads();
        #pragma unroll
        for (int kk = 0; kk < BK; ++kk) {
            float a[TM], b[TN];
            #pragma unroll
            for (int i = 0; i < TM; i++) a[i] = As[kk][trow * TM + i];
            #pragma unroll
            for (int j = 0; j < TN; j++) b[j] = Bs[kk][tcol * TN + j];
            #pragma unroll
            for (int i = 0; i < TM; i++)
                #pragma unroll
                for (int j = 0; j < TN; j++)
                    acc[i][j] = fmaf(a[i], b[j], acc[i][j]);
        }
        __syncthreads();
    }
    #pragma unroll
    for (int i = 0; i < TM; i++) {
        int gr = block_row + trow * TM + i;
        if (gr < M) {
            float4 v = make_float4(acc[i][0], acc[i][1], acc[i][2], acc[i][3]);
            *(float4*)&C[(size_t)gr * N + block_col + tcol * TN] = v;
        }
    }
}

// ---------------- per-node attention scores: warp per (n,h) ----------------
__global__ void scores_kernel(const float* __restrict__ xp,
                              const float* __restrict__ a_src,
                              const float* __restrict__ a_dst,
                              float* __restrict__ s, float* __restrict__ d,
                              int N, int H, int C) {
    int gw = (blockIdx.x * blockDim.x + threadIdx.x) >> 5;
    int lane = threadIdx.x & 31;
    if (gw >= N * H) return;
    int h = gw % H, n = gw / H;
    const float* row = xp + (size_t)n * H * C + h * C;
    float ss = 0.f, dd = 0.f;
    for (int c = lane; c < C; c += 32) {
        float v = row[c];
        ss += v * a_src[h * C + c];
        dd += v * a_dst[h * C + c];
    }
    #pragma unroll
    for (int o = 16; o; o >>= 1) {
        ss += __shfl_xor_sync(0xffffffffu, ss, o);
        dd += __shfl_xor_sync(0xffffffffu, dd, o);
    }
    if (lane == 0) { s[gw] = ss; d[gw] = dd; }
}

// ---------------- init: m=-inf, z=0, out=bias broadcast ----------------
__global__ void init_kernel(float* __restrict__ m, float* __restrict__ z,
                            float* __restrict__ out, const float* __restrict__ bias,
                            int NH, int NHC, int HC) {
    int i = blockIdx.x * blockDim.x + threadIdx.x;
    if (i < NH) { m[i] = __int_as_float(0xff800000); z[i] = 0.f; }
    if (i < NHC) out[i] = bias[i % HC];
}

// ---------------- edge pass 1: leaky score + segment max ----------------
__global__ void edge_score_kernel(const int* __restrict__ ei,
                                  const float* __restrict__ s, const float* __restrict__ d,
                                  float* __restrict__ ebuf, float* __restrict__ m, int H) {
    int idx = blockIdx.x * blockDim.x + threadIdx.x;
    if (idx >= E_TOT * H) return;
    int h = idx % H, e = idx / H;
    int src, dst;
    if (e < E_RAW) { src = ei[e]; dst = ei[E_RAW + e]; }
    else           { src = dst = e - E_RAW; }
    float v = s[src * H + h] + d[dst * H + h];
    v = v > 0.f ? v : 0.2f * v;
    ebuf[idx] = v;
    atomicMaxFloat(&m[dst * H + h], v);
}

// ---------------- edge pass 2: exp + segment sum ----------------
__global__ void edge_exp_kernel(const int* __restrict__ ei,
                                float* __restrict__ ebuf, const float* __restrict__ m,
                                float* __restrict__ z, int H) {
    int idx = blockIdx.x * blockDim.x + threadIdx.x;
    if (idx >= E_TOT * H) return;
    int h = idx % H, e = idx / H;
    int dst = (e < E_RAW) ? ei[E_RAW + e] : e - E_RAW;
    float p = __expf(ebuf[idx] - m[dst * H + h]);
    ebuf[idx] = p;
    atomicAdd(&z[dst * H + h], p);
}

// ---------------- edge pass 3: warp-per-edge scatter aggregate ----------------
__global__ void aggregate_kernel(const int* __restrict__ ei,
                                 const float* __restrict__ xp, const float* __restrict__ p,
                                 const float* __restrict__ z, float* __restrict__ out,
                                 int H, int C) {
    int gw = (blockIdx.x * blockDim.x + threadIdx.x) >> 5;
    int lane = threadIdx.x & 31;
    if (gw >= E_TOT) return;
    int e = gw;
    int src, dst;
    if (e < E_RAW) { src = ei[e]; dst = ei[E_RAW + e]; }
    else           { src = dst = e - E_RAW; }
    int HCl = H * C;
    int per = HCl >> 5;          // 8 (H=4,C=64) or 4 (H=1,C=128)
    int base = lane * per;
    int head = base / C;
    float alpha = p[e * H + head] / (z[dst * H + head] + 1e-16f);
    const float4* xs = (const float4*)(xp + (size_t)src * HCl + base);
    float* od = out + (size_t)dst * HCl + base;
    #pragma unroll 2
    for (int j = 0; j < (per >> 2); j++) {
        float4 v = xs[j];
        atomicAdd(od + j * 4 + 0, v.x * alpha);
        atomicAdd(od + j * 4 + 1, v.y * alpha);
        atomicAdd(od + j * 4 + 2, v.z * alpha);
        atomicAdd(od + j * 4 + 3, v.w * alpha);
    }
}

// ---------------- elu in place ----------------
__global__ void elu_kernel(float* __restrict__ h, int n) {
    int i = blockIdx.x * blockDim.x + threadIdx.x;
    if (i < n) {
        float v = h[i];
        h[i] = v > 0.f ? v : expm1f(v);
    }
}

// ---------------- host orchestration ----------------
static void run_layer(const float* in, int K,
                      const float* W, const float* a_src, const float* a_dst, const float* bias,
                      int H, int C, const int* ei,
                      float* xp, float* s, float* d, float* m, float* z, float* ebuf,
                      float* outbuf, bool do_elu) {
    int HCl = H * C;
    // GEMM: xp = in @ W
    {
        dim3 grid(HCl / 64, (N_NODES + 127) / 128);
        gemm_kernel<<<grid, 256>>>(in, W, xp, N_NODES, HCl, K);
    }
    // per-node scores
    {
        int warps = N_NODES * H;
        scores_kernel<<<(warps * 32 + 255) / 256, 256>>>(xp, a_src, a_dst, s, d, N_NODES, H, C);
    }
    // init
    {
        int NH = N_NODES * H, NHC = N_NODES * HCl;
        init_kernel<<<(NHC + 255) / 256, 256>>>(m, z, outbuf, bias, NH, NHC, HCl);
    }
    // edge passes
    {
        int tot = E_TOT * H;
        edge_score_kernel<<<(tot + 255) / 256, 256>>>(ei, s, d, ebuf, m, H);
        edge_exp_kernel<<<(tot + 255) / 256, 256>>>(ei, ebuf, m, z, H);
        aggregate_kernel<<<((size_t)E_TOT * 32 + 255) / 256, 256>>>(ei, xp, ebuf, z, outbuf, H, C);
    }
    if (do_elu) {
        int n = N_NODES * HCl;
        elu_kernel<<<(n + 255) / 256, 256>>>(outbuf, n);
    }
}

extern "C" void kernel_launch(void* const* d_in, const int* in_sizes, int n_in,
                              void* d_out, int out_size) {
    const float* x      = (const float*)d_in[0];
    const int*   ei     = (const int*)  d_in[1];
    const float* W0     = (const float*)d_in[2];
    const float* a_src0 = (const float*)d_in[3];
    const float* a_dst0 = (const float*)d_in[4];
    const float* b0     = (const float*)d_in[5];
    const float* W1     = (const float*)d_in[6];
    const float* a_src1 = (const float*)d_in[7];
    const float* a_dst1 = (const float*)d_in[8];
    const float* b1     = (const float*)d_in[9];
    const float* W2     = (const float*)d_in[10];
    const float* a_src2 = (const float*)d_in[11];
    const float* a_dst2 = (const float*)d_in[12];
    const float* b2     = (const float*)d_in[13];

    float *xp, *h, *s, *d, *m, *z, *e;
    cudaGetSymbolAddress((void**)&xp, g_xp);
    cudaGetSymbolAddress((void**)&h,  g_h);
    cudaGetSymbolAddress((void**)&s,  g_s);
    cudaGetSymbolAddress((void**)&d,  g_d);
    cudaGetSymbolAddress((void**)&m,  g_m);
    cudaGetSymbolAddress((void**)&z,  g_z);
    cudaGetSymbolAddress((void**)&e,  g_e);

    // Layer 0: x(N,128) -> h(N,256), elu
    run_layer(x, 128, W0, a_src0, a_dst0, b0, 4, 64, ei, xp, s, d, m, z, e, h, true);
    // Layer 1: h(N,256) -> h(N,256), elu (stream order makes in==out safe:
    // gemm fully consumes h into xp before init overwrites h)
    run_layer(h, 256, W1, a_src1, a_dst1, b1, 4, 64, ei, xp, s, d, m, z, e, h, true);
    // Layer 2: h(N,256) -> d_out(N,128), H=1 (mean over 1 head == identity), no elu
    run_layer(h, 256, W2, a_src2, a_dst2, b2, 1, 128, ei, xp, s, d, m, z, e, (float*)d_out, false);
}

// round 2
// speedup vs baseline: 3.7752x; 3.7752x over previous
#include <cuda_runtime.h>
#include <cuda_bf16.h>
#include <cstdint>

#define N_NODES 50000
#define E_RAW   800000
#define E_TOT   (E_RAW + N_NODES)   // 850000 with self loops
#define MAXH    4
#define MAXHC   256
#define SCAN_B  1024

// ---------------- device scratch (static, allocation-free) ----------------
__device__ float g_xp[(size_t)N_NODES * MAXHC];
__device__ float g_h [(size_t)N_NODES * MAXHC];
__device__ float g_s [(size_t)N_NODES * MAXH];
__device__ float g_d [(size_t)N_NODES * MAXH];
__device__ float g_m [(size_t)N_NODES * MAXH];
__device__ float g_z [(size_t)N_NODES * MAXH];
__device__ float g_e [(size_t)E_TOT   * MAXH];   // raw exp weights p
// CSR by destination
__device__ int g_deg [N_NODES];
__device__ int g_cur [N_NODES];
__device__ int g_off [N_NODES + 1];
__device__ int g_bsum[64];
__device__ int g_srcs[E_TOT];
__device__ int g_eids[E_TOT];

// ---------------- helpers ----------------
__device__ __forceinline__ void atomicMaxFloat(float* addr, float value) {
    if (value >= 0.f)
        atomicMax((int*)addr, __float_as_int(value));
    else
        atomicMin((unsigned int*)addr, __float_as_uint(value));
}

__device__ __forceinline__ void edge_endpoints(const int* __restrict__ ei, int e,
                                               int& src, int& dst) {
    if (e < E_RAW) { src = ei[e]; dst = ei[E_RAW + e]; }
    else           { src = dst = e - E_RAW; }
}

// ---------------- GEMM: C = A(MxK) * B(KxN), row-major fp32 ----------------
// 128x128 tile, BK=16, 256 threads, 8x8 per-thread.
__global__ void gemm_kernel(const float* __restrict__ A, const float* __restrict__ B,
                            float* __restrict__ C, int M, int N, int K) {
    const int BM = 128, BN = 128, BK = 16, TM = 8, TN = 8;
    __shared__ float As[BK][BM + 4];
    __shared__ float Bs[BK][BN];
    int tid = threadIdx.x;
    int brow = blockIdx.y * BM;
    int bcol = blockIdx.x * BN;
    int tcol = tid & 15;   // 0..15
    int trow = tid >> 4;   // 0..15

    float acc[TM][TN];
    #pragma unroll
    for (int i = 0; i < TM; i++)
        #pragma unroll
        for (int j = 0; j < TN; j++) acc[i][j] = 0.f;

    for (int k0 = 0; k0 < K; k0 += BK) {
        // A tile: 128x16 = 512 float4, 2 per thread, transposed store
        #pragma unroll
        for (int it = 0; it < 2; ++it) {
            int r = (tid >> 2) + it * 64;
            int c = (tid & 3) * 4;
            int gr = brow + r;
            float4 v = make_float4(0.f, 0.f, 0.f, 0.f);
            if (gr < M) v = *(const float4*)&A[(size_t)gr * K + k0 + c];
            As[c + 0][r] = v.x; As[c + 1][r] = v.y;
            As[c + 2][r] = v.z; As[c + 3][r] = v.w;
        }
        // B tile: 16x128 = 512 float4, 2 per thread
        #pragma unroll
        for (int it = 0; it < 2; ++it) {
            int r = (tid >> 5) + it * 8;
            int c = (tid & 31) * 4;
            *(float4*)&Bs[r][c] = *(const float4*)&B[(size_t)(k0 + r) * N + bcol + c];
        }
        __syncthreads();
        #pragma unroll
        for (int kk = 0; kk < BK; ++kk) {
            float4 a0 = *(const float4*)&As[kk][trow * TM];
            float4 a1 = *(const float4*)&As[kk][trow * TM + 4];
            float4 b0 = *(const float4*)&Bs[kk][tcol * TN];
            float4 b1 = *(const float4*)&Bs[kk][tcol * TN + 4];
            float a[TM] = {a0.x, a0.y, a0.z, a0.w, a1.x, a1.y, a1.z, a1.w};
            float b[TN] = {b0.x, b0.y, b0.z, b0.w, b1.x, b1.y, b1.z, b1.w};
            #pragma unroll
            for (int i = 0; i < TM; i++)
                #pragma unroll
                for (int j = 0; j < TN; j++)
                    acc[i][j] = fmaf(a[i], b[j], acc[i][j]);
        }
        __syncthreads();
    }
    #pragma unroll
    for (int i = 0; i < TM; i++) {
        int gr = brow + trow * TM + i;
        if (gr < M) {
            *(float4*)&C[(size_t)gr * N + bcol + tcol * TN] =
                make_float4(acc[i][0], acc[i][1], acc[i][2], acc[i][3]);
            *(float4*)&C[(size_t)gr * N + bcol + tcol * TN + 4] =
                make_float4(acc[i][4], acc[i][5], acc[i][6], acc[i][7]);
        }
    }
}

// ---------------- per-node attention scores: warp per (n,h) ----------------
__global__ void scores_kernel(const float* __restrict__ xp,
                              const float* __restrict__ a_src,
                              const float* __restrict__ a_dst,
                              float* __restrict__ s, float* __restrict__ d,
                              int N, int H, int C) {
    int gw = (blockIdx.x * blockDim.x + threadIdx.x) >> 5;
    int lane = threadIdx.x & 31;
    if (gw >= N * H) return;
    int h = gw % H, n = gw / H;
    const float* row = xp + (size_t)n * H * C + h * C;
    float ss = 0.f, dd = 0.f;
    for (int c = lane; c < C; c += 32) {
        float v = row[c];
        ss += v * a_src[h * C + c];
        dd += v * a_dst[h * C + c];
    }
    #pragma unroll
    for (int o = 16; o; o >>= 1) {
        ss += __shfl_xor_sync(0xffffffffu, ss, o);
        dd += __shfl_xor_sync(0xffffffffu, dd, o);
    }
    if (lane == 0) { s[gw] = ss; d[gw] = dd; }
}

// ---------------- init m/z ----------------
__global__ void init_mz_kernel(float* __restrict__ m, float* __restrict__ z, int NH) {
    int i = blockIdx.x * blockDim.x + threadIdx.x;
    if (i < NH) { m[i] = __int_as_float(0xff800000); z[i] = 0.f; }
}

// ---------------- edge pass 1: leaky score + segment max ----------------
__global__ void edge_score_kernel(const int* __restrict__ ei,
                                  const float* __restrict__ s, const float* __restrict__ d,
                                  float* __restrict__ ebuf, float* __restrict__ m, int H) {
    int idx = blockIdx.x * blockDim.x + threadIdx.x;
    if (idx >= E_TOT * H) return;
    int h = idx % H, e = idx / H;
    int src, dst;
    edge_endpoints(ei, e, src, dst);
    float v = s[src * H + h] + d[dst * H + h];
    v = v > 0.f ? v : 0.2f * v;
    ebuf[idx] = v;
    atomicMaxFloat(&m[dst * H + h], v);
}

// ---------------- edge pass 2: exp + segment sum ----------------
__global__ void edge_exp_kernel(const int* __restrict__ ei,
                                float* __restrict__ ebuf, const float* __restrict__ m,
                                float* __restrict__ z, int H) {
    int idx = blockIdx.x * blockDim.x + threadIdx.x;
    if (idx >= E_TOT * H) return;
    int h = idx % H, e = idx / H;
    int dst = (e < E_RAW) ? ei[E_RAW + e] : e - E_RAW;
    float p = __expf(ebuf[idx] - m[dst * H + h]);
    ebuf[idx] = p;
    atomicAdd(&z[dst * H + h], p);
}

// ---------------- CSR build ----------------
__global__ void csr_zero_kernel(int* __restrict__ deg, int* __restrict__ cur) {
    int i = blockIdx.x * blockDim.x + threadIdx.x;
    if (i < N_NODES) { deg[i] = 0; cur[i] = 0; }
}

__global__ void csr_count_kernel(const int* __restrict__ ei, int* __restrict__ deg) {
    int e = blockIdx.x * blockDim.x + threadIdx.x;
    if (e >= E_TOT) return;
    int dst = (e < E_RAW) ? ei[E_RAW + e] : e - E_RAW;
    atomicAdd(&deg[dst], 1);
}

__global__ void scan1_kernel(const int* __restrict__ deg, int* __restrict__ off,
                             int* __restrict__ bsum, int n) {
    __shared__ int sm[SCAN_B];
    int i = blockIdx.x * SCAN_B + threadIdx.x;
    int v = (i < n) ? deg[i] : 0;
    sm[threadIdx.x] = v;
    __syncthreads();
    for (int o = 1; o < SCAN_B; o <<= 1) {
        int t = (threadIdx.x >= o) ? sm[threadIdx.x - o] : 0;
        __syncthreads();
        sm[threadIdx.x] += t;
        __syncthreads();
    }
    if (i < n) off[i + 1] = sm[threadIdx.x];
    if (threadIdx.x == SCAN_B - 1) bsum[blockIdx.x] = sm[threadIdx.x];
}

__global__ void scan2_kernel(int* __restrict__ bsum, int nb) {
    if (threadIdx.x == 0) {
        int run = 0;
        for (int b = 0; b < nb; b++) { int t = bsum[b]; bsum[b] = run; run += t; }
    }
}

__global__ void scan3_kernel(int* __restrict__ off, const int* __restrict__ bsum, int n) {
    int i = blockIdx.x * blockDim.x + threadIdx.x;
    if (i == 0) off[0] = 0;
    if (i < n) off[i + 1] += bsum[i / SCAN_B];
}

__global__ void csr_scatter_kernel(const int* __restrict__ ei, const int* __restrict__ off,
                                   int* __restrict__ cur, int* __restrict__ srcs,
                                   int* __restrict__ eids) {
    int e = blockIdx.x * blockDim.x + threadIdx.x;
    if (e >= E_TOT) return;
    int src, dst;
    edge_endpoints(ei, e, src, dst);
    int pos = atomicAdd(&cur[dst], 1);
    int slot = off[dst] + pos;
    srcs[slot] = src;
    eids[slot] = e;
}

// ---------------- CSR gather aggregate: warp per dst node ----------------
template <int H, int C, bool ELU>
__global__ void aggregate_csr_kernel(const int* __restrict__ off,
                                     const int* __restrict__ srcs,
                                     const int* __restrict__ eids,
                                     const float* __restrict__ xp,
                                     const float* __restrict__ p,
                                     const float* __restrict__ z,
                                     const float* __restrict__ bias,
                                     float* __restrict__ out) {
    constexpr int HC = H * C;
    constexpr int PER = HC / 32;    // 8 (H=4,C=64) or 4 (H=1,C=128)
    int gw = (blockIdx.x * blockDim.x + threadIdx.x) >> 5;
    int lane = threadIdx.x & 31;
    if (gw >= N_NODES) return;
    int base = lane * PER;
    constexpr int LANES_PER_HEAD = C / PER;
    int head = (H == 1) ? 0 : (lane / LANES_PER_HEAD);
    int s0 = off[gw], s1 = off[gw + 1];
    float acc[PER];
    #pragma unroll
    for (int j = 0; j < PER; j++) acc[j] = 0.f;

    for (int t = s0; t < s1; t++) {
        int src = srcs[t];
        float pw = (H == 1) ? p[eids[t]] : p[eids[t] * H + head];
        const float4* xs = (const float4*)(xp + (size_t)src * HC + base);
        #pragma unroll
        for (int q = 0; q < PER / 4; q++) {
            float4 v = xs[q];
            acc[q * 4 + 0] = fmaf(v.x, pw, acc[q * 4 + 0]);
            acc[q * 4 + 1] = fmaf(v.y, pw, acc[q * 4 + 1]);
            acc[q * 4 + 2] = fmaf(v.z, pw, acc[q * 4 + 2]);
            acc[q * 4 + 3] = fmaf(v.w, pw, acc[q * 4 + 3]);
        }
    }
    float inv = 1.f / (z[gw * H + head] + 1e-16f);
    float* od = out + (size_t)gw * HC + base;
    #pragma unroll
    for (int q = 0; q < PER / 4; q++) {
        float4 r;
        r.x = acc[q * 4 + 0] * inv + bias[base + q * 4 + 0];
        r.y = acc[q * 4 + 1] * inv + bias[base + q * 4 + 1];
        r.z = acc[q * 4 + 2] * inv + bias[base + q * 4 + 2];
        r.w = acc[q * 4 + 3] * inv + bias[base + q * 4 + 3];
        if (ELU) {
            r.x = r.x > 0.f ? r.x : expm1f(r.x);
            r.y = r.y > 0.f ? r.y : expm1f(r.y);
            r.z = r.z > 0.f ? r.z : expm1f(r.z);
            r.w = r.w > 0.f ? r.w : expm1f(r.w);
        }
        *(float4*)&od[q * 4] = r;
    }
}

// ---------------- host orchestration ----------------
struct Bufs {
    float *xp, *h, *s, *d, *m, *z, *e;
    int *deg, *cur, *off, *bsum, *srcs, *eids;
};

template <int H, int C, bool ELU>
static void run_layer(const float* in, int K,
                      const float* W, const float* a_src, const float* a_dst,
                      const float* bias, const int* ei, const Bufs& b, float* outbuf) {
    constexpr int HCl = H * C;
    {
        dim3 grid(HCl / 128, (N_NODES + 127) / 128);
        gemm_kernel<<<grid, 256>>>(in, W, b.xp, N_NODES, HCl, K);
    }
    {
        int warps = N_NODES * H;
        scores_kernel<<<(warps * 32 + 255) / 256, 256>>>(b.xp, a_src, a_dst, b.s, b.d,
                                                         N_NODES, H, C);
    }
    {
        int NH = N_NODES * H;
        init_mz_kernel<<<(NH + 255) / 256, 256>>>(b.m, b.z, NH);
    }
    {
        int tot = E_TOT * H;
        edge_score_kernel<<<(tot + 255) / 256, 256>>>(ei, b.s, b.d, b.e, b.m, H);
        edge_exp_kernel<<<(tot + 255) / 256, 256>>>(ei, b.e, b.m, b.z, H);
    }
    {
        aggregate_csr_kernel<H, C, ELU>
            <<<((size_t)N_NODES * 32 + 255) / 256, 256>>>(b.off, b.srcs, b.eids, b.xp,
                                                          b.e, b.z, bias, outbuf);
    }
}

extern "C" void kernel_launch(void* const* d_in, const int* in_sizes, int n_in,
                              void* d_out, int out_size) {
    const float* x      = (const float*)d_in[0];
    const int*   ei     = (const int*)  d_in[1];
    const float* W0     = (const float*)d_in[2];
    const float* a_src0 = (const float*)d_in[3];
    const float* a_dst0 = (const float*)d_in[4];
    const float* b0     = (const float*)d_in[5];
    const float* W1     = (const float*)d_in[6];
    const float* a_src1 = (const float*)d_in[7];
    const float* a_dst1 = (const float*)d_in[8];
    const float* b1     = (const float*)d_in[9];
    const float* W2     = (const float*)d_in[10];
    const float* a_src2 = (const float*)d_in[11];
    const float* a_dst2 = (const float*)d_in[12];
    const float* b2     = (const float*)d_in[13];

    Bufs b;
    cudaGetSymbolAddress((void**)&b.xp,   g_xp);
    cudaGetSymbolAddress((void**)&b.h,    g_h);
    cudaGetSymbolAddress((void**)&b.s,    g_s);
    cudaGetSymbolAddress((void**)&b.d,    g_d);
    cudaGetSymbolAddress((void**)&b.m,    g_m);
    cudaGetSymbolAddress((void**)&b.z,    g_z);
    cudaGetSymbolAddress((void**)&b.e,    g_e);
    cudaGetSymbolAddress((void**)&b.deg,  g_deg);
    cudaGetSymbolAddress((void**)&b.cur,  g_cur);
    cudaGetSymbolAddress((void**)&b.off,  g_off);
    cudaGetSymbolAddress((void**)&b.bsum, g_bsum);
    cudaGetSymbolAddress((void**)&b.srcs, g_srcs);
    cudaGetSymbolAddress((void**)&b.eids, g_eids);

    // ---- CSR build (once; graph is identical for all 3 layers) ----
    csr_zero_kernel<<<(N_NODES + 255) / 256, 256>>>(b.deg, b.cur);
    csr_count_kernel<<<(E_TOT + 255) / 256, 256>>>(ei, b.deg);
    int nblk = (N_NODES + SCAN_B - 1) / SCAN_B;
    scan1_kernel<<<nblk, SCAN_B>>>(b.deg, b.off, b.bsum, N_NODES);
    scan2_kernel<<<1, 32>>>(b.bsum, nblk);
    scan3_kernel<<<(N_NODES + 255) / 256, 256>>>(b.off, b.bsum, N_NODES);
    csr_scatter_kernel<<<(E_TOT + 255) / 256, 256>>>(ei, b.off, b.cur, b.srcs, b.eids);

    // ---- 3 GAT layers ----
    run_layer<4, 64, true >(x,   128, W0, a_src0, a_dst0, b0, ei, b, b.h);
    run_layer<4, 64, true >(b.h, 256, W1, a_src1, a_dst1, b1, ei, b, b.h);
    run_layer<1, 128, false>(b.h, 256, W2, a_src2, a_dst2, b2, ei, b, (float*)d_out);
}

// round 4
// speedup vs baseline: 4.2151x; 1.1165x over previous
#include <cuda_runtime.h>
#include <cuda_bf16.h>
#include <cstdint>

#define N_NODES 50000
#define E_RAW   800000
#define E_TOT   (E_RAW + N_NODES)   // 850000 with self loops
#define MAXH    4
#define MAXHC   256
#define SCAN_B  1024

// ---------------- device scratch (static, allocation-free) ----------------
__device__ float g_xp[(size_t)N_NODES * MAXHC];
__device__ float g_h [(size_t)N_NODES * MAXHC];
__device__ float g_wt[MAXHC * MAXHC];            // transposed weights [N,K]
__device__ float g_s [(size_t)N_NODES * MAXH];
__device__ float g_d [(size_t)N_NODES * MAXH];
__device__ float g_m [(size_t)N_NODES * MAXH];
__device__ float g_z [(size_t)N_NODES * MAXH];
__device__ float g_e [(size_t)E_TOT   * MAXH];   // raw leaky scores (edge order)
__device__ float g_p [(size_t)E_TOT   * MAXH];   // exp weights (CSR order)
// CSR by destination
__device__ int g_deg [N_NODES];
__device__ int g_cur [N_NODES];
__device__ int g_off [N_NODES + 1];
__device__ int g_bsum[64];
__device__ int g_srcs[E_TOT];
__device__ int g_slot[E_TOT];                    // edge id -> CSR slot

// ---------------- small PTX helpers ----------------
__device__ __forceinline__ uint32_t smem_u32(const void* p) {
    uint32_t a;
    asm("{ .reg .u64 t; cvta.to.shared.u64 t, %1; cvt.u32.u64 %0, t; }" : "=r"(a) : "l"(p));
    return a;
}
__device__ __forceinline__ void ldm_x4(uint32_t& r0, uint32_t& r1, uint32_t& r2, uint32_t& r3,
                                       uint32_t addr) {
    asm volatile("ldmatrix.sync.aligned.m8n8.x4.shared.b16 {%0,%1,%2,%3}, [%4];"
                 : "=r"(r0), "=r"(r1), "=r"(r2), "=r"(r3) : "r"(addr));
}
__device__ __forceinline__ void mma_bf16(float* d, const uint32_t* a, uint32_t b0, uint32_t b1) {
    asm volatile(
        "mma.sync.aligned.m16n8k16.row.col.f32.bf16.bf16.f32 "
        "{%0,%1,%2,%3}, {%4,%5,%6,%7}, {%8,%9}, {%0,%1,%2,%3};"
        : "+f"(d[0]), "+f"(d[1]), "+f"(d[2]), "+f"(d[3])
        : "r"(a[0]), "r"(a[1]), "r"(a[2]), "r"(a[3]), "r"(b0), "r"(b1));
}

// ---------------- weight transpose: Wt[n,k] = W[k,n] ----------------
__global__ void transpose_kernel(const float* __restrict__ W, float* __restrict__ Wt,
                                 int K, int N) {
    __shared__ float t[32][33];
    int bn = blockIdx.x * 32, bk = blockIdx.y * 32;
    int x = threadIdx.x, y = threadIdx.y;
    #pragma unroll
    for (int j = 0; j < 32; j += 8) t[y + j][x] = W[(size_t)(bk + y + j) * N + bn + x];
    __syncthreads();
    #pragma unroll
    for (int j = 0; j < 32; j += 8) Wt[(size_t)(bn + y + j) * K + bk + x] = t[x][y + j];
}

// ---------------- tensor GEMM via mma.sync, split bf16 ----------------
// C[M,N] = A[M,K] @ Bt[N,K]^T , fp32 in/out.
// Block tile 128x128, K-chunk 32. 256 threads = 8 warps (4 M x 2 N), warp tile 32x64.
#define PITCH 40           // bf16 elems per smem row (32 + 8 pad); 80 bytes
#define TILE_B (128 * PITCH * 2)

__global__ __launch_bounds__(256) void gemm_mma_kernel(const float* __restrict__ A,
                                                       const float* __restrict__ Bt,
                                                       float* __restrict__ C,
                                                       int M, int N, int K) {
    __shared__ __align__(16) char sm[4 * TILE_B];   // Ahi, Alo, Bhi, Blo
    char* sAhi = sm;
    char* sAlo = sm + TILE_B;
    char* sBhi = sm + 2 * TILE_B;
    char* sBlo = sm + 3 * TILE_B;
    uint32_t base = smem_u32(sm);

    int tid = threadIdx.x, lane = tid & 31, wid = tid >> 5;
    int wm = (wid >> 1) * 32;          // warp M offset in tile (0,32,64,96)
    int wn = (wid & 1) * 64;           // warp N offset in tile (0,64)
    int brow = blockIdx.y * 128;
    int bcol = blockIdx.x * 128;
    int valid = M - brow; if (valid > 128) valid = 128;

    float acc[2][8][4];
    #pragma unroll
    for (int i = 0; i < 2; i++)
        #pragma unroll
        for (int j = 0; j < 8; j++)
            #pragma unroll
            for (int q = 0; q < 4; q++) acc[i][j][q] = 0.f;

    // ldmatrix source addresses (fixed per thread, tile base varies)
    // A/B frag x4: mat = t/8; row = (mat%2)*8 + t%8 [A] ; col byte = (mat/2)*16
    int a_r = ((lane >> 3) & 1) * 8 + (lane & 7);
    int a_cb = (lane >> 4) * 16;
    // B frag x4: row = (mat/2)*8 + t%8 ; col byte = (mat%2)*16
    int b_r = (lane >> 4) * 8 + (lane & 7);
    int b_cb = ((lane >> 3) & 1) * 16;

    int nch = K >> 5;
    for (int ch = 0; ch < nch; ch++) {
        int k0 = ch << 5;
        __syncthreads();
        // load + convert A tile (128x32) and B tile (128x32), 1024 float4 each
        #pragma unroll
        for (int j = 0; j < 4; j++) {
            int i = tid + j * 256;
            int r = i >> 3, c = (i & 7) << 2;
            // ---- A ----
            float4 v = make_float4(0.f, 0.f, 0.f, 0.f);
            if (r < valid) v = *(const float4*)&A[(size_t)(brow + r) * K + k0 + c];
            {
                __nv_bfloat16 h0 = __float2bfloat16_rn(v.x), h1 = __float2bfloat16_rn(v.y);
                __nv_bfloat16 h2 = __float2bfloat16_rn(v.z), h3 = __float2bfloat16_rn(v.w);
                __nv_bfloat16 l0 = __float2bfloat16_rn(v.x - __bfloat162float(h0));
                __nv_bfloat16 l1 = __float2bfloat16_rn(v.y - __bfloat162float(h1));
                __nv_bfloat16 l2 = __float2bfloat16_rn(v.z - __bfloat162float(h2));
                __nv_bfloat16 l3 = __float2bfloat16_rn(v.w - __bfloat162float(h3));
                uint2 uh, ul;
                uh.x = (uint32_t)__bfloat16_as_ushort(h0) | ((uint32_t)__bfloat16_as_ushort(h1) << 16);
                uh.y = (uint32_t)__bfloat16_as_ushort(h2) | ((uint32_t)__bfloat16_as_ushort(h3) << 16);
                ul.x = (uint32_t)__bfloat16_as_ushort(l0) | ((uint32_t)__bfloat16_as_ushort(l1) << 16);
                ul.y = (uint32_t)__bfloat16_as_ushort(l2) | ((uint32_t)__bfloat16_as_ushort(l3) << 16);
                int o = r * (PITCH * 2) + c * 2;
                *(uint2*)(sAhi + o) = uh;
                *(uint2*)(sAlo + o) = ul;
            }
            // ---- B ----
            float4 w = *(const float4*)&Bt[(size_t)(bcol + r) * K + k0 + c];
            {
                __nv_bfloat16 h0 = __float2bfloat16_rn(w.x), h1 = __float2bfloat16_rn(w.y);
                __nv_bfloat16 h2 = __float2bfloat16_rn(w.z), h3 = __float2bfloat16_rn(w.w);
                __nv_bfloat16 l0 = __float2bfloat16_rn(w.x - __bfloat162float(h0));
                __nv_bfloat16 l1 = __float2bfloat16_rn(w.y - __bfloat162float(h1));
                __nv_bfloat16 l2 = __float2bfloat16_rn(w.z - __bfloat162float(h2));
                __nv_bfloat16 l3 = __float2bfloat16_rn(w.w - __bfloat162float(h3));
                uint2 uh, ul;
                uh.x = (uint32_t)__bfloat16_as_ushort(h0) | ((uint32_t)__bfloat16_as_ushort(h1) << 16);
                uh.y = (uint32_t)__bfloat16_as_ushort(h2) | ((uint32_t)__bfloat16_as_ushort(h3) << 16);
                ul.x = (uint32_t)__bfloat16_as_ushort(l0) | ((uint32_t)__bfloat16_as_ushort(l1) << 16);
                ul.y = (uint32_t)__bfloat16_as_ushort(l2) | ((uint32_t)__bfloat16_as_ushort(l3) << 16);
                int o = r * (PITCH * 2) + c * 2;
                *(uint2*)(sBhi + o) = uh;
                *(uint2*)(sBlo + o) = ul;
            }
        }
        __syncthreads();

        #pragma unroll
        for (int ks = 0; ks < 2; ks++) {          // two k16 steps per chunk
            int kb = ks * 32;                     // byte offset of k-step (16 bf16)
            // A fragments: 2 m16 tiles, hi + lo
            uint32_t ah[2][4], al[2][4];
            #pragma unroll
            for (int mt = 0; mt < 2; mt++) {
                int ro = (wm + mt * 16 + a_r) * (PITCH * 2) + kb + a_cb;
                ldm_x4(ah[mt][0], ah[mt][1], ah[mt][2], ah[mt][3],
                       base + (uint32_t)(sAhi - sm) + ro);
                ldm_x4(al[mt][0], al[mt][1], al[mt][2], al[mt][3],
                       base + (uint32_t)(sAlo - sm) + ro);
            }
            #pragma unroll
            for (int nt = 0; nt < 4; nt++) {      // 4 n16 tiles per warp
                int ro = (wn + nt * 16 + b_r) * (PITCH * 2) + kb + b_cb;
                uint32_t bh[4], bl[4];
                ldm_x4(bh[0], bh[1], bh[2], bh[3], base + (uint32_t)(sBhi - sm) + ro);
                ldm_x4(bl[0], bl[1], bl[2], bl[3], base + (uint32_t)(sBlo - sm) + ro);
                #pragma unroll
                for (int mt = 0; mt < 2; mt++) {
                    mma_bf16(acc[mt][nt * 2 + 0], ah[mt], bh[0], bh[1]);
                    mma_bf16(acc[mt][nt * 2 + 1], ah[mt], bh[2], bh[3]);
                    mma_bf16(acc[mt][nt * 2 + 0], ah[mt], bl[0], bl[1]);
                    mma_bf16(acc[mt][nt * 2 + 1], ah[mt], bl[2], bl[3]);
                    mma_bf16(acc[mt][nt * 2 + 0], al[mt], bh[0], bh[1]);
                    mma_bf16(acc[mt][nt * 2 + 1], al[mt], bh[2], bh[3]);
                }
            }
        }
    }

    // epilogue: c0,c1 -> row t/4, cols 2*(t%4)+{0,1}; c2,c3 -> row t/4+8
    int er = lane >> 2, ec = (lane & 3) * 2;
    #pragma unroll
    for (int mt = 0; mt < 2; mt++) {
        int r0 = brow + wm + mt * 16 + er;
        #pragma unroll
        for (int nt = 0; nt < 8; nt++) {
            int col = bcol + wn + nt * 8 + ec;
            if (r0 < M)
                *(float2*)&C[(size_t)r0 * N + col] = make_float2(acc[mt][nt][0], acc[mt][nt][1]);
            if (r0 + 8 < M)
                *(float2*)&C[(size_t)(r0 + 8) * N + col] = make_float2(acc[mt][nt][2], acc[mt][nt][3]);
        }
    }
}

// ---------------- per-node attention scores: warp per (n,h) ----------------
__global__ void scores_kernel(const float* __restrict__ xp,
                              const float* __restrict__ a_src,
                              const float* __restrict__ a_dst,
                              float* __restrict__ s, float* __restrict__ d,
                              int N, int H, int C) {
    int gw = (blockIdx.x * blockDim.x + threadIdx.x) >> 5;
    int lane = threadIdx.x & 31;
    if (gw >= N * H) return;
    int h = gw % H, n = gw / H;
    const float* row = xp + (size_t)n * H * C + h * C;
    float ss = 0.f, dd = 0.f;
    for (int c = lane; c < C; c += 32) {
        float v = row[c];
        ss += v * a_src[h * C + c];
        dd += v * a_dst[h * C + c];
    }
    #pragma unroll
    for (int o = 16; o; o >>= 1) {
        ss += __shfl_xor_sync(0xffffffffu, ss, o);
        dd += __shfl_xor_sync(0xffffffffu, dd, o);
    }
    if (lane == 0) { s[gw] = ss; d[gw] = dd; }
}

// ---------------- init m/z ----------------
__global__ void init_mz_kernel(float* __restrict__ m, float* __restrict__ z, int NH) {
    int i = blockIdx.x * blockDim.x + threadIdx.x;
    if (i < NH) { m[i] = __int_as_float(0xff800000); z[i] = 0.f; }
}

// ---------------- helpers ----------------
__device__ __forceinline__ void atomicMaxFloat(float* addr, float value) {
    if (value >= 0.f)
        atomicMax((int*)addr, __float_as_int(value));
    else
        atomicMin((unsigned int*)addr, __float_as_uint(value));
}
__device__ __forceinline__ void edge_endpoints(const int* __restrict__ ei, int e,
                                               int& src, int& dst) {
    if (e < E_RAW) { src = ei[e]; dst = ei[E_RAW + e]; }
    else           { src = dst = e - E_RAW; }
}

// ---------------- edge pass 1: leaky score + segment max ----------------
__global__ void edge_score_kernel(const int* __restrict__ ei,
                                  const float* __restrict__ s, const float* __restrict__ d,
                                  float* __restrict__ ebuf, float* __restrict__ m, int H) {
    int idx = blockIdx.x * blockDim.x + threadIdx.x;
    if (idx >= E_TOT * H) return;
    int h = idx % H, e = idx / H;
    int src, dst;
    edge_endpoints(ei, e, src, dst);
    float v = s[src * H + h] + d[dst * H + h];
    v = v > 0.f ? v : 0.2f * v;
    ebuf[idx] = v;
    atomicMaxFloat(&m[dst * H + h], v);
}

// ---------------- edge pass 2: exp + segment sum, write p in CSR order ----------------
__global__ void edge_exp_kernel(const int* __restrict__ ei, const int* __restrict__ slot,
                                const float* __restrict__ ebuf, const float* __restrict__ m,
                                float* __restrict__ z, float* __restrict__ pcsr, int H) {
    int idx = blockIdx.x * blockDim.x + threadIdx.x;
    if (idx >= E_TOT * H) return;
    int h = idx % H, e = idx / H;
    int dst = (e < E_RAW) ? ei[E_RAW + e] : e - E_RAW;
    float p = __expf(ebuf[idx] - m[dst * H + h]);
    pcsr[slot[e] * H + h] = p;
    atomicAdd(&z[dst * H + h], p);
}

// ---------------- CSR build ----------------
__global__ void csr_zero_kernel(int* __restrict__ deg, int* __restrict__ cur) {
    int i = blockIdx.x * blockDim.x + threadIdx.x;
    if (i < N_NODES) { deg[i] = 0; cur[i] = 0; }
}
__global__ void csr_count_kernel(const int* __restrict__ ei, int* __restrict__ deg) {
    int e = blockIdx.x * blockDim.x + threadIdx.x;
    if (e >= E_TOT) return;
    int dst = (e < E_RAW) ? ei[E_RAW + e] : e - E_RAW;
    atomicAdd(&deg[dst], 1);
}
__global__ void scan1_kernel(const int* __restrict__ deg, int* __restrict__ off,
                             int* __restrict__ bsum, int n) {
    __shared__ int sm[SCAN_B];
    int i = blockIdx.x * SCAN_B + threadIdx.x;
    int v = (i < n) ? deg[i] : 0;
    sm[threadIdx.x] = v;
    __syncthreads();
    for (int o = 1; o < SCAN_B; o <<= 1) {
        int t = (threadIdx.x >= o) ? sm[threadIdx.x - o] : 0;
        __syncthreads();
        sm[threadIdx.x] += t;
        __syncthreads();
    }
    if (i < n) off[i + 1] = sm[threadIdx.x];
    if (threadIdx.x == SCAN_B - 1) bsum[blockIdx.x] = sm[threadIdx.x];
}
__global__ void scan2_kernel(int* __restrict__ bsum, int nb) {
    if (threadIdx.x == 0) {
        int run = 0;
        for (int b = 0; b < nb; b++) { int t = bsum[b]; bsum[b] = run; run += t; }
    }
}
__global__ void scan3_kernel(int* __restrict__ off, const int* __restrict__ bsum, int n) {
    int i = blockIdx.x * blockDim.x + threadIdx.x;
    if (i == 0) off[0] = 0;
    if (i < n) off[i + 1] += bsum[i / SCAN_B];
}
__global__ void csr_scatter_kernel(const int* __restrict__ ei, const int* __restrict__ off,
                                   int* __restrict__ cur, int* __restrict__ srcs,
                                   int* __restrict__ slot) {
    int e = blockIdx.x * blockDim.x + threadIdx.x;
    if (e >= E_TOT) return;
    int src, dst;
    edge_endpoints(ei, e, src, dst);
    int pos = atomicAdd(&cur[dst], 1);
    int sl = off[dst] + pos;
    srcs[sl] = src;
    slot[e] = sl;
}

// ---------------- CSR gather aggregate: warp per dst node ----------------
template <int H, int C, bool ELU>
__global__ void aggregate_csr_kernel(const int* __restrict__ off,
                                     const int* __restrict__ srcs,
                                     const float* __restrict__ xp,
                                     const float* __restrict__ pcsr,
                                     const float* __restrict__ z,
                                     const float* __restrict__ bias,
                                     float* __restrict__ out) {
    constexpr int HC = H * C;
    constexpr int PER = HC / 32;
    int gw = (blockIdx.x * blockDim.x + threadIdx.x) >> 5;
    int lane = threadIdx.x & 31;
    if (gw >= N_NODES) return;
    int base = lane * PER;
    constexpr int LANES_PER_HEAD = C / PER;
    int head = (H == 1) ? 0 : (lane / LANES_PER_HEAD);
    int s0 = off[gw], s1 = off[gw + 1];
    float acc[PER];
    #pragma unroll
    for (int j = 0; j < PER; j++) acc[j] = 0.f;

    for (int t = s0; t < s1; t++) {
        int src = srcs[t];
        float pw = pcsr[t * H + head];
        const float4* xs = (const float4*)(xp + (size_t)src * HC + base);
        #pragma unroll
        for (int q = 0; q < PER / 4; q++) {
            float4 v = xs[q];
            acc[q * 4 + 0] = fmaf(v.x, pw, acc[q * 4 + 0]);
            acc[q * 4 + 1] = fmaf(v.y, pw, acc[q * 4 + 1]);
            acc[q * 4 + 2] = fmaf(v.z, pw, acc[q * 4 + 2]);
            acc[q * 4 + 3] = fmaf(v.w, pw, acc[q * 4 + 3]);
        }
    }
    float inv = 1.f / (z[gw * H + head] + 1e-16f);
    float* od = out + (size_t)gw * HC + base;
    #pragma unroll
    for (int q = 0; q < PER / 4; q++) {
        float4 r;
        r.x = acc[q * 4 + 0] * inv + bias[base + q * 4 + 0];
        r.y = acc[q * 4 + 1] * inv + bias[base + q * 4 + 1];
        r.z = acc[q * 4 + 2] * inv + bias[base + q * 4 + 2];
        r.w = acc[q * 4 + 3] * inv + bias[base + q * 4 + 3];
        if (ELU) {
            r.x = r.x > 0.f ? r.x : expm1f(r.x);
            r.y = r.y > 0.f ? r.y : expm1f(r.y);
            r.z = r.z > 0.f ? r.z : expm1f(r.z);
            r.w = r.w > 0.f ? r.w : expm1f(r.w);
        }
        *(float4*)&od[q * 4] = r;
    }
}

// ---------------- host orchestration ----------------
struct Bufs {
    float *xp, *h, *wt, *s, *d, *m, *z, *e, *p;
    int *deg, *cur, *off, *bsum, *srcs, *slot;
};

template <int H, int C, bool ELU>
static void run_layer(const float* in, int K,
                      const float* W, const float* a_src, const float* a_dst,
                      const float* bias, const int* ei, const Bufs& b, float* outbuf) {
    constexpr int HCl = H * C;
    {   // W^T then mma.sync GEMM: xp = in @ W
        dim3 tg(HCl / 32, K / 32);
        transpose_kernel<<<tg, dim3(32, 8)>>>(W, b.wt, K, HCl);
        dim3 grid(HCl / 128, (N_NODES + 127) / 128);
        gemm_mma_kernel<<<grid, 256>>>(in, b.wt, b.xp, N_NODES, HCl, K);
    }
    {
        int warps = N_NODES * H;
        scores_kernel<<<(warps * 32 + 255) / 256, 256>>>(b.xp, a_src, a_dst, b.s, b.d,
                                                         N_NODES, H, C);
    }
    {
        int NH = N_NODES * H;
        init_mz_kernel<<<(NH + 255) / 256, 256>>>(b.m, b.z, NH);
    }
    {
        int tot = E_TOT * H;
        edge_score_kernel<<<(tot + 255) / 256, 256>>>(ei, b.s, b.d, b.e, b.m, H);
        edge_exp_kernel<<<(tot + 255) / 256, 256>>>(ei, b.slot, b.e, b.m, b.z, b.p, H);
    }
    {
        aggregate_csr_kernel<H, C, ELU>
            <<<((size_t)N_NODES * 32 + 255) / 256, 256>>>(b.off, b.srcs, b.xp,
                                                          b.p, b.z, bias, outbuf);
    }
}

extern "C" void kernel_launch(void* const* d_in, const int* in_sizes, int n_in,
                              void* d_out, int out_size) {
    const float* x      = (const float*)d_in[0];
    const int*   ei     = (const int*)  d_in[1];
    const float* W0     = (const float*)d_in[2];
    const float* a_src0 = (const float*)d_in[3];
    const float* a_dst0 = (const float*)d_in[4];
    const float* b0     = (const float*)d_in[5];
    const float* W1     = (const float*)d_in[6];
    const float* a_src1 = (const float*)d_in[7];
    const float* a_dst1 = (const float*)d_in[8];
    const float* b1     = (const float*)d_in[9];
    const float* W2     = (const float*)d_in[10];
    const float* a_src2 = (const float*)d_in[11];
    const float* a_dst2 = (const float*)d_in[12];
    const float* b2     = (const float*)d_in[13];

    Bufs b;
    cudaGetSymbolAddress((void**)&b.xp,   g_xp);
    cudaGetSymbolAddress((void**)&b.h,    g_h);
    cudaGetSymbolAddress((void**)&b.wt,   g_wt);
    cudaGetSymbolAddress((void**)&b.s,    g_s);
    cudaGetSymbolAddress((void**)&b.d,    g_d);
    cudaGetSymbolAddress((void**)&b.m,    g_m);
    cudaGetSymbolAddress((void**)&b.z,    g_z);
    cudaGetSymbolAddress((void**)&b.e,    g_e);
    cudaGetSymbolAddress((void**)&b.p,    g_p);
    cudaGetSymbolAddress((void**)&b.deg,  g_deg);
    cudaGetSymbolAddress((void**)&b.cur,  g_cur);
    cudaGetSymbolAddress((void**)&b.off,  g_off);
    cudaGetSymbolAddress((void**)&b.bsum, g_bsum);
    cudaGetSymbolAddress((void**)&b.srcs, g_srcs);
    cudaGetSymbolAddress((void**)&b.slot, g_slot);

    // ---- CSR build (once; graph is identical for all 3 layers) ----
    csr_zero_kernel<<<(N_NODES + 255) / 256, 256>>>(b.deg, b.cur);
    csr_count_kernel<<<(E_TOT + 255) / 256, 256>>>(ei, b.deg);
    int nblk = (N_NODES + SCAN_B - 1) / SCAN_B;
    scan1_kernel<<<nblk, SCAN_B>>>(b.deg, b.off, b.bsum, N_NODES);
    scan2_kernel<<<1, 32>>>(b.bsum, nblk);
    scan3_kernel<<<(N_NODES + 255) / 256, 256>>>(b.off, b.bsum, N_NODES);
    csr_scatter_kernel<<<(E_TOT + 255) / 256, 256>>>(ei, b.off, b.cur, b.srcs, b.slot);

    // ---- 3 GAT layers ----
    run_layer<4, 64, true >(x,   128, W0, a_src0, a_dst0, b0, ei, b, b.h);
    run_layer<4, 64, true >(b.h, 256, W1, a_src1, a_dst1, b1, ei, b, b.h);
    run_layer<1, 128, false>(b.h, 256, W2, a_src2, a_dst2, b2, ei, b, (float*)d_out);
}

// round 5
// speedup vs baseline: 5.7921x; 1.3741x over previous
#include <cuda_runtime.h>
#include <cuda_bf16.h>
#include <cstdint>

#define N_NODES 50000
#define E_RAW   800000
#define E_TOT   (E_RAW + N_NODES)   // 850000 with self loops
#define MAXH    4
#define MAXHC   256
#define SCAN_B  1024

// ---------------- device scratch (static, allocation-free) ----------------
__device__ float g_xp[(size_t)N_NODES * MAXHC];
__device__ float g_h [(size_t)N_NODES * MAXHC];
__device__ __nv_bfloat16 g_whi[MAXHC * MAXHC];   // W^T hi [N,K] bf16
__device__ __nv_bfloat16 g_wlo[MAXHC * MAXHC];   // W^T lo [N,K] bf16
__device__ float g_s [(size_t)N_NODES * MAXH];
__device__ float g_d [(size_t)N_NODES * MAXH];
__device__ float g_z [(size_t)N_NODES * MAXH];
__device__ float g_p [(size_t)E_TOT   * MAXH];   // exp weights (CSR order)
// CSR by destination
__device__ int g_deg [N_NODES];
__device__ int g_cur [N_NODES];
__device__ int g_off [N_NODES + 1];
__device__ int g_bsum[64];
__device__ int g_srcs[E_TOT];
__device__ int g_slot[E_TOT];                    // edge id -> CSR slot

// ---------------- small PTX helpers ----------------
__device__ __forceinline__ uint32_t smem_u32(const void* p) {
    uint32_t a;
    asm("{ .reg .u64 t; cvta.to.shared.u64 t, %1; cvt.u32.u64 %0, t; }" : "=r"(a) : "l"(p));
    return a;
}
__device__ __forceinline__ void ldm_x4(uint32_t& r0, uint32_t& r1, uint32_t& r2, uint32_t& r3,
                                       uint32_t addr) {
    asm volatile("ldmatrix.sync.aligned.m8n8.x4.shared.b16 {%0,%1,%2,%3}, [%4];"
                 : "=r"(r0), "=r"(r1), "=r"(r2), "=r"(r3) : "r"(addr));
}
__device__ __forceinline__ void mma_bf16(float* d, const uint32_t* a, uint32_t b0, uint32_t b1) {
    asm volatile(
        "mma.sync.aligned.m16n8k16.row.col.f32.bf16.bf16.f32 "
        "{%0,%1,%2,%3}, {%4,%5,%6,%7}, {%8,%9}, {%0,%1,%2,%3};"
        : "+f"(d[0]), "+f"(d[1]), "+f"(d[2]), "+f"(d[3])
        : "r"(a[0]), "r"(a[1]), "r"(a[2]), "r"(a[3]), "r"(b0), "r"(b1));
}
__device__ __forceinline__ void cp_async16(uint32_t dst, const void* src) {
    asm volatile("cp.async.ca.shared.global [%0], [%1], 16;" :: "r"(dst), "l"(src));
}
#define CP_COMMIT() asm volatile("cp.async.commit_group;")
#define CP_WAIT0()  asm volatile("cp.async.wait_group 0;" ::: "memory")

// ---------------- weight transpose + bf16 split: Wt[n,k] = W[k,n] ----------------
__global__ void transpose_convert_kernel(const float* __restrict__ W,
                                         __nv_bfloat16* __restrict__ Whi,
                                         __nv_bfloat16* __restrict__ Wlo,
                                         int K, int N) {
    __shared__ float t[32][33];
    int bn = blockIdx.x * 32, bk = blockIdx.y * 32;
    int x = threadIdx.x, y = threadIdx.y;
    #pragma unroll
    for (int j = 0; j < 32; j += 8) t[y + j][x] = W[(size_t)(bk + y + j) * N + bn + x];
    __syncthreads();
    #pragma unroll
    for (int j = 0; j < 32; j += 8) {
        float v = t[x][y + j];
        __nv_bfloat16 hi = __float2bfloat16_rn(v);
        __nv_bfloat16 lo = __float2bfloat16_rn(v - __bfloat162float(hi));
        size_t o = (size_t)(bn + y + j) * K + bk + x;
        Whi[o] = hi;
        Wlo[o] = lo;
    }
}

// ---------------- tensor GEMM via mma.sync, split bf16, double-buffered ----------------
// C[M,N] = A[M,K](fp32) @ Bt[N,K]^T (bf16 hi/lo precomputed).
// Block tile 128x128, K-chunk 32. 8 warps (4Mx2N), warp tile 32x64.
#define PITCH    40                   // bf16 per smem row (32 + 8 pad) = 80 bytes
#define TILE_B   (128 * PITCH * 2)    // 10240 bytes per matrix-half
#define GEMM_SMEM (8 * TILE_B)        // 2 stages x (Ahi,Alo,Bhi,Blo)

__global__ __launch_bounds__(256, 2) void gemm_mma_kernel(const float* __restrict__ A,
                                                          const __nv_bfloat16* __restrict__ Bh,
                                                          const __nv_bfloat16* __restrict__ Bl,
                                                          float* __restrict__ C,
                                                          int M, int N, int K) {
    extern __shared__ __align__(16) char sm[];
    uint32_t base = smem_u32(sm);

    int tid = threadIdx.x, lane = tid & 31, wid = tid >> 5;
    int wm = (wid >> 1) * 32;
    int wn = (wid & 1) * 64;
    int brow = blockIdx.y * 128;
    int bcol = blockIdx.x * 128;
    int valid = M - brow; if (valid > 128) valid = 128;

    float acc[2][8][4];
    #pragma unroll
    for (int i = 0; i < 2; i++)
        #pragma unroll
        for (int j = 0; j < 8; j++)
            #pragma unroll
            for (int q = 0; q < 4; q++) acc[i][j][q] = 0.f;

    // per-thread A load coords: 4 float4, i = tid + j*256 -> r=i>>3, c=(i&7)*4
    int la_r[4], la_c[4];
    #pragma unroll
    for (int j = 0; j < 4; j++) {
        int i = tid + j * 256;
        la_r[j] = i >> 3;
        la_c[j] = (i & 7) << 2;
    }
    // per-thread B cp.async coords: 4 ops, i = tid + j*256 (0..1023):
    // seg=i&3, row=(i>>2)&127, half=i>>9 (0=hi,1=lo)
    // ldmatrix fragment coords
    int a_r = ((lane >> 3) & 1) * 8 + (lane & 7);
    int a_cb = (lane >> 4) * 16;
    int b_r = (lane >> 4) * 8 + (lane & 7);
    int b_cb = ((lane >> 3) & 1) * 16;

    float4 av[4];
    int nch = K >> 5;

    auto ldgA = [&](int ch) {
        int k0 = ch << 5;
        #pragma unroll
        for (int j = 0; j < 4; j++) {
            if (la_r[j] < valid)
                av[j] = *(const float4*)&A[(size_t)(brow + la_r[j]) * K + k0 + la_c[j]];
            else
                av[j] = make_float4(0.f, 0.f, 0.f, 0.f);
        }
    };
    auto loadB_async = [&](int stage, int ch) {
        int k0 = ch << 5;
        #pragma unroll
        for (int j = 0; j < 4; j++) {
            int i = tid + j * 256;
            int seg = i & 3, row = (i >> 2) & 127, half = i >> 9;
            const __nv_bfloat16* src = (half ? Bl : Bh) + (size_t)(bcol + row) * K + k0 + seg * 8;
            uint32_t dst = base + (uint32_t)((stage * 4 + 2 + half) * TILE_B)
                         + (uint32_t)(row * (PITCH * 2) + seg * 16);
            cp_async16(dst, src);
        }
    };
    auto convA_sts = [&](int stage) {
        uint32_t hi_b = base + (uint32_t)((stage * 4 + 0) * TILE_B);
        uint32_t lo_b = base + (uint32_t)((stage * 4 + 1) * TILE_B);
        #pragma unroll
        for (int j = 0; j < 4; j++) {
            float4 v = av[j];
            __nv_bfloat16 h0 = __float2bfloat16_rn(v.x), h1 = __float2bfloat16_rn(v.y);
            __nv_bfloat16 h2 = __float2bfloat16_rn(v.z), h3 = __float2bfloat16_rn(v.w);
            __nv_bfloat16 l0 = __float2bfloat16_rn(v.x - __bfloat162float(h0));
            __nv_bfloat16 l1 = __float2bfloat16_rn(v.y - __bfloat162float(h1));
            __nv_bfloat16 l2 = __float2bfloat16_rn(v.z - __bfloat162float(h2));
            __nv_bfloat16 l3 = __float2bfloat16_rn(v.w - __bfloat162float(h3));
            uint2 uh, ul;
            uh.x = (uint32_t)__bfloat16_as_ushort(h0) | ((uint32_t)__bfloat16_as_ushort(h1) << 16);
            uh.y = (uint32_t)__bfloat16_as_ushort(h2) | ((uint32_t)__bfloat16_as_ushort(h3) << 16);
            ul.x = (uint32_t)__bfloat16_as_ushort(l0) | ((uint32_t)__bfloat16_as_ushort(l1) << 16);
            ul.y = (uint32_t)__bfloat16_as_ushort(l2) | ((uint32_t)__bfloat16_as_ushort(l3) << 16);
            uint32_t o = (uint32_t)(la_r[j] * (PITCH * 2) + la_c[j] * 2);
            asm volatile("st.shared.v2.b32 [%0], {%1,%2};" :: "r"(hi_b + o), "r"(uh.x), "r"(uh.y));
            asm volatile("st.shared.v2.b32 [%0], {%1,%2};" :: "r"(lo_b + o), "r"(ul.x), "r"(ul.y));
        }
    };

    // prologue: fill stage 0
    ldgA(0);
    loadB_async(0, 0);
    CP_COMMIT();
    convA_sts(0);
    CP_WAIT0();
    __syncthreads();

    for (int ch = 0; ch < nch; ch++) {
        int cur = ch & 1, nxt = cur ^ 1;
        bool more = (ch + 1 < nch);
        if (more) {
            ldgA(ch + 1);
            loadB_async(nxt, ch + 1);
            CP_COMMIT();
        }
        // ---- mma over stage cur ----
        uint32_t sAhi = base + (uint32_t)((cur * 4 + 0) * TILE_B);
        uint32_t sAlo = base + (uint32_t)((cur * 4 + 1) * TILE_B);
        uint32_t sBhi = base + (uint32_t)((cur * 4 + 2) * TILE_B);
        uint32_t sBlo = base + (uint32_t)((cur * 4 + 3) * TILE_B);
        #pragma unroll
        for (int ks = 0; ks < 2; ks++) {
            int kb = ks * 32;
            uint32_t ah[2][4], al[2][4];
            #pragma unroll
            for (int mt = 0; mt < 2; mt++) {
                uint32_t ro = (uint32_t)((wm + mt * 16 + a_r) * (PITCH * 2) + kb + a_cb);
                ldm_x4(ah[mt][0], ah[mt][1], ah[mt][2], ah[mt][3], sAhi + ro);
                ldm_x4(al[mt][0], al[mt][1], al[mt][2], al[mt][3], sAlo + ro);
            }
            #pragma unroll
            for (int nt = 0; nt < 4; nt++) {
                uint32_t ro = (uint32_t)((wn + nt * 16 + b_r) * (PITCH * 2) + kb + b_cb);
                uint32_t bh[4], bl[4];
                ldm_x4(bh[0], bh[1], bh[2], bh[3], sBhi + ro);
                ldm_x4(bl[0], bl[1], bl[2], bl[3], sBlo + ro);
                #pragma unroll
                for (int mt = 0; mt < 2; mt++) {
                    mma_bf16(acc[mt][nt * 2 + 0], ah[mt], bh[0], bh[1]);
                    mma_bf16(acc[mt][nt * 2 + 1], ah[mt], bh[2], bh[3]);
                    mma_bf16(acc[mt][nt * 2 + 0], ah[mt], bl[0], bl[1]);
                    mma_bf16(acc[mt][nt * 2 + 1], ah[mt], bl[2], bl[3]);
                    mma_bf16(acc[mt][nt * 2 + 0], al[mt], bh[0], bh[1]);
                    mma_bf16(acc[mt][nt * 2 + 1], al[mt], bh[2], bh[3]);
                }
            }
        }
        if (more) {
            convA_sts(nxt);
            CP_WAIT0();
        }
        __syncthreads();
    }

    int er = lane >> 2, ec = (lane & 3) * 2;
    #pragma unroll
    for (int mt = 0; mt < 2; mt++) {
        int r0 = brow + wm + mt * 16 + er;
        #pragma unroll
        for (int nt = 0; nt < 8; nt++) {
            int col = bcol + wn + nt * 8 + ec;
            if (r0 < M)
                *(float2*)&C[(size_t)r0 * N + col] = make_float2(acc[mt][nt][0], acc[mt][nt][1]);
            if (r0 + 8 < M)
                *(float2*)&C[(size_t)(r0 + 8) * N + col] = make_float2(acc[mt][nt][2], acc[mt][nt][3]);
        }
    }
}

// ---------------- per-node attention scores: warp per (n,h) ----------------
__global__ void scores_kernel(const float* __restrict__ xp,
                              const float* __restrict__ a_src,
                              const float* __restrict__ a_dst,
                              float* __restrict__ s, float* __restrict__ d,
                              int N, int H, int C) {
    int gw = (blockIdx.x * blockDim.x + threadIdx.x) >> 5;
    int lane = threadIdx.x & 31;
    if (gw >= N * H) return;
    int h = gw % H, n = gw / H;
    const float* row = xp + (size_t)n * H * C + h * C;
    float ss = 0.f, dd = 0.f;
    for (int c = lane; c < C; c += 32) {
        float v = row[c];
        ss += v * a_src[h * C + c];
        dd += v * a_dst[h * C + c];
    }
    #pragma unroll
    for (int o = 16; o; o >>= 1) {
        ss += __shfl_xor_sync(0xffffffffu, ss, o);
        dd += __shfl_xor_sync(0xffffffffu, dd, o);
    }
    if (lane == 0) { s[gw] = ss; d[gw] = dd; }
}

// ---------------- init z ----------------
__global__ void init_z_kernel(float* __restrict__ z, int NH) {
    int i = blockIdx.x * blockDim.x + threadIdx.x;
    if (i < NH) z[i] = 0.f;
}

// ---------------- fused edge softmax (no max shift; exact, overflow-guarded) ----------------
__global__ void edge_soft_kernel(const int* __restrict__ ei, const int* __restrict__ slot,
                                 const float* __restrict__ s, const float* __restrict__ d,
                                 float* __restrict__ z, float* __restrict__ pcsr, int H) {
    int idx = blockIdx.x * blockDim.x + threadIdx.x;
    if (idx >= E_TOT * H) return;
    int h = idx % H, e = idx / H;
    int src, dst;
    if (e < E_RAW) { src = ei[e]; dst = ei[E_RAW + e]; }
    else           { src = dst = e - E_RAW; }
    float v = s[src * H + h] + d[dst * H + h];
    v = v > 0.f ? v : 0.2f * v;
    float p = __expf(fminf(v, 80.f));
    pcsr[slot[e] * H + h] = p;
    atomicAdd(&z[dst * H + h], p);
}

// ---------------- CSR build ----------------
__device__ __forceinline__ void edge_endpoints(const int* __restrict__ ei, int e,
                                               int& src, int& dst) {
    if (e < E_RAW) { src = ei[e]; dst = ei[E_RAW + e]; }
    else           { src = dst = e - E_RAW; }
}
__global__ void csr_zero_kernel(int* __restrict__ deg, int* __restrict__ cur) {
    int i = blockIdx.x * blockDim.x + threadIdx.x;
    if (i < N_NODES) { deg[i] = 0; cur[i] = 0; }
}
__global__ void csr_count_kernel(const int* __restrict__ ei, int* __restrict__ deg) {
    int e = blockIdx.x * blockDim.x + threadIdx.x;
    if (e >= E_TOT) return;
    int dst = (e < E_RAW) ? ei[E_RAW + e] : e - E_RAW;
    atomicAdd(&deg[dst], 1);
}
__global__ void scan1_kernel(const int* __restrict__ deg, int* __restrict__ off,
                             int* __restrict__ bsum, int n) {
    __shared__ int sm[SCAN_B];
    int i = blockIdx.x * SCAN_B + threadIdx.x;
    int v = (i < n) ? deg[i] : 0;
    sm[threadIdx.x] = v;
    __syncthreads();
    for (int o = 1; o < SCAN_B; o <<= 1) {
        int t = (threadIdx.x >= o) ? sm[threadIdx.x - o] : 0;
        __syncthreads();
        sm[threadIdx.x] += t;
        __syncthreads();
    }
    if (i < n) off[i + 1] = sm[threadIdx.x];
    if (threadIdx.x == SCAN_B - 1) bsum[blockIdx.x] = sm[threadIdx.x];
}
__global__ void scan2_kernel(int* __restrict__ bsum, int nb) {
    if (threadIdx.x == 0) {
        int run = 0;
        for (int b = 0; b < nb; b++) { int t = bsum[b]; bsum[b] = run; run += t; }
    }
}
__global__ void scan3_kernel(int* __restrict__ off, const int* __restrict__ bsum, int n) {
    int i = blockIdx.x * blockDim.x + threadIdx.x;
    if (i == 0) off[0] = 0;
    if (i < n) off[i + 1] += bsum[i / SCAN_B];
}
__global__ void csr_scatter_kernel(const int* __restrict__ ei, const int* __restrict__ off,
                                   int* __restrict__ cur, int* __restrict__ srcs,
                                   int* __restrict__ slot) {
    int e = blockIdx.x * blockDim.x + threadIdx.x;
    if (e >= E_TOT) return;
    int src, dst;
    edge_endpoints(ei, e, src, dst);
    int pos = atomicAdd(&cur[dst], 1);
    int sl = off[dst] + pos;
    srcs[sl] = src;
    slot[e] = sl;
}

// ---------------- CSR gather aggregate: warp per dst node ----------------
template <int H, int C, bool ELU>
__global__ void aggregate_csr_kernel(const int* __restrict__ off,
                                     const int* __restrict__ srcs,
                                     const float* __restrict__ xp,
                                     const float* __restrict__ pcsr,
                                     const float* __restrict__ z,
                                     const float* __restrict__ bias,
                                     float* __restrict__ out) {
    constexpr int HC = H * C;
    constexpr int PER = HC / 32;
    int gw = (blockIdx.x * blockDim.x + threadIdx.x) >> 5;
    int lane = threadIdx.x & 31;
    if (gw >= N_NODES) return;
    int base = lane * PER;
    constexpr int LANES_PER_HEAD = C / PER;
    int head = (H == 1) ? 0 : (lane / LANES_PER_HEAD);
    int s0 = off[gw], s1 = off[gw + 1];
    float acc[PER];
    #pragma unroll
    for (int j = 0; j < PER; j++) acc[j] = 0.f;

    for (int t = s0; t < s1; t++) {
        int src = srcs[t];
        float pw = pcsr[t * H + head];
        const float4* xs = (const float4*)(xp + (size_t)src * HC + base);
        #pragma unroll
        for (int q = 0; q < PER / 4; q++) {
            float4 v = xs[q];
            acc[q * 4 + 0] = fmaf(v.x, pw, acc[q * 4 + 0]);
            acc[q * 4 + 1] = fmaf(v.y, pw, acc[q * 4 + 1]);
            acc[q * 4 + 2] = fmaf(v.z, pw, acc[q * 4 + 2]);
            acc[q * 4 + 3] = fmaf(v.w, pw, acc[q * 4 + 3]);
        }
    }
    float inv = 1.f / (z[gw * H + head] + 1e-16f);
    float* od = out + (size_t)gw * HC + base;
    #pragma unroll
    for (int q = 0; q < PER / 4; q++) {
        float4 r;
        r.x = acc[q * 4 + 0] * inv + bias[base + q * 4 + 0];
        r.y = acc[q * 4 + 1] * inv + bias[base + q * 4 + 1];
        r.z = acc[q * 4 + 2] * inv + bias[base + q * 4 + 2];
        r.w = acc[q * 4 + 3] * inv + bias[base + q * 4 + 3];
        if (ELU) {
            r.x = r.x > 0.f ? r.x : expm1f(r.x);
            r.y = r.y > 0.f ? r.y : expm1f(r.y);
            r.z = r.z > 0.f ? r.z : expm1f(r.z);
            r.w = r.w > 0.f ? r.w : expm1f(r.w);
        }
        *(float4*)&od[q * 4] = r;
    }
}

// ---------------- host orchestration ----------------
struct Bufs {
    float *xp, *h, *s, *d, *z, *p;
    __nv_bfloat16 *whi, *wlo;
    int *deg, *cur, *off, *bsum, *srcs, *slot;
};

template <int H, int C, bool ELU>
static void run_layer_body(const float* in, int K,
                           const float* a_src, const float* a_dst,
                           const float* bias, const int* ei, const Bufs& b, float* outbuf) {
    constexpr int HCl = H * C;
    {
        dim3 grid(HCl / 128, (N_NODES + 127) / 128);
        gemm_mma_kernel<<<grid, 256, GEMM_SMEM>>>(in, b.whi, b.wlo, b.xp, N_NODES, HCl, K);
    }
    {
        int warps = N_NODES * H;
        scores_kernel<<<(warps * 32 + 255) / 256, 256>>>(b.xp, a_src, a_dst, b.s, b.d,
                                                         N_NODES, H, C);
    }
    {
        int NH = N_NODES * H;
        init_z_kernel<<<(NH + 255) / 256, 256>>>(b.z, NH);
    }
    {
        int tot = E_TOT * H;
        edge_soft_kernel<<<(tot + 255) / 256, 256>>>(ei, b.slot, b.s, b.d, b.z, b.p, H);
    }
    {
        aggregate_csr_kernel<H, C, ELU>
            <<<((size_t)N_NODES * 32 + 255) / 256, 256>>>(b.off, b.srcs, b.xp,
                                                          b.p, b.z, bias, outbuf);
    }
}

static void prep_weights(const float* W, int K, int HCl, const Bufs& b) {
    dim3 tg(HCl / 32, K / 32);
    transpose_convert_kernel<<<tg, dim3(32, 8)>>>(W, b.whi, b.wlo, K, HCl);
}

extern "C" void kernel_launch(void* const* d_in, const int* in_sizes, int n_in,
                              void* d_out, int out_size) {
    const float* x      = (const float*)d_in[0];
    const int*   ei     = (const int*)  d_in[1];
    const float* W0     = (const float*)d_in[2];
    const float* a_src0 = (const float*)d_in[3];
    const float* a_dst0 = (const float*)d_in[4];
    const float* b0     = (const float*)d_in[5];
    const float* W1     = (const float*)d_in[6];
    const float* a_src1 = (const float*)d_in[7];
    const float* a_dst1 = (const float*)d_in[8];
    const float* b1     = (const float*)d_in[9];
    const float* W2     = (const float*)d_in[10];
    const float* a_src2 = (const float*)d_in[11];
    const float* a_dst2 = (const float*)d_in[12];
    const float* b2     = (const float*)d_in[13];

    Bufs b;
    cudaGetSymbolAddress((void**)&b.xp,   g_xp);
    cudaGetSymbolAddress((void**)&b.h,    g_h);
    cudaGetSymbolAddress((void**)&b.whi,  g_whi);
    cudaGetSymbolAddress((void**)&b.wlo,  g_wlo);
    cudaGetSymbolAddress((void**)&b.s,    g_s);
    cudaGetSymbolAddress((void**)&b.d,    g_d);
    cudaGetSymbolAddress((void**)&b.z,    g_z);
    cudaGetSymbolAddress((void**)&b.p,    g_p);
    cudaGetSymbolAddress((void**)&b.deg,  g_deg);
    cudaGetSymbolAddress((void**)&b.cur,  g_cur);
    cudaGetSymbolAddress((void**)&b.off,  g_off);
    cudaGetSymbolAddress((void**)&b.bsum, g_bsum);
    cudaGetSymbolAddress((void**)&b.srcs, g_srcs);
    cudaGetSymbolAddress((void**)&b.slot, g_slot);

    cudaFuncSetAttribute(gemm_mma_kernel, cudaFuncAttributeMaxDynamicSharedMemorySize,
                         GEMM_SMEM);

    // Launch order puts gemm_mma at slot 4 for ncu (-s 5 window).
    prep_weights(W0, 128, 256, b);                                     // 1
    csr_zero_kernel<<<(N_NODES + 255) / 256, 256>>>(b.deg, b.cur);     // 2
    csr_count_kernel<<<(E_TOT + 255) / 256, 256>>>(ei, b.deg);         // 3
    {
        dim3 grid(2, (N_NODES + 127) / 128);
        gemm_mma_kernel<<<grid, 256, GEMM_SMEM>>>(x, b.whi, b.wlo, b.xp, N_NODES, 256, 128); // 4
    }
    int nblk = (N_NODES + SCAN_B - 1) / SCAN_B;
    scan1_kernel<<<nblk, SCAN_B>>>(b.deg, b.off, b.bsum, N_NODES);     // 5
    scan2_kernel<<<1, 32>>>(b.bsum, nblk);                             // 6
    scan3_kernel<<<(N_NODES + 255) / 256, 256>>>(b.off, b.bsum, N_NODES);            // 7
    csr_scatter_kernel<<<(E_TOT + 255) / 256, 256>>>(ei, b.off, b.cur, b.srcs, b.slot); // 8

    // rest of layer 0 (gemm already done above)
    {
        int warps = N_NODES * 4;
        scores_kernel<<<(warps * 32 + 255) / 256, 256>>>(b.xp, a_src0, a_dst0, b.s, b.d,
                                                         N_NODES, 4, 64);
        init_z_kernel<<<(N_NODES * 4 + 255) / 256, 256>>>(b.z, N_NODES * 4);
        edge_soft_kernel<<<(E_TOT * 4 + 255) / 256, 256>>>(ei, b.slot, b.s, b.d, b.z, b.p, 4);
        aggregate_csr_kernel<4, 64, true>
            <<<((size_t)N_NODES * 32 + 255) / 256, 256>>>(b.off, b.srcs, b.xp,
                                                          b.p, b.z, b0, b.h);
    }
    // layer 1
    prep_weights(W1, 256, 256, b);
    run_layer_body<4, 64, true>(b.h, 256, a_src1, a_dst1, b1, ei, b, b.h);
    // layer 2
    prep_weights(W2, 256, 128, b);
    run_layer_body<1, 128, false>(b.h, 256, a_src2, a_dst2, b2, ei, b, (float*)d_out);
}

// round 6
// speedup vs baseline: 6.0702x; 1.0480x over previous
#include <cuda_runtime.h>
#include <cuda_bf16.h>
#include <cuda_fp16.h>
#include <cstdint>

#define N_NODES 50000
#define E_RAW   800000
#define E_TOT   (E_RAW + N_NODES)   // 850000 with self loops
#define MAXH    4
#define MAXHC   256
#define SCAN_B  1024

// ---------------- device scratch (static, allocation-free) ----------------
__device__ __half g_xph[(size_t)N_NODES * MAXHC];   // transformed features, fp16
__device__ float g_h [(size_t)N_NODES * MAXHC];     // layer output (fp32)
__device__ __nv_bfloat16 g_whi[MAXHC * MAXHC];      // W^T hi [N,K] bf16
__device__ __nv_bfloat16 g_wlo[MAXHC * MAXHC];      // W^T lo [N,K] bf16
__device__ float g_s [(size_t)N_NODES * MAXH];
__device__ float g_d [(size_t)N_NODES * MAXH];
__device__ float g_z [(size_t)N_NODES * MAXH];
__device__ float g_p [(size_t)E_TOT   * MAXH];      // exp weights (CSR order)
// CSR by destination
__device__ int g_deg [N_NODES];
__device__ int g_cur [N_NODES];
__device__ int g_off [N_NODES + 1];
__device__ int g_bsum[64];
__device__ int g_srcs[E_TOT];
__device__ int g_slot[E_TOT];                       // edge id -> CSR slot

// ---------------- small PTX helpers ----------------
__device__ __forceinline__ uint32_t smem_u32(const void* p) {
    uint32_t a;
    asm("{ .reg .u64 t; cvta.to.shared.u64 t, %1; cvt.u32.u64 %0, t; }" : "=r"(a) : "l"(p));
    return a;
}
__device__ __forceinline__ void ldm_x4(uint32_t& r0, uint32_t& r1, uint32_t& r2, uint32_t& r3,
                                       uint32_t addr) {
    asm volatile("ldmatrix.sync.aligned.m8n8.x4.shared.b16 {%0,%1,%2,%3}, [%4];"
                 : "=r"(r0), "=r"(r1), "=r"(r2), "=r"(r3) : "r"(addr));
}
__device__ __forceinline__ void mma_bf16(float* d, const uint32_t* a, uint32_t b0, uint32_t b1) {
    asm volatile(
        "mma.sync.aligned.m16n8k16.row.col.f32.bf16.bf16.f32 "
        "{%0,%1,%2,%3}, {%4,%5,%6,%7}, {%8,%9}, {%0,%1,%2,%3};"
        : "+f"(d[0]), "+f"(d[1]), "+f"(d[2]), "+f"(d[3])
        : "r"(a[0]), "r"(a[1]), "r"(a[2]), "r"(a[3]), "r"(b0), "r"(b1));
}
__device__ __forceinline__ void cp_async16(uint32_t dst, const void* src) {
    asm volatile("cp.async.ca.shared.global [%0], [%1], 16;" :: "r"(dst), "l"(src));
}
#define CP_COMMIT() asm volatile("cp.async.commit_group;")
#define CP_WAIT0()  asm volatile("cp.async.wait_group 0;" ::: "memory")

// ---------------- weight transpose + bf16 split: Wt[n,k] = W[k,n] ----------------
__global__ void transpose_convert_kernel(const float* __restrict__ W,
                                         __nv_bfloat16* __restrict__ Whi,
                                         __nv_bfloat16* __restrict__ Wlo,
                                         int K, int N) {
    __shared__ float t[32][33];
    int bn = blockIdx.x * 32, bk = blockIdx.y * 32;
    int x = threadIdx.x, y = threadIdx.y;
    #pragma unroll
    for (int j = 0; j < 32; j += 8) t[y + j][x] = W[(size_t)(bk + y + j) * N + bn + x];
    __syncthreads();
    #pragma unroll
    for (int j = 0; j < 32; j += 8) {
        float v = t[x][y + j];
        __nv_bfloat16 hi = __float2bfloat16_rn(v);
        __nv_bfloat16 lo = __float2bfloat16_rn(v - __bfloat162float(hi));
        size_t o = (size_t)(bn + y + j) * K + bk + x;
        Whi[o] = hi;
        Wlo[o] = lo;
    }
}

// ---------------- tensor GEMM via mma.sync, split bf16, double-buffered ----------------
// C[M,N](fp16) = A[M,K](fp32) @ Bt[N,K]^T (bf16 hi/lo precomputed).
// Block tile 128x128, K-chunk 32. 8 warps (4Mx2N), warp tile 32x64.
#define PITCH    40                   // bf16 per smem row (32 + 8 pad) = 80 bytes
#define TILE_B   (128 * PITCH * 2)    // 10240 bytes per matrix-half
#define GEMM_SMEM (8 * TILE_B)        // 2 stages x (Ahi,Alo,Bhi,Blo)

__global__ __launch_bounds__(256, 2) void gemm_mma_kernel(const float* __restrict__ A,
                                                          const __nv_bfloat16* __restrict__ Bh,
                                                          const __nv_bfloat16* __restrict__ Bl,
                                                          __half* __restrict__ C,
                                                          int M, int N, int K) {
    extern __shared__ __align__(16) char sm[];
    uint32_t base = smem_u32(sm);

    int tid = threadIdx.x, lane = tid & 31, wid = tid >> 5;
    int wm = (wid >> 1) * 32;
    int wn = (wid & 1) * 64;
    int brow = blockIdx.y * 128;
    int bcol = blockIdx.x * 128;
    int valid = M - brow; if (valid > 128) valid = 128;

    float acc[2][8][4];
    #pragma unroll
    for (int i = 0; i < 2; i++)
        #pragma unroll
        for (int j = 0; j < 8; j++)
            #pragma unroll
            for (int q = 0; q < 4; q++) acc[i][j][q] = 0.f;

    int la_r[4], la_c[4];
    #pragma unroll
    for (int j = 0; j < 4; j++) {
        int i = tid + j * 256;
        la_r[j] = i >> 3;
        la_c[j] = (i & 7) << 2;
    }
    int a_r = ((lane >> 3) & 1) * 8 + (lane & 7);
    int a_cb = (lane >> 4) * 16;
    int b_r = (lane >> 4) * 8 + (lane & 7);
    int b_cb = ((lane >> 3) & 1) * 16;

    float4 av[4];
    int nch = K >> 5;

    auto ldgA = [&](int ch) {
        int k0 = ch << 5;
        #pragma unroll
        for (int j = 0; j < 4; j++) {
            if (la_r[j] < valid)
                av[j] = *(const float4*)&A[(size_t)(brow + la_r[j]) * K + k0 + la_c[j]];
            else
                av[j] = make_float4(0.f, 0.f, 0.f, 0.f);
        }
    };
    auto loadB_async = [&](int stage, int ch) {
        int k0 = ch << 5;
        #pragma unroll
        for (int j = 0; j < 4; j++) {
            int i = tid + j * 256;
            int seg = i & 3, row = (i >> 2) & 127, half = i >> 9;
            const __nv_bfloat16* src = (half ? Bl : Bh) + (size_t)(bcol + row) * K + k0 + seg * 8;
            uint32_t dst = base + (uint32_t)((stage * 4 + 2 + half) * TILE_B)
                         + (uint32_t)(row * (PITCH * 2) + seg * 16);
            cp_async16(dst, src);
        }
    };
    auto convA_sts = [&](int stage) {
        uint32_t hi_b = base + (uint32_t)((stage * 4 + 0) * TILE_B);
        uint32_t lo_b = base + (uint32_t)((stage * 4 + 1) * TILE_B);
        #pragma unroll
        for (int j = 0; j < 4; j++) {
            float4 v = av[j];
            __nv_bfloat16 h0 = __float2bfloat16_rn(v.x), h1 = __float2bfloat16_rn(v.y);
            __nv_bfloat16 h2 = __float2bfloat16_rn(v.z), h3 = __float2bfloat16_rn(v.w);
            __nv_bfloat16 l0 = __float2bfloat16_rn(v.x - __bfloat162float(h0));
            __nv_bfloat16 l1 = __float2bfloat16_rn(v.y - __bfloat162float(h1));
            __nv_bfloat16 l2 = __float2bfloat16_rn(v.z - __bfloat162float(h2));
            __nv_bfloat16 l3 = __float2bfloat16_rn(v.w - __bfloat162float(h3));
            uint2 uh, ul;
            uh.x = (uint32_t)__bfloat16_as_ushort(h0) | ((uint32_t)__bfloat16_as_ushort(h1) << 16);
            uh.y = (uint32_t)__bfloat16_as_ushort(h2) | ((uint32_t)__bfloat16_as_ushort(h3) << 16);
            ul.x = (uint32_t)__bfloat16_as_ushort(l0) | ((uint32_t)__bfloat16_as_ushort(l1) << 16);
            ul.y = (uint32_t)__bfloat16_as_ushort(l2) | ((uint32_t)__bfloat16_as_ushort(l3) << 16);
            uint32_t o = (uint32_t)(la_r[j] * (PITCH * 2) + la_c[j] * 2);
            asm volatile("st.shared.v2.b32 [%0], {%1,%2};" :: "r"(hi_b + o), "r"(uh.x), "r"(uh.y));
            asm volatile("st.shared.v2.b32 [%0], {%1,%2};" :: "r"(lo_b + o), "r"(ul.x), "r"(ul.y));
        }
    };

    ldgA(0);
    loadB_async(0, 0);
    CP_COMMIT();
    convA_sts(0);
    CP_WAIT0();
    __syncthreads();

    for (int ch = 0; ch < nch; ch++) {
        int cur = ch & 1, nxt = cur ^ 1;
        bool more = (ch + 1 < nch);
        if (more) {
            ldgA(ch + 1);
            loadB_async(nxt, ch + 1);
            CP_COMMIT();
        }
        uint32_t sAhi = base + (uint32_t)((cur * 4 + 0) * TILE_B);
        uint32_t sAlo = base + (uint32_t)((cur * 4 + 1) * TILE_B);
        uint32_t sBhi = base + (uint32_t)((cur * 4 + 2) * TILE_B);
        uint32_t sBlo = base + (uint32_t)((cur * 4 + 3) * TILE_B);
        #pragma unroll
        for (int ks = 0; ks < 2; ks++) {
            int kb = ks * 32;
            uint32_t ah[2][4], al[2][4];
            #pragma unroll
            for (int mt = 0; mt < 2; mt++) {
                uint32_t ro = (uint32_t)((wm + mt * 16 + a_r) * (PITCH * 2) + kb + a_cb);
                ldm_x4(ah[mt][0], ah[mt][1], ah[mt][2], ah[mt][3], sAhi + ro);
                ldm_x4(al[mt][0], al[mt][1], al[mt][2], al[mt][3], sAlo + ro);
            }
            #pragma unroll
            for (int nt = 0; nt < 4; nt++) {
                uint32_t ro = (uint32_t)((wn + nt * 16 + b_r) * (PITCH * 2) + kb + b_cb);
                uint32_t bh[4], bl[4];
                ldm_x4(bh[0], bh[1], bh[2], bh[3], sBhi + ro);
                ldm_x4(bl[0], bl[1], bl[2], bl[3], sBlo + ro);
                #pragma unroll
                for (int mt = 0; mt < 2; mt++) {
                    mma_bf16(acc[mt][nt * 2 + 0], ah[mt], bh[0], bh[1]);
                    mma_bf16(acc[mt][nt * 2 + 1], ah[mt], bh[2], bh[3]);
                    mma_bf16(acc[mt][nt * 2 + 0], ah[mt], bl[0], bl[1]);
                    mma_bf16(acc[mt][nt * 2 + 1], ah[mt], bl[2], bl[3]);
                    mma_bf16(acc[mt][nt * 2 + 0], al[mt], bh[0], bh[1]);
                    mma_bf16(acc[mt][nt * 2 + 1], al[mt], bh[2], bh[3]);
                }
            }
        }
        if (more) {
            convA_sts(nxt);
            CP_WAIT0();
        }
        __syncthreads();
    }

    // epilogue -> fp16
    int er = lane >> 2, ec = (lane & 3) * 2;
    #pragma unroll
    for (int mt = 0; mt < 2; mt++) {
        int r0 = brow + wm + mt * 16 + er;
        #pragma unroll
        for (int nt = 0; nt < 8; nt++) {
            int col = bcol + wn + nt * 8 + ec;
            if (r0 < M)
                *(__half2*)&C[(size_t)r0 * N + col] =
                    __floats2half2_rn(acc[mt][nt][0], acc[mt][nt][1]);
            if (r0 + 8 < M)
                *(__half2*)&C[(size_t)(r0 + 8) * N + col] =
                    __floats2half2_rn(acc[mt][nt][2], acc[mt][nt][3]);
        }
    }
}

// ---------------- per-node attention scores: warp per (n,h), fp16 xp ----------------
__global__ void scores_kernel(const __half* __restrict__ xp,
                              const float* __restrict__ a_src,
                              const float* __restrict__ a_dst,
                              float* __restrict__ s, float* __restrict__ d,
                              int N, int H, int C) {
    int gw = (blockIdx.x * blockDim.x + threadIdx.x) >> 5;
    int lane = threadIdx.x & 31;
    if (gw >= N * H) return;
    int h = gw % H, n = gw / H;
    const __half* row = xp + (size_t)n * H * C + h * C;
    float ss = 0.f, dd = 0.f;
    for (int c = lane * 2; c < C; c += 64) {
        float2 f = __half22float2(*(const __half2*)(row + c));
        ss += f.x * a_src[h * C + c] + f.y * a_src[h * C + c + 1];
        dd += f.x * a_dst[h * C + c] + f.y * a_dst[h * C + c + 1];
    }
    #pragma unroll
    for (int o = 16; o; o >>= 1) {
        ss += __shfl_xor_sync(0xffffffffu, ss, o);
        dd += __shfl_xor_sync(0xffffffffu, dd, o);
    }
    if (lane == 0) { s[gw] = ss; d[gw] = dd; }
}

// ---------------- init z ----------------
__global__ void init_z_kernel(float* __restrict__ z, int NH) {
    int i = blockIdx.x * blockDim.x + threadIdx.x;
    if (i < NH) z[i] = 0.f;
}

// ---------------- fused edge softmax (no max shift; overflow-guarded) ----------------
__global__ void edge_soft_kernel(const int* __restrict__ ei, const int* __restrict__ slot,
                                 const float* __restrict__ s, const float* __restrict__ d,
                                 float* __restrict__ z, float* __restrict__ pcsr, int H) {
    int idx = blockIdx.x * blockDim.x + threadIdx.x;
    if (idx >= E_TOT * H) return;
    int h = idx % H, e = idx / H;
    int src, dst;
    if (e < E_RAW) { src = ei[e]; dst = ei[E_RAW + e]; }
    else           { src = dst = e - E_RAW; }
    float v = s[src * H + h] + d[dst * H + h];
    v = v > 0.f ? v : 0.2f * v;
    float p = __expf(fminf(v, 80.f));
    pcsr[slot[e] * H + h] = p;
    atomicAdd(&z[dst * H + h], p);
}

// ---------------- CSR build ----------------
__device__ __forceinline__ void edge_endpoints(const int* __restrict__ ei, int e,
                                               int& src, int& dst) {
    if (e < E_RAW) { src = ei[e]; dst = ei[E_RAW + e]; }
    else           { src = dst = e - E_RAW; }
}
__global__ void csr_zero_kernel(int* __restrict__ deg, int* __restrict__ cur) {
    int i = blockIdx.x * blockDim.x + threadIdx.x;
    if (i < N_NODES) { deg[i] = 0; cur[i] = 0; }
}
__global__ void csr_count_kernel(const int* __restrict__ ei, int* __restrict__ deg) {
    int e = blockIdx.x * blockDim.x + threadIdx.x;
    if (e >= E_TOT) return;
    int dst = (e < E_RAW) ? ei[E_RAW + e] : e - E_RAW;
    atomicAdd(&deg[dst], 1);
}
__global__ void scan1_kernel(const int* __restrict__ deg, int* __restrict__ off,
                             int* __restrict__ bsum, int n) {
    __shared__ int sm[SCAN_B];
    int i = blockIdx.x * SCAN_B + threadIdx.x;
    int v = (i < n) ? deg[i] : 0;
    sm[threadIdx.x] = v;
    __syncthreads();
    for (int o = 1; o < SCAN_B; o <<= 1) {
        int t = (threadIdx.x >= o) ? sm[threadIdx.x - o] : 0;
        __syncthreads();
        sm[threadIdx.x] += t;
        __syncthreads();
    }
    if (i < n) off[i + 1] = sm[threadIdx.x];
    if (threadIdx.x == SCAN_B - 1) bsum[blockIdx.x] = sm[threadIdx.x];
}
__global__ void scan2_kernel(int* __restrict__ bsum, int nb) {
    if (threadIdx.x == 0) {
        int run = 0;
        for (int b = 0; b < nb; b++) { int t = bsum[b]; bsum[b] = run; run += t; }
    }
}
__global__ void scan3_kernel(int* __restrict__ off, const int* __restrict__ bsum, int n) {
    int i = blockIdx.x * blockDim.x + threadIdx.x;
    if (i == 0) off[0] = 0;
    if (i < n) off[i + 1] += bsum[i / SCAN_B];
}
__global__ void csr_scatter_kernel(const int* __restrict__ ei, const int* __restrict__ off,
                                   int* __restrict__ cur, int* __restrict__ srcs,
                                   int* __restrict__ slot) {
    int e = blockIdx.x * blockDim.x + threadIdx.x;
    if (e >= E_TOT) return;
    int src, dst;
    edge_endpoints(ei, e, src, dst);
    int pos = atomicAdd(&cur[dst], 1);
    int sl = off[dst] + pos;
    srcs[sl] = src;
    slot[e] = sl;
}

// ---------------- CSR gather aggregate: warp per dst node, fp16 xp ----------------
template <int H, int C, bool ELU>
__global__ void aggregate_csr_kernel(const int* __restrict__ off,
                                     const int* __restrict__ srcs,
                                     const __half* __restrict__ xp,
                                     const float* __restrict__ pcsr,
                                     const float* __restrict__ z,
                                     const float* __restrict__ bias,
                                     float* __restrict__ out) {
    constexpr int HC = H * C;
    constexpr int PER = HC / 32;    // 8 (H=4,C=64) or 4 (H=1,C=128)
    int gw = (blockIdx.x * blockDim.x + threadIdx.x) >> 5;
    int lane = threadIdx.x & 31;
    if (gw >= N_NODES) return;
    int base = lane * PER;
    constexpr int LANES_PER_HEAD = C / PER;
    int head = (H == 1) ? 0 : (lane / LANES_PER_HEAD);
    int s0 = off[gw], s1 = off[gw + 1];
    float acc[PER];
    #pragma unroll
    for (int j = 0; j < PER; j++) acc[j] = 0.f;

    auto body = [&](int t) {
        int src = srcs[t];
        float pw = pcsr[t * H + head];
        const __half2* xs = (const __half2*)(xp + (size_t)src * HC + base);
        #pragma unroll
        for (int q = 0; q < PER / 2; q++) {
            float2 f = __half22float2(xs[q]);
            acc[q * 2 + 0] = fmaf(f.x, pw, acc[q * 2 + 0]);
            acc[q * 2 + 1] = fmaf(f.y, pw, acc[q * 2 + 1]);
        }
    };
    int t = s0;
    for (; t + 1 < s1; t += 2) {    // 2-edge unroll for MLP
        int srcA = srcs[t], srcB = srcs[t + 1];
        float pwA = pcsr[t * H + head], pwB = pcsr[(t + 1) * H + head];
        const __half2* xa = (const __half2*)(xp + (size_t)srcA * HC + base);
        const __half2* xb = (const __half2*)(xp + (size_t)srcB * HC + base);
        #pragma unroll
        for (int q = 0; q < PER / 2; q++) {
            float2 fa = __half22float2(xa[q]);
            float2 fb = __half22float2(xb[q]);
            acc[q * 2 + 0] = fmaf(fa.x, pwA, acc[q * 2 + 0]);
            acc[q * 2 + 1] = fmaf(fa.y, pwA, acc[q * 2 + 1]);
            acc[q * 2 + 0] = fmaf(fb.x, pwB, acc[q * 2 + 0]);
            acc[q * 2 + 1] = fmaf(fb.y, pwB, acc[q * 2 + 1]);
        }
    }
    if (t < s1) body(t);

    float inv = 1.f / (z[gw * H + head] + 1e-16f);
    float* od = out + (size_t)gw * HC + base;
    #pragma unroll
    for (int q = 0; q < PER / 4; q++) {
        float4 r;
        r.x = acc[q * 4 + 0] * inv + bias[base + q * 4 + 0];
        r.y = acc[q * 4 + 1] * inv + bias[base + q * 4 + 1];
        r.z = acc[q * 4 + 2] * inv + bias[base + q * 4 + 2];
        r.w = acc[q * 4 + 3] * inv + bias[base + q * 4 + 3];
        if (ELU) {
            r.x = r.x > 0.f ? r.x : expm1f(r.x);
            r.y = r.y > 0.f ? r.y : expm1f(r.y);
            r.z = r.z > 0.f ? r.z : expm1f(r.z);
            r.w = r.w > 0.f ? r.w : expm1f(r.w);
        }
        *(float4*)&od[q * 4] = r;
    }
}

// ---------------- host orchestration ----------------
struct Bufs {
    __half *xph;
    float *h, *s, *d, *z, *p;
    __nv_bfloat16 *whi, *wlo;
    int *deg, *cur, *off, *bsum, *srcs, *slot;
};

template <int H, int C, bool ELU>
static void run_layer_body(const float* in, int K,
                           const float* a_src, const float* a_dst,
                           const float* bias, const int* ei, const Bufs& b, float* outbuf) {
    constexpr int HCl = H * C;
    {
        dim3 grid(HCl / 128, (N_NODES + 127) / 128);
        gemm_mma_kernel<<<grid, 256, GEMM_SMEM>>>(in, b.whi, b.wlo, b.xph, N_NODES, HCl, K);
    }
    {
        int warps = N_NODES * H;
        scores_kernel<<<(warps * 32 + 255) / 256, 256>>>(b.xph, a_src, a_dst, b.s, b.d,
                                                         N_NODES, H, C);
    }
    {
        int NH = N_NODES * H;
        init_z_kernel<<<(NH + 255) / 256, 256>>>(b.z, NH);
    }
    {
        int tot = E_TOT * H;
        edge_soft_kernel<<<(tot + 255) / 256, 256>>>(ei, b.slot, b.s, b.d, b.z, b.p, H);
    }
    {
        aggregate_csr_kernel<H, C, ELU>
            <<<((size_t)N_NODES * 32 + 255) / 256, 256>>>(b.off, b.srcs, b.xph,
                                                          b.p, b.z, bias, outbuf);
    }
}

static void prep_weights(const float* W, int K, int HCl, const Bufs& b) {
    dim3 tg(HCl / 32, K / 32);
    transpose_convert_kernel<<<tg, dim3(32, 8)>>>(W, b.whi, b.wlo, K, HCl);
}

extern "C" void kernel_launch(void* const* d_in, const int* in_sizes, int n_in,
                              void* d_out, int out_size) {
    const float* x      = (const float*)d_in[0];
    const int*   ei     = (const int*)  d_in[1];
    const float* W0     = (const float*)d_in[2];
    const float* a_src0 = (const float*)d_in[3];
    const float* a_dst0 = (const float*)d_in[4];
    const float* b0     = (const float*)d_in[5];
    const float* W1     = (const float*)d_in[6];
    const float* a_src1 = (const float*)d_in[7];
    const float* a_dst1 = (const float*)d_in[8];
    const float* b1     = (const float*)d_in[9];
    const float* W2     = (const float*)d_in[10];
    const float* a_src2 = (const float*)d_in[11];
    const float* a_dst2 = (const float*)d_in[12];
    const float* b2     = (const float*)d_in[13];

    Bufs b;
    cudaGetSymbolAddress((void**)&b.xph,  g_xph);
    cudaGetSymbolAddress((void**)&b.h,    g_h);
    cudaGetSymbolAddress((void**)&b.whi,  g_whi);
    cudaGetSymbolAddress((void**)&b.wlo,  g_wlo);
    cudaGetSymbolAddress((void**)&b.s,    g_s);
    cudaGetSymbolAddress((void**)&b.d,    g_d);
    cudaGetSymbolAddress((void**)&b.z,    g_z);
    cudaGetSymbolAddress((void**)&b.p,    g_p);
    cudaGetSymbolAddress((void**)&b.deg,  g_deg);
    cudaGetSymbolAddress((void**)&b.cur,  g_cur);
    cudaGetSymbolAddress((void**)&b.off,  g_off);
    cudaGetSymbolAddress((void**)&b.bsum, g_bsum);
    cudaGetSymbolAddress((void**)&b.srcs, g_srcs);
    cudaGetSymbolAddress((void**)&b.slot, g_slot);

    cudaFuncSetAttribute(gemm_mma_kernel, cudaFuncAttributeMaxDynamicSharedMemorySize,
                         GEMM_SMEM);

    // Launch order keeps gemm_mma at slot 4 for ncu.
    prep_weights(W0, 128, 256, b);                                     // 1
    csr_zero_kernel<<<(N_NODES + 255) / 256, 256>>>(b.deg, b.cur);     // 2
    csr_count_kernel<<<(E_TOT + 255) / 256, 256>>>(ei, b.deg);         // 3
    {
        dim3 grid(2, (N_NODES + 127) / 128);
        gemm_mma_kernel<<<grid, 256, GEMM_SMEM>>>(x, b.whi, b.wlo, b.xph, N_NODES, 256, 128); // 4
    }
    int nblk = (N_NODES + SCAN_B - 1) / SCAN_B;
    scan1_kernel<<<nblk, SCAN_B>>>(b.deg, b.off, b.bsum, N_NODES);     // 5
    scan2_kernel<<<1, 32>>>(b.bsum, nblk);                             // 6
    scan3_kernel<<<(N_NODES + 255) / 256, 256>>>(b.off, b.bsum, N_NODES);               // 7
    csr_scatter_kernel<<<(E_TOT + 255) / 256, 256>>>(ei, b.off, b.cur, b.srcs, b.slot); // 8

    // rest of layer 0 (gemm already done above)
    {
        int warps = N_NODES * 4;
        scores_kernel<<<(warps * 32 + 255) / 256, 256>>>(b.xph, a_src0, a_dst0, b.s, b.d,
                                                         N_NODES, 4, 64);
        init_z_kernel<<<(N_NODES * 4 + 255) / 256, 256>>>(b.z, N_NODES * 4);
        edge_soft_kernel<<<(E_TOT * 4 + 255) / 256, 256>>>(ei, b.slot, b.s, b.d, b.z, b.p, 4);
        aggregate_csr_kernel<4, 64, true>
            <<<((size_t)N_NODES * 32 + 255) / 256, 256>>>(b.off, b.srcs, b.xph,
                                                          b.p, b.z, b0, b.h);
    }
    // layer 1
    prep_weights(W1, 256, 256, b);
    run_layer_body<4, 64, true>(b.h, 256, a_src1, a_dst1, b1, ei, b, b.h);
    // layer 2
    prep_weights(W2, 256, 128, b);
    run_layer_body<1, 128, false>(b.h, 256, a_src2, a_dst2, b2, ei, b, (float*)d_out);
}

// round 7
// speedup vs baseline: 7.7280x; 1.2731x over previous
#include <cuda_runtime.h>
#include <cuda_bf16.h>
#include <cuda_fp16.h>
#include <cstdint>

#define N_NODES 50000
#define E_RAW   800000
#define E_TOT   (E_RAW + N_NODES)   // 850000 with self loops
#define MAXH    4
#define MAXHC   256
#define SCAN_B  1024

// ---------------- device scratch (static, allocation-free) ----------------
__device__ __half g_xph[(size_t)N_NODES * MAXHC];   // transformed features, fp16
__device__ float g_h [(size_t)N_NODES * MAXHC];     // layer output (fp32)
__device__ __nv_bfloat16 g_whi[MAXHC * MAXHC];      // W^T hi [N,K] bf16
__device__ __nv_bfloat16 g_wlo[MAXHC * MAXHC];      // W^T lo [N,K] bf16
__device__ float g_s [(size_t)N_NODES * MAXH];
__device__ float g_d [(size_t)N_NODES * MAXH];
// CSR by destination
__device__ int g_deg [N_NODES];
__device__ int g_cur [N_NODES];
__device__ int g_off [N_NODES + 1];
__device__ int g_bsum[64];
__device__ int g_srcs[E_TOT];

// ---------------- small PTX helpers ----------------
__device__ __forceinline__ uint32_t smem_u32(const void* p) {
    uint32_t a;
    asm("{ .reg .u64 t; cvta.to.shared.u64 t, %1; cvt.u32.u64 %0, t; }" : "=r"(a) : "l"(p));
    return a;
}
__device__ __forceinline__ void ldm_x4(uint32_t& r0, uint32_t& r1, uint32_t& r2, uint32_t& r3,
                                       uint32_t addr) {
    asm volatile("ldmatrix.sync.aligned.m8n8.x4.shared.b16 {%0,%1,%2,%3}, [%4];"
                 : "=r"(r0), "=r"(r1), "=r"(r2), "=r"(r3) : "r"(addr));
}
__device__ __forceinline__ void mma_bf16(float* d, const uint32_t* a, uint32_t b0, uint32_t b1) {
    asm volatile(
        "mma.sync.aligned.m16n8k16.row.col.f32.bf16.bf16.f32 "
        "{%0,%1,%2,%3}, {%4,%5,%6,%7}, {%8,%9}, {%0,%1,%2,%3};"
        : "+f"(d[0]), "+f"(d[1]), "+f"(d[2]), "+f"(d[3])
        : "r"(a[0]), "r"(a[1]), "r"(a[2]), "r"(a[3]), "r"(b0), "r"(b1));
}
__device__ __forceinline__ void cp_async16(uint32_t dst, const void* src) {
    asm volatile("cp.async.ca.shared.global [%0], [%1], 16;" :: "r"(dst), "l"(src));
}
#define CP_COMMIT() asm volatile("cp.async.commit_group;")
#define CP_WAIT0()  asm volatile("cp.async.wait_group 0;" ::: "memory")

// ---------------- weight transpose + bf16 split: Wt[n,k] = W[k,n] ----------------
__global__ void transpose_convert_kernel(const float* __restrict__ W,
                                         __nv_bfloat16* __restrict__ Whi,
                                         __nv_bfloat16* __restrict__ Wlo,
                                         int K, int N) {
    __shared__ float t[32][33];
    int bn = blockIdx.x * 32, bk = blockIdx.y * 32;
    int x = threadIdx.x, y = threadIdx.y;
    #pragma unroll
    for (int j = 0; j < 32; j += 8) t[y + j][x] = W[(size_t)(bk + y + j) * N + bn + x];
    __syncthreads();
    #pragma unroll
    for (int j = 0; j < 32; j += 8) {
        float v = t[x][y + j];
        __nv_bfloat16 hi = __float2bfloat16_rn(v);
        __nv_bfloat16 lo = __float2bfloat16_rn(v - __bfloat162float(hi));
        size_t o = (size_t)(bn + y + j) * K + bk + x;
        Whi[o] = hi;
        Wlo[o] = lo;
    }
}

// ---------------- zero s/d (only needed for the atomic path, C=128) ----------------
__global__ void init_sd_kernel(float* __restrict__ s, float* __restrict__ d, int n) {
    int i = blockIdx.x * blockDim.x + threadIdx.x;
    if (i < n) { s[i] = 0.f; d[i] = 0.f; }
}

// ---------------- tensor GEMM via mma.sync, split bf16, double-buffered ----------------
// C[M,N](fp16) = A[M,K](fp32) @ Bt[N,K]^T (bf16 hi/lo precomputed).
// Fused epilogue also emits attention scores s[n,h], d[n,h].
// Block tile 128x128, K-chunk 32. 8 warps (4Mx2N), warp tile 32x64.
#define PITCH    40                   // bf16 per smem row (32 + 8 pad) = 80 bytes
#define TILE_B   (128 * PITCH * 2)    // 10240 bytes per matrix-half
#define GEMM_SMEM (8 * TILE_B)        // 2 stages x (Ahi,Alo,Bhi,Blo)

__global__ __launch_bounds__(256, 2) void gemm_mma_kernel(const float* __restrict__ A,
                                                          const __nv_bfloat16* __restrict__ Bh,
                                                          const __nv_bfloat16* __restrict__ Bl,
                                                          __half* __restrict__ C,
                                                          const float* __restrict__ Asrc,
                                                          const float* __restrict__ Adst,
                                                          float* __restrict__ sArr,
                                                          float* __restrict__ dArr,
                                                          int M, int N, int K, int Chead) {
    extern __shared__ __align__(16) char sm[];
    uint32_t base = smem_u32(sm);

    int tid = threadIdx.x, lane = tid & 31, wid = tid >> 5;
    int wm = (wid >> 1) * 32;
    int wn = (wid & 1) * 64;
    int brow = blockIdx.y * 128;
    int bcol = blockIdx.x * 128;
    int valid = M - brow; if (valid > 128) valid = 128;

    float acc[2][8][4];
    #pragma unroll
    for (int i = 0; i < 2; i++)
        #pragma unroll
        for (int j = 0; j < 8; j++)
            #pragma unroll
            for (int q = 0; q < 4; q++) acc[i][j][q] = 0.f;

    int la_r[4], la_c[4];
    #pragma unroll
    for (int j = 0; j < 4; j++) {
        int i = tid + j * 256;
        la_r[j] = i >> 3;
        la_c[j] = (i & 7) << 2;
    }
    int a_r = ((lane >> 3) & 1) * 8 + (lane & 7);
    int a_cb = (lane >> 4) * 16;
    int b_r = (lane >> 4) * 8 + (lane & 7);
    int b_cb = ((lane >> 3) & 1) * 16;

    float4 av[4];
    int nch = K >> 5;

    auto ldgA = [&](int ch) {
        int k0 = ch << 5;
        #pragma unroll
        for (int j = 0; j < 4; j++) {
            if (la_r[j] < valid)
                av[j] = *(const float4*)&A[(size_t)(brow + la_r[j]) * K + k0 + la_c[j]];
            else
                av[j] = make_float4(0.f, 0.f, 0.f, 0.f);
        }
    };
    auto loadB_async = [&](int stage, int ch) {
        int k0 = ch << 5;
        #pragma unroll
        for (int j = 0; j < 4; j++) {
            int i = tid + j * 256;
            int seg = i & 3, row = (i >> 2) & 127, half = i >> 9;
            const __nv_bfloat16* src = (half ? Bl : Bh) + (size_t)(bcol + row) * K + k0 + seg * 8;
            uint32_t dst = base + (uint32_t)((stage * 4 + 2 + half) * TILE_B)
                         + (uint32_t)(row * (PITCH * 2) + seg * 16);
            cp_async16(dst, src);
        }
    };
    auto convA_sts = [&](int stage) {
        uint32_t hi_b = base + (uint32_t)((stage * 4 + 0) * TILE_B);
        uint32_t lo_b = base + (uint32_t)((stage * 4 + 1) * TILE_B);
        #pragma unroll
        for (int j = 0; j < 4; j++) {
            float4 v = av[j];
            __nv_bfloat16 h0 = __float2bfloat16_rn(v.x), h1 = __float2bfloat16_rn(v.y);
            __nv_bfloat16 h2 = __float2bfloat16_rn(v.z), h3 = __float2bfloat16_rn(v.w);
            __nv_bfloat16 l0 = __float2bfloat16_rn(v.x - __bfloat162float(h0));
            __nv_bfloat16 l1 = __float2bfloat16_rn(v.y - __bfloat162float(h1));
            __nv_bfloat16 l2 = __float2bfloat16_rn(v.z - __bfloat162float(h2));
            __nv_bfloat16 l3 = __float2bfloat16_rn(v.w - __bfloat162float(h3));
            uint2 uh, ul;
            uh.x = (uint32_t)__bfloat16_as_ushort(h0) | ((uint32_t)__bfloat16_as_ushort(h1) << 16);
            uh.y = (uint32_t)__bfloat16_as_ushort(h2) | ((uint32_t)__bfloat16_as_ushort(h3) << 16);
            ul.x = (uint32_t)__bfloat16_as_ushort(l0) | ((uint32_t)__bfloat16_as_ushort(l1) << 16);
            ul.y = (uint32_t)__bfloat16_as_ushort(l2) | ((uint32_t)__bfloat16_as_ushort(l3) << 16);
            uint32_t o = (uint32_t)(la_r[j] * (PITCH * 2) + la_c[j] * 2);
            asm volatile("st.shared.v2.b32 [%0], {%1,%2};" :: "r"(hi_b + o), "r"(uh.x), "r"(uh.y));
            asm volatile("st.shared.v2.b32 [%0], {%1,%2};" :: "r"(lo_b + o), "r"(ul.x), "r"(ul.y));
        }
    };

    ldgA(0);
    loadB_async(0, 0);
    CP_COMMIT();
    convA_sts(0);
    CP_WAIT0();
    __syncthreads();

    for (int ch = 0; ch < nch; ch++) {
        int cur = ch & 1, nxt = cur ^ 1;
        bool more = (ch + 1 < nch);
        if (more) {
            ldgA(ch + 1);
            loadB_async(nxt, ch + 1);
            CP_COMMIT();
        }
        uint32_t sAhi = base + (uint32_t)((cur * 4 + 0) * TILE_B);
        uint32_t sAlo = base + (uint32_t)((cur * 4 + 1) * TILE_B);
        uint32_t sBhi = base + (uint32_t)((cur * 4 + 2) * TILE_B);
        uint32_t sBlo = base + (uint32_t)((cur * 4 + 3) * TILE_B);
        #pragma unroll
        for (int ks = 0; ks < 2; ks++) {
            int kb = ks * 32;
            uint32_t ah[2][4], al[2][4];
            #pragma unroll
            for (int mt = 0; mt < 2; mt++) {
                uint32_t ro = (uint32_t)((wm + mt * 16 + a_r) * (PITCH * 2) + kb + a_cb);
                ldm_x4(ah[mt][0], ah[mt][1], ah[mt][2], ah[mt][3], sAhi + ro);
                ldm_x4(al[mt][0], al[mt][1], al[mt][2], al[mt][3], sAlo + ro);
            }
            #pragma unroll
            for (int nt = 0; nt < 4; nt++) {
                uint32_t ro = (uint32_t)((wn + nt * 16 + b_r) * (PITCH * 2) + kb + b_cb);
                uint32_t bh[4], bl[4];
                ldm_x4(bh[0], bh[1], bh[2], bh[3], sBhi + ro);
                ldm_x4(bl[0], bl[1], bl[2], bl[3], sBlo + ro);
                #pragma unroll
                for (int mt = 0; mt < 2; mt++) {
                    mma_bf16(acc[mt][nt * 2 + 0], ah[mt], bh[0], bh[1]);
                    mma_bf16(acc[mt][nt * 2 + 1], ah[mt], bh[2], bh[3]);
                    mma_bf16(acc[mt][nt * 2 + 0], ah[mt], bl[0], bl[1]);
                    mma_bf16(acc[mt][nt * 2 + 1], ah[mt], bl[2], bl[3]);
                    mma_bf16(acc[mt][nt * 2 + 0], al[mt], bh[0], bh[1]);
                    mma_bf16(acc[mt][nt * 2 + 1], al[mt], bh[2], bh[3]);
                }
            }
        }
        if (more) {
            convA_sts(nxt);
            CP_WAIT0();
        }
        __syncthreads();
    }

    // ---- epilogue: write fp16 C + fused attention scores ----
    int er = lane >> 2, ec = (lane & 3) * 2;
    float ps0[2] = {0.f, 0.f}, ps1[2] = {0.f, 0.f};
    float pd0[2] = {0.f, 0.f}, pd1[2] = {0.f, 0.f};
    #pragma unroll
    for (int mt = 0; mt < 2; mt++) {
        int r0 = brow + wm + mt * 16 + er;
        #pragma unroll
        for (int nt = 0; nt < 8; nt++) {
            int gc = bcol + wn + nt * 8 + ec;
            float a0 = Asrc[gc], a1 = Asrc[gc + 1];
            float b0 = Adst[gc], b1 = Adst[gc + 1];
            ps0[mt] += acc[mt][nt][0] * a0 + acc[mt][nt][1] * a1;
            pd0[mt] += acc[mt][nt][0] * b0 + acc[mt][nt][1] * b1;
            ps1[mt] += acc[mt][nt][2] * a0 + acc[mt][nt][3] * a1;
            pd1[mt] += acc[mt][nt][2] * b0 + acc[mt][nt][3] * b1;
            int col = gc;
            if (r0 < M)
                *(__half2*)&C[(size_t)r0 * N + col] =
                    __floats2half2_rn(acc[mt][nt][0], acc[mt][nt][1]);
            if (r0 + 8 < M)
                *(__half2*)&C[(size_t)(r0 + 8) * N + col] =
                    __floats2half2_rn(acc[mt][nt][2], acc[mt][nt][3]);
        }
    }
    // reduce score partials over the 4 lanes sharing a row (lane&3)
    #pragma unroll
    for (int o = 1; o <= 2; o <<= 1) {
        #pragma unroll
        for (int mt = 0; mt < 2; mt++) {
            ps0[mt] += __shfl_xor_sync(0xffffffffu, ps0[mt], o);
            ps1[mt] += __shfl_xor_sync(0xffffffffu, ps1[mt], o);
            pd0[mt] += __shfl_xor_sync(0xffffffffu, pd0[mt], o);
            pd1[mt] += __shfl_xor_sync(0xffffffffu, pd1[mt], o);
        }
    }
    if ((lane & 3) == 0) {
        int Hloc = N / Chead;
        int head = (bcol + wn) / Chead;
        #pragma unroll
        for (int mt = 0; mt < 2; mt++) {
            int r0 = brow + wm + mt * 16 + er;
            if (Chead == 64) {       // warp owns the complete head: direct store
                if (r0 < M)     { sArr[r0 * Hloc + head] = ps0[mt]; dArr[r0 * Hloc + head] = pd0[mt]; }
                if (r0 + 8 < M) { sArr[(r0 + 8) * Hloc + head] = ps1[mt]; dArr[(r0 + 8) * Hloc + head] = pd1[mt]; }
            } else {                 // head spans both warps: atomic into zeroed arrays
                if (r0 < M)     { atomicAdd(&sArr[r0], ps0[mt]); atomicAdd(&dArr[r0], pd0[mt]); }
                if (r0 + 8 < M) { atomicAdd(&sArr[r0 + 8], ps1[mt]); atomicAdd(&dArr[r0 + 8], pd1[mt]); }
            }
        }
    }
}

// ---------------- CSR build ----------------
__device__ __forceinline__ void edge_endpoints(const int* __restrict__ ei, int e,
                                               int& src, int& dst) {
    if (e < E_RAW) { src = ei[e]; dst = ei[E_RAW + e]; }
    else           { src = dst = e - E_RAW; }
}
__global__ void csr_zero_kernel(int* __restrict__ deg, int* __restrict__ cur) {
    int i = blockIdx.x * blockDim.x + threadIdx.x;
    if (i < N_NODES) { deg[i] = 0; cur[i] = 0; }
}
__global__ void csr_count_kernel(const int* __restrict__ ei, int* __restrict__ deg) {
    int e = blockIdx.x * blockDim.x + threadIdx.x;
    if (e >= E_TOT) return;
    int dst = (e < E_RAW) ? ei[E_RAW + e] : e - E_RAW;
    atomicAdd(&deg[dst], 1);
}
__global__ void scan1_kernel(const int* __restrict__ deg, int* __restrict__ off,
                             int* __restrict__ bsum, int n) {
    __shared__ int sm[SCAN_B];
    int i = blockIdx.x * SCAN_B + threadIdx.x;
    int v = (i < n) ? deg[i] : 0;
    sm[threadIdx.x] = v;
    __syncthreads();
    for (int o = 1; o < SCAN_B; o <<= 1) {
        int t = (threadIdx.x >= o) ? sm[threadIdx.x - o] : 0;
        __syncthreads();
        sm[threadIdx.x] += t;
        __syncthreads();
    }
    if (i < n) off[i + 1] = sm[threadIdx.x];
    if (threadIdx.x == SCAN_B - 1) bsum[blockIdx.x] = sm[threadIdx.x];
}
__global__ void scan2_kernel(int* __restrict__ bsum, int nb) {
    if (threadIdx.x == 0) {
        int run = 0;
        for (int b = 0; b < nb; b++) { int t = bsum[b]; bsum[b] = run; run += t; }
    }
}
__global__ void scan3_kernel(int* __restrict__ off, const int* __restrict__ bsum, int n) {
    int i = blockIdx.x * blockDim.x + threadIdx.x;
    if (i == 0) off[0] = 0;
    if (i < n) off[i + 1] += bsum[i / SCAN_B];
}
__global__ void csr_scatter_kernel(const int* __restrict__ ei, const int* __restrict__ off,
                                   int* __restrict__ cur, int* __restrict__ srcs) {
    int e = blockIdx.x * blockDim.x + threadIdx.x;
    if (e >= E_TOT) return;
    int src, dst;
    edge_endpoints(ei, e, src, dst);
    int pos = atomicAdd(&cur[dst], 1);
    srcs[off[dst] + pos] = src;
}

// ---------------- fused aggregate: inline softmax, warp per dst node ----------------
// out[n,:] = (Σ_e exp(leaky(s[src_e]+d[n]))·xp[src_e]) / Σ_e p + bias  (+ELU)
template <int H, int C, bool ELU>
__global__ void agg_soft_kernel(const int* __restrict__ off,
                                const int* __restrict__ srcs,
                                const __half* __restrict__ xp,
                                const float* __restrict__ sArr,
                                const float* __restrict__ dArr,
                                const float* __restrict__ bias,
                                float* __restrict__ out) {
    constexpr int HC = H * C;
    constexpr int PER = HC / 32;    // 8 (H=4,C=64) or 4 (H=1,C=128)
    int gw = (blockIdx.x * blockDim.x + threadIdx.x) >> 5;
    int lane = threadIdx.x & 31;
    if (gw >= N_NODES) return;
    int base = lane * PER;
    int head = (H == 1) ? 0 : (lane >> 3);           // 8 lanes per head when H=4
    float d4 = (lane < H) ? dArr[gw * H + lane] : 0.f;
    int s0 = off[gw], s1 = off[gw + 1];
    float acc[PER];
    #pragma unroll
    for (int j = 0; j < PER; j++) acc[j] = 0.f;
    float z = 0.f;

    auto edge_p = [&](int src) {
        float sv = (lane < H) ? sArr[src * H + lane] : 0.f;
        float v = sv + d4;
        v = v > 0.f ? v : 0.2f * v;
        float p = __expf(fminf(v, 80.f));
        return __shfl_sync(0xffffffffu, p, head);
    };
    auto accum = [&](int src, float pw) {
        if (PER == 8) {
            uint4 u = *(const uint4*)(xp + (size_t)src * HC + base);
            float2 f0 = __half22float2(*(__half2*)&u.x);
            float2 f1 = __half22float2(*(__half2*)&u.y);
            float2 f2 = __half22float2(*(__half2*)&u.z);
            float2 f3 = __half22float2(*(__half2*)&u.w);
            acc[0] = fmaf(f0.x, pw, acc[0]); acc[1] = fmaf(f0.y, pw, acc[1]);
            acc[2] = fmaf(f1.x, pw, acc[2]); acc[3] = fmaf(f1.y, pw, acc[3]);
            acc[4] = fmaf(f2.x, pw, acc[4]); acc[5] = fmaf(f2.y, pw, acc[5]);
            acc[6] = fmaf(f3.x, pw, acc[6]); acc[7] = fmaf(f3.y, pw, acc[7]);
        } else {
            uint2 u = *(const uint2*)(xp + (size_t)src * HC + base);
            float2 f0 = __half22float2(*(__half2*)&u.x);
            float2 f1 = __half22float2(*(__half2*)&u.y);
            acc[0] = fmaf(f0.x, pw, acc[0]); acc[1] = fmaf(f0.y, pw, acc[1]);
            acc[PER > 2 ? 2 : 0] = fmaf(f1.x, pw, acc[PER > 2 ? 2 : 0]);
            acc[PER > 3 ? 3 : 0] = fmaf(f1.y, pw, acc[PER > 3 ? 3 : 0]);
        }
    };

    int t = s0;
    for (; t + 1 < s1; t += 2) {
        int srcA = srcs[t], srcB = srcs[t + 1];
        float pwA = edge_p(srcA);
        float pwB = edge_p(srcB);
        z += pwA + pwB;
        accum(srcA, pwA);
        accum(srcB, pwB);
    }
    if (t < s1) {
        int src = srcs[t];
        float pw = edge_p(src);
        z += pw;
        accum(src, pw);
    }

    float inv = 1.f / (z + 1e-16f);
    float* od = out + (size_t)gw * HC + base;
    #pragma unroll
    for (int q = 0; q < PER / 4; q++) {
        float4 r;
        r.x = acc[q * 4 + 0] * inv + bias[base + q * 4 + 0];
        r.y = acc[q * 4 + 1] * inv + bias[base + q * 4 + 1];
        r.z = acc[q * 4 + 2] * inv + bias[base + q * 4 + 2];
        r.w = acc[q * 4 + 3] * inv + bias[base + q * 4 + 3];
        if (ELU) {
            r.x = r.x > 0.f ? r.x : expm1f(r.x);
            r.y = r.y > 0.f ? r.y : expm1f(r.y);
            r.z = r.z > 0.f ? r.z : expm1f(r.z);
            r.w = r.w > 0.f ? r.w : expm1f(r.w);
        }
        *(float4*)&od[q * 4] = r;
    }
}

// ---------------- host orchestration ----------------
struct Bufs {
    __half *xph;
    float *h, *s, *d;
    __nv_bfloat16 *whi, *wlo;
    int *deg, *cur, *off, *bsum, *srcs;
};

static void prep_weights(const float* W, int K, int HCl, const Bufs& b) {
    dim3 tg(HCl / 32, K / 32);
    transpose_convert_kernel<<<tg, dim3(32, 8)>>>(W, b.whi, b.wlo, K, HCl);
}

static void launch_gemm(const float* in, int K, int HCl, int Chead,
                        const float* a_src, const float* a_dst, const Bufs& b) {
    dim3 grid(HCl / 128, (N_NODES + 127) / 128);
    gemm_mma_kernel<<<grid, 256, GEMM_SMEM>>>(in, b.whi, b.wlo, b.xph,
                                              a_src, a_dst, b.s, b.d,
                                              N_NODES, HCl, K, Chead);
}

extern "C" void kernel_launch(void* const* d_in, const int* in_sizes, int n_in,
                              void* d_out, int out_size) {
    const float* x      = (const float*)d_in[0];
    const int*   ei     = (const int*)  d_in[1];
    const float* W0     = (const float*)d_in[2];
    const float* a_src0 = (const float*)d_in[3];
    const float* a_dst0 = (const float*)d_in[4];
    const float* b0     = (const float*)d_in[5];
    const float* W1     = (const float*)d_in[6];
    const float* a_src1 = (const float*)d_in[7];
    const float* a_dst1 = (const float*)d_in[8];
    const float* b1     = (const float*)d_in[9];
    const float* W2     = (const float*)d_in[10];
    const float* a_src2 = (const float*)d_in[11];
    const float* a_dst2 = (const float*)d_in[12];
    const float* b2     = (const float*)d_in[13];

    Bufs b;
    cudaGetSymbolAddress((void**)&b.xph,  g_xph);
    cudaGetSymbolAddress((void**)&b.h,    g_h);
    cudaGetSymbolAddress((void**)&b.whi,  g_whi);
    cudaGetSymbolAddress((void**)&b.wlo,  g_wlo);
    cudaGetSymbolAddress((void**)&b.s,    g_s);
    cudaGetSymbolAddress((void**)&b.d,    g_d);
    cudaGetSymbolAddress((void**)&b.deg,  g_deg);
    cudaGetSymbolAddress((void**)&b.cur,  g_cur);
    cudaGetSymbolAddress((void**)&b.off,  g_off);
    cudaGetSymbolAddress((void**)&b.bsum, g_bsum);
    cudaGetSymbolAddress((void**)&b.srcs, g_srcs);

    cudaFuncSetAttribute(gemm_mma_kernel, cudaFuncAttributeMaxDynamicSharedMemorySize,
                         GEMM_SMEM);

    const int nwarp_grid = (int)(((size_t)N_NODES * 32 + 255) / 256);

    // Launch order keeps gemm_mma at slot 4 for ncu.
    prep_weights(W0, 128, 256, b);                                     // 1
    csr_zero_kernel<<<(N_NODES + 255) / 256, 256>>>(b.deg, b.cur);     // 2
    csr_count_kernel<<<(E_TOT + 255) / 256, 256>>>(ei, b.deg);         // 3
    launch_gemm(x, 128, 256, 64, a_src0, a_dst0, b);                   // 4 (profiled)
    int nblk = (N_NODES + SCAN_B - 1) / SCAN_B;
    scan1_kernel<<<nblk, SCAN_B>>>(b.deg, b.off, b.bsum, N_NODES);     // 5
    scan2_kernel<<<1, 32>>>(b.bsum, nblk);                             // 6
    scan3_kernel<<<(N_NODES + 255) / 256, 256>>>(b.off, b.bsum, N_NODES);        // 7
    csr_scatter_kernel<<<(E_TOT + 255) / 256, 256>>>(ei, b.off, b.cur, b.srcs);  // 8

    // layer 0 aggregate (gemm done above)
    agg_soft_kernel<4, 64, true><<<nwarp_grid, 256>>>(b.off, b.srcs, b.xph,
                                                      b.s, b.d, b0, b.h);
    // layer 1
    prep_weights(W1, 256, 256, b);
    launch_gemm(b.h, 256, 256, 64, a_src1, a_dst1, b);
    agg_soft_kernel<4, 64, true><<<nwarp_grid, 256>>>(b.off, b.srcs, b.xph,
                                                      b.s, b.d, b1, b.h);
    // layer 2 (H=1, C=128 -> atomic score path needs zeroed s/d)
    prep_weights(W2, 256, 128, b);
    init_sd_kernel<<<(N_NODES + 255) / 256, 256>>>(b.s, b.d, N_NODES);
    launch_gemm(b.h, 256, 128, 128, a_src2, a_dst2, b);
    agg_soft_kernel<1, 128, false><<<nwarp_grid, 256>>>(b.off, b.srcs, b.xph,
                                                        b.s, b.d, b2, (float*)d_out);
}

// round 8
// speedup vs baseline: 9.3254x; 1.2067x over previous
#include <cuda_runtime.h>
#include <cuda_fp16.h>
#include <cstdint>

#define N_NODES 50000
#define E_RAW   800000
#define E_TOT   (E_RAW + N_NODES)   // 850000 with self loops
#define MAXH    4
#define MAXHC   256
#define SCAN_B  1024

// ---------------- device scratch (static, allocation-free) ----------------
__device__ __half g_xph[(size_t)N_NODES * MAXHC];   // transformed features, fp16
__device__ float g_h [(size_t)N_NODES * MAXHC];     // layer output (fp32)
__device__ __half g_wh[MAXHC * MAXHC];              // W^T [N,K] fp16
__device__ float g_s [(size_t)N_NODES * MAXH];
__device__ float g_d [(size_t)N_NODES * MAXH];
// CSR by destination
__device__ int g_deg [N_NODES];
__device__ int g_cur [N_NODES];
__device__ int g_off [N_NODES + 1];
__device__ int g_bsum[64];
__device__ int g_srcs[E_TOT];

// ---------------- small PTX helpers ----------------
__device__ __forceinline__ uint32_t smem_u32(const void* p) {
    uint32_t a;
    asm("{ .reg .u64 t; cvta.to.shared.u64 t, %1; cvt.u32.u64 %0, t; }" : "=r"(a) : "l"(p));
    return a;
}
__device__ __forceinline__ void ldm_x4(uint32_t& r0, uint32_t& r1, uint32_t& r2, uint32_t& r3,
                                       uint32_t addr) {
    asm volatile("ldmatrix.sync.aligned.m8n8.x4.shared.b16 {%0,%1,%2,%3}, [%4];"
                 : "=r"(r0), "=r"(r1), "=r"(r2), "=r"(r3) : "r"(addr));
}
__device__ __forceinline__ void mma_f16(float* d, const uint32_t* a, uint32_t b0, uint32_t b1) {
    asm volatile(
        "mma.sync.aligned.m16n8k16.row.col.f32.f16.f16.f32 "
        "{%0,%1,%2,%3}, {%4,%5,%6,%7}, {%8,%9}, {%0,%1,%2,%3};"
        : "+f"(d[0]), "+f"(d[1]), "+f"(d[2]), "+f"(d[3])
        : "r"(a[0]), "r"(a[1]), "r"(a[2]), "r"(a[3]), "r"(b0), "r"(b1));
}
__device__ __forceinline__ void cp_async16(uint32_t dst, const void* src) {
    asm volatile("cp.async.ca.shared.global [%0], [%1], 16;" :: "r"(dst), "l"(src));
}
#define CP_COMMIT() asm volatile("cp.async.commit_group;")
#define CP_WAIT0()  asm volatile("cp.async.wait_group 0;" ::: "memory")

// ---------------- weight transpose + fp16 convert: Wt[n,k] = W[k,n] ----------------
__global__ void transpose_convert_kernel(const float* __restrict__ W,
                                         __half* __restrict__ Wh,
                                         int K, int N) {
    __shared__ float t[32][33];
    int bn = blockIdx.x * 32, bk = blockIdx.y * 32;
    int x = threadIdx.x, y = threadIdx.y;
    #pragma unroll
    for (int j = 0; j < 32; j += 8) t[y + j][x] = W[(size_t)(bk + y + j) * N + bn + x];
    __syncthreads();
    #pragma unroll
    for (int j = 0; j < 32; j += 8)
        Wh[(size_t)(bn + y + j) * K + bk + x] = __float2half_rn(t[x][y + j]);
}

// ---------------- zero s/d (only needed for the atomic path, C=128) ----------------
__global__ void init_sd_kernel(float* __restrict__ s, float* __restrict__ d, int n) {
    int i = blockIdx.x * blockDim.x + threadIdx.x;
    if (i < n) { s[i] = 0.f; d[i] = 0.f; }
}

// ---------------- fp16 tensor GEMM via mma.sync, double-buffered ----------------
// C[M,N](fp16) = A[M,K](fp32->fp16) @ Bt[N,K]^T (fp16).
// Fused epilogue emits attention scores s[n,h], d[n,h].
// Block tile 128x128, K-chunk 32. 8 warps (4Mx2N), warp tile 32x64.
#define PITCH    40                   // fp16 per smem row (32 + 8 pad) = 80 bytes
#define TILE_B   (128 * PITCH * 2)    // 10240 bytes per matrix tile
#define GEMM_SMEM (4 * TILE_B)        // 2 stages x (A, B)

__global__ __launch_bounds__(256, 2) void gemm_mma_kernel(const float* __restrict__ A,
                                                          const __half* __restrict__ Bt,
                                                          __half* __restrict__ C,
                                                          const float* __restrict__ Asrc,
                                                          const float* __restrict__ Adst,
                                                          float* __restrict__ sArr,
                                                          float* __restrict__ dArr,
                                                          int M, int N, int K, int Chead) {
    extern __shared__ __align__(16) char sm[];
    uint32_t base = smem_u32(sm);

    int tid = threadIdx.x, lane = tid & 31, wid = tid >> 5;
    int wm = (wid >> 1) * 32;
    int wn = (wid & 1) * 64;
    int brow = blockIdx.y * 128;
    int bcol = blockIdx.x * 128;
    int valid = M - brow; if (valid > 128) valid = 128;

    float acc[2][8][4];
    #pragma unroll
    for (int i = 0; i < 2; i++)
        #pragma unroll
        for (int j = 0; j < 8; j++)
            #pragma unroll
            for (int q = 0; q < 4; q++) acc[i][j][q] = 0.f;

    int la_r[4], la_c[4];
    #pragma unroll
    for (int j = 0; j < 4; j++) {
        int i = tid + j * 256;
        la_r[j] = i >> 3;
        la_c[j] = (i & 7) << 2;
    }
    int a_r = ((lane >> 3) & 1) * 8 + (lane & 7);
    int a_cb = (lane >> 4) * 16;
    int b_r = (lane >> 4) * 8 + (lane & 7);
    int b_cb = ((lane >> 3) & 1) * 16;

    float4 av[4];
    int nch = K >> 5;

    auto ldgA = [&](int ch) {
        int k0 = ch << 5;
        #pragma unroll
        for (int j = 0; j < 4; j++) {
            if (la_r[j] < valid)
                av[j] = *(const float4*)&A[(size_t)(brow + la_r[j]) * K + k0 + la_c[j]];
            else
                av[j] = make_float4(0.f, 0.f, 0.f, 0.f);
        }
    };
    // B tile: 128 rows x 32 halves (64B) = 512 x 16B segs / 2 per thread
    auto loadB_async = [&](int stage, int ch) {
        int k0 = ch << 5;
        #pragma unroll
        for (int j = 0; j < 2; j++) {
            int i = tid + j * 256;
            int seg = i & 3, row = i >> 2;
            const __half* src = Bt + (size_t)(bcol + row) * K + k0 + seg * 8;
            uint32_t dst = base + (uint32_t)((stage * 2 + 1) * TILE_B)
                         + (uint32_t)(row * (PITCH * 2) + seg * 16);
            cp_async16(dst, src);
        }
    };
    auto convA_sts = [&](int stage) {
        uint32_t a_b = base + (uint32_t)((stage * 2 + 0) * TILE_B);
        #pragma unroll
        for (int j = 0; j < 4; j++) {
            float4 v = av[j];
            __half2 p0 = __floats2half2_rn(v.x, v.y);
            __half2 p1 = __floats2half2_rn(v.z, v.w);
            uint32_t u0 = *(uint32_t*)&p0, u1 = *(uint32_t*)&p1;
            uint32_t o = (uint32_t)(la_r[j] * (PITCH * 2) + la_c[j] * 2);
            asm volatile("st.shared.v2.b32 [%0], {%1,%2};" :: "r"(a_b + o), "r"(u0), "r"(u1));
        }
    };

    ldgA(0);
    loadB_async(0, 0);
    CP_COMMIT();
    convA_sts(0);
    CP_WAIT0();
    __syncthreads();

    for (int ch = 0; ch < nch; ch++) {
        int cur = ch & 1, nxt = cur ^ 1;
        bool more = (ch + 1 < nch);
        if (more) {
            ldgA(ch + 1);
            loadB_async(nxt, ch + 1);
            CP_COMMIT();
        }
        uint32_t sA = base + (uint32_t)((cur * 2 + 0) * TILE_B);
        uint32_t sB = base + (uint32_t)((cur * 2 + 1) * TILE_B);
        #pragma unroll
        for (int ks = 0; ks < 2; ks++) {
            int kb = ks * 32;
            uint32_t ah[2][4];
            #pragma unroll
            for (int mt = 0; mt < 2; mt++) {
                uint32_t ro = (uint32_t)((wm + mt * 16 + a_r) * (PITCH * 2) + kb + a_cb);
                ldm_x4(ah[mt][0], ah[mt][1], ah[mt][2], ah[mt][3], sA + ro);
            }
            #pragma unroll
            for (int nt = 0; nt < 4; nt++) {
                uint32_t ro = (uint32_t)((wn + nt * 16 + b_r) * (PITCH * 2) + kb + b_cb);
                uint32_t bh[4];
                ldm_x4(bh[0], bh[1], bh[2], bh[3], sB + ro);
                #pragma unroll
                for (int mt = 0; mt < 2; mt++) {
                    mma_f16(acc[mt][nt * 2 + 0], ah[mt], bh[0], bh[1]);
                    mma_f16(acc[mt][nt * 2 + 1], ah[mt], bh[2], bh[3]);
                }
            }
        }
        if (more) {
            convA_sts(nxt);
            CP_WAIT0();
        }
        __syncthreads();
    }

    // ---- epilogue: write fp16 C + fused attention scores ----
    int er = lane >> 2, ec = (lane & 3) * 2;
    float ps0[2] = {0.f, 0.f}, ps1[2] = {0.f, 0.f};
    float pd0[2] = {0.f, 0.f}, pd1[2] = {0.f, 0.f};
    #pragma unroll
    for (int mt = 0; mt < 2; mt++) {
        int r0 = brow + wm + mt * 16 + er;
        #pragma unroll
        for (int nt = 0; nt < 8; nt++) {
            int gc = bcol + wn + nt * 8 + ec;
            float a0 = Asrc[gc], a1 = Asrc[gc + 1];
            float b0 = Adst[gc], b1 = Adst[gc + 1];
            ps0[mt] += acc[mt][nt][0] * a0 + acc[mt][nt][1] * a1;
            pd0[mt] += acc[mt][nt][0] * b0 + acc[mt][nt][1] * b1;
            ps1[mt] += acc[mt][nt][2] * a0 + acc[mt][nt][3] * a1;
            pd1[mt] += acc[mt][nt][2] * b0 + acc[mt][nt][3] * b1;
            if (r0 < M)
                *(__half2*)&C[(size_t)r0 * N + gc] =
                    __floats2half2_rn(acc[mt][nt][0], acc[mt][nt][1]);
            if (r0 + 8 < M)
                *(__half2*)&C[(size_t)(r0 + 8) * N + gc] =
                    __floats2half2_rn(acc[mt][nt][2], acc[mt][nt][3]);
        }
    }
    #pragma unroll
    for (int o = 1; o <= 2; o <<= 1) {
        #pragma unroll
        for (int mt = 0; mt < 2; mt++) {
            ps0[mt] += __shfl_xor_sync(0xffffffffu, ps0[mt], o);
            ps1[mt] += __shfl_xor_sync(0xffffffffu, ps1[mt], o);
            pd0[mt] += __shfl_xor_sync(0xffffffffu, pd0[mt], o);
            pd1[mt] += __shfl_xor_sync(0xffffffffu, pd1[mt], o);
        }
    }
    if ((lane & 3) == 0) {
        int Hloc = N / Chead;
        int head = (bcol + wn) / Chead;
        #pragma unroll
        for (int mt = 0; mt < 2; mt++) {
            int r0 = brow + wm + mt * 16 + er;
            if (Chead == 64) {
                if (r0 < M)     { sArr[r0 * Hloc + head] = ps0[mt]; dArr[r0 * Hloc + head] = pd0[mt]; }
                if (r0 + 8 < M) { sArr[(r0 + 8) * Hloc + head] = ps1[mt]; dArr[(r0 + 8) * Hloc + head] = pd1[mt]; }
            } else {
                if (r0 < M)     { atomicAdd(&sArr[r0], ps0[mt]); atomicAdd(&dArr[r0], pd0[mt]); }
                if (r0 + 8 < M) { atomicAdd(&sArr[r0 + 8], ps1[mt]); atomicAdd(&dArr[r0 + 8], pd1[mt]); }
            }
        }
    }
}

// ---------------- CSR build ----------------
__device__ __forceinline__ void edge_endpoints(const int* __restrict__ ei, int e,
                                               int& src, int& dst) {
    if (e < E_RAW) { src = ei[e]; dst = ei[E_RAW + e]; }
    else           { src = dst = e - E_RAW; }
}
__global__ void csr_zero_kernel(int* __restrict__ deg, int* __restrict__ cur) {
    int i = blockIdx.x * blockDim.x + threadIdx.x;
    if (i < N_NODES) { deg[i] = 0; cur[i] = 0; }
}
__global__ void csr_count_kernel(const int* __restrict__ ei, int* __restrict__ deg) {
    int e = blockIdx.x * blockDim.x + threadIdx.x;
    if (e >= E_TOT) return;
    int dst = (e < E_RAW) ? ei[E_RAW + e] : e - E_RAW;
    atomicAdd(&deg[dst], 1);
}
__global__ void scan1_kernel(const int* __restrict__ deg, int* __restrict__ off,
                             int* __restrict__ bsum, int n) {
    __shared__ int sm[SCAN_B];
    int i = blockIdx.x * SCAN_B + threadIdx.x;
    int v = (i < n) ? deg[i] : 0;
    sm[threadIdx.x] = v;
    __syncthreads();
    for (int o = 1; o < SCAN_B; o <<= 1) {
        int t = (threadIdx.x >= o) ? sm[threadIdx.x - o] : 0;
        __syncthreads();
        sm[threadIdx.x] += t;
        __syncthreads();
    }
    if (i < n) off[i + 1] = sm[threadIdx.x];
    if (threadIdx.x == SCAN_B - 1) bsum[blockIdx.x] = sm[threadIdx.x];
}
__global__ void scan2_kernel(int* __restrict__ bsum, int nb) {
    if (threadIdx.x == 0) {
        int run = 0;
        for (int b = 0; b < nb; b++) { int t = bsum[b]; bsum[b] = run; run += t; }
    }
}
__global__ void scan3_kernel(int* __restrict__ off, const int* __restrict__ bsum, int n) {
    int i = blockIdx.x * blockDim.x + threadIdx.x;
    if (i == 0) off[0] = 0;
    if (i < n) off[i + 1] += bsum[i / SCAN_B];
}
__global__ void csr_scatter_kernel(const int* __restrict__ ei, const int* __restrict__ off,
                                   int* __restrict__ cur, int* __restrict__ srcs) {
    int e = blockIdx.x * blockDim.x + threadIdx.x;
    if (e >= E_TOT) return;
    int src, dst;
    edge_endpoints(ei, e, src, dst);
    int pos = atomicAdd(&cur[dst], 1);
    srcs[off[dst] + pos] = src;
}

// ---------------- fused aggregate: inline softmax, warp per dst node ----------------
template <int H, int C, bool ELU>
__global__ void agg_soft_kernel(const int* __restrict__ off,
                                const int* __restrict__ srcs,
                                const __half* __restrict__ xp,
                                const float* __restrict__ sArr,
                                const float* __restrict__ dArr,
                                const float* __restrict__ bias,
                                float* __restrict__ out) {
    constexpr int HC = H * C;
    constexpr int PER = HC / 32;
    int gw = (blockIdx.x * blockDim.x + threadIdx.x) >> 5;
    int lane = threadIdx.x & 31;
    if (gw >= N_NODES) return;
    int base = lane * PER;
    int head = (H == 1) ? 0 : (lane >> 3);
    float d4 = (lane < H) ? dArr[gw * H + lane] : 0.f;
    int s0 = off[gw], s1 = off[gw + 1];
    float acc[PER];
    #pragma unroll
    for (int j = 0; j < PER; j++) acc[j] = 0.f;
    float z = 0.f;

    auto edge_p = [&](int src) {
        float sv = (lane < H) ? sArr[src * H + lane] : 0.f;
        float v = sv + d4;
        v = v > 0.f ? v : 0.2f * v;
        float p = __expf(fminf(v, 80.f));
        return __shfl_sync(0xffffffffu, p, head);
    };
    auto accum = [&](int src, float pw) {
        if (PER == 8) {
            uint4 u = *(const uint4*)(xp + (size_t)src * HC + base);
            float2 f0 = __half22float2(*(__half2*)&u.x);
            float2 f1 = __half22float2(*(__half2*)&u.y);
            float2 f2 = __half22float2(*(__half2*)&u.z);
            float2 f3 = __half22float2(*(__half2*)&u.w);
            acc[0] = fmaf(f0.x, pw, acc[0]); acc[1] = fmaf(f0.y, pw, acc[1]);
            acc[2] = fmaf(f1.x, pw, acc[2]); acc[3] = fmaf(f1.y, pw, acc[3]);
            acc[4] = fmaf(f2.x, pw, acc[4]); acc[5] = fmaf(f2.y, pw, acc[5]);
            acc[6] = fmaf(f3.x, pw, acc[6]); acc[7] = fmaf(f3.y, pw, acc[7]);
        } else {
            uint2 u = *(const uint2*)(xp + (size_t)src * HC + base);
            float2 f0 = __half22float2(*(__half2*)&u.x);
            float2 f1 = __half22float2(*(__half2*)&u.y);
            acc[0] = fmaf(f0.x, pw, acc[0]); acc[1] = fmaf(f0.y, pw, acc[1]);
            acc[PER > 2 ? 2 : 0] = fmaf(f1.x, pw, acc[PER > 2 ? 2 : 0]);
            acc[PER > 3 ? 3 : 0] = fmaf(f1.y, pw, acc[PER > 3 ? 3 : 0]);
        }
    };

    int t = s0;
    for (; t + 1 < s1; t += 2) {
        int srcA = srcs[t], srcB = srcs[t + 1];
        float pwA = edge_p(srcA);
        float pwB = edge_p(srcB);
        z += pwA + pwB;
        accum(srcA, pwA);
        accum(srcB, pwB);
    }
    if (t < s1) {
        int src = srcs[t];
        float pw = edge_p(src);
        z += pw;
        accum(src, pw);
    }

    float inv = 1.f / (z + 1e-16f);
    float* od = out + (size_t)gw * HC + base;
    #pragma unroll
    for (int q = 0; q < PER / 4; q++) {
        float4 r;
        r.x = acc[q * 4 + 0] * inv + bias[base + q * 4 + 0];
        r.y = acc[q * 4 + 1] * inv + bias[base + q * 4 + 1];
        r.z = acc[q * 4 + 2] * inv + bias[base + q * 4 + 2];
        r.w = acc[q * 4 + 3] * inv + bias[base + q * 4 + 3];
        if (ELU) {
            r.x = r.x > 0.f ? r.x : expm1f(r.x);
            r.y = r.y > 0.f ? r.y : expm1f(r.y);
            r.z = r.z > 0.f ? r.z : expm1f(r.z);
            r.w = r.w > 0.f ? r.w : expm1f(r.w);
        }
        *(float4*)&od[q * 4] = r;
    }
}

// ---------------- host orchestration ----------------
struct Bufs {
    __half *xph, *wh;
    float *h, *s, *d;
    int *deg, *cur, *off, *bsum, *srcs;
};

static void prep_weights(const float* W, int K, int HCl, const Bufs& b) {
    dim3 tg(HCl / 32, K / 32);
    transpose_convert_kernel<<<tg, dim3(32, 8)>>>(W, b.wh, K, HCl);
}

static void launch_gemm(const float* in, int K, int HCl, int Chead,
                        const float* a_src, const float* a_dst, const Bufs& b) {
    dim3 grid(HCl / 128, (N_NODES + 127) / 128);
    gemm_mma_kernel<<<grid, 256, GEMM_SMEM>>>(in, b.wh, b.xph,
                                              a_src, a_dst, b.s, b.d,
                                              N_NODES, HCl, K, Chead);
}

extern "C" void kernel_launch(void* const* d_in, const int* in_sizes, int n_in,
                              void* d_out, int out_size) {
    const float* x      = (const float*)d_in[0];
    const int*   ei     = (const int*)  d_in[1];
    const float* W0     = (const float*)d_in[2];
    const float* a_src0 = (const float*)d_in[3];
    const float* a_dst0 = (const float*)d_in[4];
    const float* b0     = (const float*)d_in[5];
    const float* W1     = (const float*)d_in[6];
    const float* a_src1 = (const float*)d_in[7];
    const float* a_dst1 = (const float*)d_in[8];
    const float* b1     = (const float*)d_in[9];
    const float* W2     = (const float*)d_in[10];
    const float* a_src2 = (const float*)d_in[11];
    const float* a_dst2 = (const float*)d_in[12];
    const float* b2     = (const float*)d_in[13];

    Bufs b;
    cudaGetSymbolAddress((void**)&b.xph,  g_xph);
    cudaGetSymbolAddress((void**)&b.wh,   g_wh);
    cudaGetSymbolAddress((void**)&b.h,    g_h);
    cudaGetSymbolAddress((void**)&b.s,    g_s);
    cudaGetSymbolAddress((void**)&b.d,    g_d);
    cudaGetSymbolAddress((void**)&b.deg,  g_deg);
    cudaGetSymbolAddress((void**)&b.cur,  g_cur);
    cudaGetSymbolAddress((void**)&b.off,  g_off);
    cudaGetSymbolAddress((void**)&b.bsum, g_bsum);
    cudaGetSymbolAddress((void**)&b.srcs, g_srcs);

    cudaFuncSetAttribute(gemm_mma_kernel, cudaFuncAttributeMaxDynamicSharedMemorySize,
                         GEMM_SMEM);

    const int nwarp_grid = (int)(((size_t)N_NODES * 32 + 255) / 256);

    // Launch order keeps gemm_mma at slot 4 for ncu.
    prep_weights(W0, 128, 256, b);                                     // 1
    csr_zero_kernel<<<(N_NODES + 255) / 256, 256>>>(b.deg, b.cur);     // 2
    csr_count_kernel<<<(E_TOT + 255) / 256, 256>>>(ei, b.deg);         // 3
    launch_gemm(x, 128, 256, 64, a_src0, a_dst0, b);                   // 4 (profiled)
    int nblk = (N_NODES + SCAN_B - 1) / SCAN_B;
    scan1_kernel<<<nblk, SCAN_B>>>(b.deg, b.off, b.bsum, N_NODES);     // 5
    scan2_kernel<<<1, 32>>>(b.bsum, nblk);                             // 6
    scan3_kernel<<<(N_NODES + 255) / 256, 256>>>(b.off, b.bsum, N_NODES);        // 7
    csr_scatter_kernel<<<(E_TOT + 255) / 256, 256>>>(ei, b.off, b.cur, b.srcs);  // 8

    // layer 0 aggregate (gemm done above)
    agg_soft_kernel<4, 64, true><<<nwarp_grid, 256>>>(b.off, b.srcs, b.xph,
                                                      b.s, b.d, b0, b.h);
    // layer 1
    prep_weights(W1, 256, 256, b);
    launch_gemm(b.h, 256, 256, 64, a_src1, a_dst1, b);
    agg_soft_kernel<4, 64, true><<<nwarp_grid, 256>>>(b.off, b.srcs, b.xph,
                                                      b.s, b.d, b1, b.h);
    // layer 2 (H=1, C=128 -> atomic score path needs zeroed s/d)
    prep_weights(W2, 256, 128, b);
    init_sd_kernel<<<(N_NODES + 255) / 256, 256>>>(b.s, b.d, N_NODES);
    launch_gemm(b.h, 256, 128, 128, a_src2, a_dst2, b);
    agg_soft_kernel<1, 128, false><<<nwarp_grid, 256>>>(b.off, b.srcs, b.xph,
                                                        b.s, b.d, b2, (float*)d_out);
}

// round 9
// speedup vs baseline: 9.5219x; 1.0211x over previous
#include <cuda_runtime.h>
#include <cuda_fp16.h>
#include <cstdint>

#define N_NODES 50000
#define E_RAW   800000
#define E_TOT   (E_RAW + N_NODES)   // 850000 with self loops
#define MAXH    4
#define MAXHC   256
#define SCAN_B  1024

// ---------------- device scratch (static, allocation-free) ----------------
// g_hh: fp16 layer input/output, padded by 128 rows so GEMM tiles can read
// past M without faulting (pad rows stay zero from module init; never written).
__device__ __half g_hh [(size_t)(N_NODES + 128) * MAXHC];
__device__ __half g_xph[(size_t)N_NODES * MAXHC];   // transformed features, fp16
__device__ __half g_wh [MAXHC * MAXHC];             // W^T [N,K] fp16
__device__ float g_s [(size_t)N_NODES * MAXH];
__device__ float g_d [(size_t)N_NODES * MAXH];
// CSR by destination
__device__ int g_deg [N_NODES];
__device__ int g_cur [N_NODES];
__device__ int g_off [N_NODES + 1];
__device__ int g_bsum[64];
__device__ int g_srcs[E_TOT];

// ---------------- small PTX helpers ----------------
__device__ __forceinline__ uint32_t smem_u32(const void* p) {
    uint32_t a;
    asm("{ .reg .u64 t; cvta.to.shared.u64 t, %1; cvt.u32.u64 %0, t; }" : "=r"(a) : "l"(p));
    return a;
}
__device__ __forceinline__ void ldm_x4(uint32_t& r0, uint32_t& r1, uint32_t& r2, uint32_t& r3,
                                       uint32_t addr) {
    asm volatile("ldmatrix.sync.aligned.m8n8.x4.shared.b16 {%0,%1,%2,%3}, [%4];"
                 : "=r"(r0), "=r"(r1), "=r"(r2), "=r"(r3) : "r"(addr));
}
__device__ __forceinline__ void mma_f16(float* d, const uint32_t* a, uint32_t b0, uint32_t b1) {
    asm volatile(
        "mma.sync.aligned.m16n8k16.row.col.f32.f16.f16.f32 "
        "{%0,%1,%2,%3}, {%4,%5,%6,%7}, {%8,%9}, {%0,%1,%2,%3};"
        : "+f"(d[0]), "+f"(d[1]), "+f"(d[2]), "+f"(d[3])
        : "r"(a[0]), "r"(a[1]), "r"(a[2]), "r"(a[3]), "r"(b0), "r"(b1));
}
__device__ __forceinline__ void cp_async16(uint32_t dst, const void* src) {
    asm volatile("cp.async.ca.shared.global [%0], [%1], 16;" :: "r"(dst), "l"(src));
}
#define CP_COMMIT()  asm volatile("cp.async.commit_group;")
#define CP_WAIT(n)   asm volatile("cp.async.wait_group %0;" :: "n"(n) : "memory")

// ---------------- weight transpose + fp16 convert: Wt[n,k] = W[k,n] ----------------
__global__ void transpose_convert_kernel(const float* __restrict__ W,
                                         __half* __restrict__ Wh,
                                         int K, int N) {
    __shared__ float t[32][33];
    int bn = blockIdx.x * 32, bk = blockIdx.y * 32;
    int x = threadIdx.x, y = threadIdx.y;
    #pragma unroll
    for (int j = 0; j < 32; j += 8) t[y + j][x] = W[(size_t)(bk + y + j) * N + bn + x];
    __syncthreads();
    #pragma unroll
    for (int j = 0; j < 32; j += 8)
        Wh[(size_t)(bn + y + j) * K + bk + x] = __float2half_rn(t[x][y + j]);
}

// ---------------- x (fp32) -> fp16 ----------------
__global__ void conv_x_kernel(const float* __restrict__ x, __half* __restrict__ out, int n2) {
    int i = blockIdx.x * blockDim.x + threadIdx.x;
    if (i < n2) {
        float2 v = *(const float2*)&x[i * 2];
        *(__half2*)&out[i * 2] = __floats2half2_rn(v.x, v.y);
    }
}

// ---------------- zero s/d (only for the atomic score path, C=128) ----------------
__global__ void init_sd_kernel(float* __restrict__ s, float* __restrict__ d, int n) {
    int i = blockIdx.x * blockDim.x + threadIdx.x;
    if (i < n) { s[i] = 0.f; d[i] = 0.f; }
}

// ---------------- fp16 tensor GEMM, all-cp.async, 3-stage pipeline ----------------
// C[M,N](fp16) = A[M,K](fp16) @ Bt[N,K]^T (fp16). Fused score epilogue.
// Block tile 128x128, K-chunk 32. 8 warps (4Mx2N), warp tile 32x64.
#define PITCH    40                   // fp16 per smem row (32 + 8 pad) = 80 bytes
#define TILE_B   (128 * PITCH * 2)    // 10240 bytes per tile
#define NSTAGE   3
#define GEMM_SMEM (NSTAGE * 2 * TILE_B)

__global__ __launch_bounds__(256, 2) void gemm_mma_kernel(const __half* __restrict__ A,
                                                          const __half* __restrict__ Bt,
                                                          __half* __restrict__ C,
                                                          const float* __restrict__ Asrc,
                                                          const float* __restrict__ Adst,
                                                          float* __restrict__ sArr,
                                                          float* __restrict__ dArr,
                                                          int M, int N, int K, int Chead) {
    extern __shared__ __align__(16) char sm[];
    uint32_t base = smem_u32(sm);

    int tid = threadIdx.x, lane = tid & 31, wid = tid >> 5;
    int wm = (wid >> 1) * 32;
    int wn = (wid & 1) * 64;
    int brow = blockIdx.y * 128;
    int bcol = blockIdx.x * 128;

    float acc[2][8][4];
    #pragma unroll
    for (int i = 0; i < 2; i++)
        #pragma unroll
        for (int j = 0; j < 8; j++)
            #pragma unroll
            for (int q = 0; q < 4; q++) acc[i][j][q] = 0.f;

    int a_r = ((lane >> 3) & 1) * 8 + (lane & 7);
    int a_cb = (lane >> 4) * 16;
    int b_r = (lane >> 4) * 8 + (lane & 7);
    int b_cb = ((lane >> 3) & 1) * 16;

    int nch = K >> 5;

    // 128 rows x 32 halves (64B) per tile = 512 x 16B segs; 2 per thread per tile
    auto loadAB = [&](int stage, int ch) {
        int k0 = ch << 5;
        uint32_t sbase = base + (uint32_t)(stage * 2 * TILE_B);
        #pragma unroll
        for (int j = 0; j < 2; j++) {
            int i = tid + j * 256;
            int seg = i & 3, row = i >> 2;
            uint32_t o = (uint32_t)(row * (PITCH * 2) + seg * 16);
            cp_async16(sbase + o, A + (size_t)(brow + row) * K + k0 + seg * 8);
            cp_async16(sbase + TILE_B + o, Bt + (size_t)(bcol + row) * K + k0 + seg * 8);
        }
    };

    #pragma unroll
    for (int s = 0; s < NSTAGE - 1; s++) {
        if (s < nch) { loadAB(s, s); }
        CP_COMMIT();
    }

    for (int ch = 0; ch < nch; ch++) {
        int cur = ch % NSTAGE;
        if (ch == nch - 1) CP_WAIT(0); else CP_WAIT(1);
        __syncthreads();
        uint32_t sA = base + (uint32_t)(cur * 2 * TILE_B);
        uint32_t sB = sA + TILE_B;
        #pragma unroll
        for (int ks = 0; ks < 2; ks++) {
            int kb = ks * 32;
            uint32_t ah[2][4];
            #pragma unroll
            for (int mt = 0; mt < 2; mt++) {
                uint32_t ro = (uint32_t)((wm + mt * 16 + a_r) * (PITCH * 2) + kb + a_cb);
                ldm_x4(ah[mt][0], ah[mt][1], ah[mt][2], ah[mt][3], sA + ro);
            }
            #pragma unroll
            for (int nt = 0; nt < 4; nt++) {
                uint32_t ro = (uint32_t)((wn + nt * 16 + b_r) * (PITCH * 2) + kb + b_cb);
                uint32_t bh[4];
                ldm_x4(bh[0], bh[1], bh[2], bh[3], sB + ro);
                #pragma unroll
                for (int mt = 0; mt < 2; mt++) {
                    mma_f16(acc[mt][nt * 2 + 0], ah[mt], bh[0], bh[1]);
                    mma_f16(acc[mt][nt * 2 + 1], ah[mt], bh[2], bh[3]);
                }
            }
        }
        __syncthreads();                  // all warps done reading stage cur
        int nl = ch + NSTAGE - 1;
        if (nl < nch) { loadAB(nl % NSTAGE, nl); }
        CP_COMMIT();
    }

    // ---- epilogue: write fp16 C + fused attention scores ----
    int er = lane >> 2, ec = (lane & 3) * 2;
    float ps0[2] = {0.f, 0.f}, ps1[2] = {0.f, 0.f};
    float pd0[2] = {0.f, 0.f}, pd1[2] = {0.f, 0.f};
    #pragma unroll
    for (int mt = 0; mt < 2; mt++) {
        int r0 = brow + wm + mt * 16 + er;
        #pragma unroll
        for (int nt = 0; nt < 8; nt++) {
            int gc = bcol + wn + nt * 8 + ec;
            float a0 = Asrc[gc], a1 = Asrc[gc + 1];
            float b0 = Adst[gc], b1 = Adst[gc + 1];
            ps0[mt] += acc[mt][nt][0] * a0 + acc[mt][nt][1] * a1;
            pd0[mt] += acc[mt][nt][0] * b0 + acc[mt][nt][1] * b1;
            ps1[mt] += acc[mt][nt][2] * a0 + acc[mt][nt][3] * a1;
            pd1[mt] += acc[mt][nt][2] * b0 + acc[mt][nt][3] * b1;
            if (r0 < M)
                *(__half2*)&C[(size_t)r0 * N + gc] =
                    __floats2half2_rn(acc[mt][nt][0], acc[mt][nt][1]);
            if (r0 + 8 < M)
                *(__half2*)&C[(size_t)(r0 + 8) * N + gc] =
                    __floats2half2_rn(acc[mt][nt][2], acc[mt][nt][3]);
        }
    }
    #pragma unroll
    for (int o = 1; o <= 2; o <<= 1) {
        #pragma unroll
        for (int mt = 0; mt < 2; mt++) {
            ps0[mt] += __shfl_xor_sync(0xffffffffu, ps0[mt], o);
            ps1[mt] += __shfl_xor_sync(0xffffffffu, ps1[mt], o);
            pd0[mt] += __shfl_xor_sync(0xffffffffu, pd0[mt], o);
            pd1[mt] += __shfl_xor_sync(0xffffffffu, pd1[mt], o);
        }
    }
    if ((lane & 3) == 0) {
        int Hloc = N / Chead;
        int head = (bcol + wn) / Chead;
        #pragma unroll
        for (int mt = 0; mt < 2; mt++) {
            int r0 = brow + wm + mt * 16 + er;
            if (Chead == 64) {
                if (r0 < M)     { sArr[r0 * Hloc + head] = ps0[mt]; dArr[r0 * Hloc + head] = pd0[mt]; }
                if (r0 + 8 < M) { sArr[(r0 + 8) * Hloc + head] = ps1[mt]; dArr[(r0 + 8) * Hloc + head] = pd1[mt]; }
            } else {
                if (r0 < M)     { atomicAdd(&sArr[r0], ps0[mt]); atomicAdd(&dArr[r0], pd0[mt]); }
                if (r0 + 8 < M) { atomicAdd(&sArr[r0 + 8], ps1[mt]); atomicAdd(&dArr[r0 + 8], pd1[mt]); }
            }
        }
    }
}

// ---------------- CSR build ----------------
__device__ __forceinline__ void edge_endpoints(const int* __restrict__ ei, int e,
                                               int& src, int& dst) {
    if (e < E_RAW) { src = ei[e]; dst = ei[E_RAW + e]; }
    else           { src = dst = e - E_RAW; }
}
__global__ void csr_zero_kernel(int* __restrict__ deg, int* __restrict__ cur) {
    int i = blockIdx.x * blockDim.x + threadIdx.x;
    if (i < N_NODES) { deg[i] = 0; cur[i] = 0; }
}
__global__ void csr_count_kernel(const int* __restrict__ ei, int* __restrict__ deg) {
    int e = blockIdx.x * blockDim.x + threadIdx.x;
    if (e >= E_TOT) return;
    int dst = (e < E_RAW) ? ei[E_RAW + e] : e - E_RAW;
    atomicAdd(&deg[dst], 1);
}
__global__ void scan1_kernel(const int* __restrict__ deg, int* __restrict__ off,
                             int* __restrict__ bsum, int n) {
    __shared__ int sm[SCAN_B];
    int i = blockIdx.x * SCAN_B + threadIdx.x;
    int v = (i < n) ? deg[i] : 0;
    sm[threadIdx.x] = v;
    __syncthreads();
    for (int o = 1; o < SCAN_B; o <<= 1) {
        int t = (threadIdx.x >= o) ? sm[threadIdx.x - o] : 0;
        __syncthreads();
        sm[threadIdx.x] += t;
        __syncthreads();
    }
    if (i < n) off[i + 1] = sm[threadIdx.x];
    if (threadIdx.x == SCAN_B - 1) bsum[blockIdx.x] = sm[threadIdx.x];
}
__global__ void scan2_kernel(int* __restrict__ bsum, int nb) {
    if (threadIdx.x == 0) {
        int run = 0;
        for (int b = 0; b < nb; b++) { int t = bsum[b]; bsum[b] = run; run += t; }
    }
}
__global__ void scan3_kernel(int* __restrict__ off, const int* __restrict__ bsum, int n) {
    int i = blockIdx.x * blockDim.x + threadIdx.x;
    if (i == 0) off[0] = 0;
    if (i < n) off[i + 1] += bsum[i / SCAN_B];
}
__global__ void csr_scatter_kernel(const int* __restrict__ ei, const int* __restrict__ off,
                                   int* __restrict__ cur, int* __restrict__ srcs) {
    int e = blockIdx.x * blockDim.x + threadIdx.x;
    if (e >= E_TOT) return;
    int src, dst;
    edge_endpoints(ei, e, src, dst);
    int pos = atomicAdd(&cur[dst], 1);
    srcs[off[dst] + pos] = src;
}

// ---------------- fused aggregate: inline softmax, warp per dst node ----------------
template <int H, int C, bool ELU, typename OutT>
__global__ void agg_soft_kernel(const int* __restrict__ off,
                                const int* __restrict__ srcs,
                                const __half* __restrict__ xp,
                                const float* __restrict__ sArr,
                                const float* __restrict__ dArr,
                                const float* __restrict__ bias,
                                OutT* __restrict__ out) {
    constexpr int HC = H * C;
    constexpr int PER = HC / 32;
    int gw = (blockIdx.x * blockDim.x + threadIdx.x) >> 5;
    int lane = threadIdx.x & 31;
    if (gw >= N_NODES) return;
    int base = lane * PER;
    int head = (H == 1) ? 0 : (lane >> 3);
    float d4 = (lane < H) ? dArr[gw * H + lane] : 0.f;
    int s0 = off[gw], s1 = off[gw + 1];
    float acc[PER];
    #pragma unroll
    for (int j = 0; j < PER; j++) acc[j] = 0.f;
    float z = 0.f;

    auto edge_p = [&](int src) {
        float sv = (lane < H) ? sArr[src * H + lane] : 0.f;
        float v = sv + d4;
        v = v > 0.f ? v : 0.2f * v;
        float p = __expf(fminf(v, 80.f));
        return __shfl_sync(0xffffffffu, p, head);
    };
    auto accum = [&](int src, float pw) {
        if (PER == 8) {
            uint4 u = *(const uint4*)(xp + (size_t)src * HC + base);
            float2 f0 = __half22float2(*(__half2*)&u.x);
            float2 f1 = __half22float2(*(__half2*)&u.y);
            float2 f2 = __half22float2(*(__half2*)&u.z);
            float2 f3 = __half22float2(*(__half2*)&u.w);
            acc[0] = fmaf(f0.x, pw, acc[0]); acc[1] = fmaf(f0.y, pw, acc[1]);
            acc[2] = fmaf(f1.x, pw, acc[2]); acc[3] = fmaf(f1.y, pw, acc[3]);
            acc[4] = fmaf(f2.x, pw, acc[4]); acc[5] = fmaf(f2.y, pw, acc[5]);
            acc[6] = fmaf(f3.x, pw, acc[6]); acc[7] = fmaf(f3.y, pw, acc[7]);
        } else {
            uint2 u = *(const uint2*)(xp + (size_t)src * HC + base);
            float2 f0 = __half22float2(*(__half2*)&u.x);
            float2 f1 = __half22float2(*(__half2*)&u.y);
            acc[0] = fmaf(f0.x, pw, acc[0]); acc[1] = fmaf(f0.y, pw, acc[1]);
            acc[PER > 2 ? 2 : 0] = fmaf(f1.x, pw, acc[PER > 2 ? 2 : 0]);
            acc[PER > 3 ? 3 : 0] = fmaf(f1.y, pw, acc[PER > 3 ? 3 : 0]);
        }
    };

    int t = s0;
    for (; t + 1 < s1; t += 2) {
        int srcA = srcs[t], srcB = srcs[t + 1];
        float pwA = edge_p(srcA);
        float pwB = edge_p(srcB);
        z += pwA + pwB;
        accum(srcA, pwA);
        accum(srcB, pwB);
    }
    if (t < s1) {
        int src = srcs[t];
        float pw = edge_p(src);
        z += pw;
        accum(src, pw);
    }

    float inv = 1.f / (z + 1e-16f);
    OutT* od = out + (size_t)gw * HC + base;
    #pragma unroll
    for (int q = 0; q < PER / 4; q++) {
        float4 r;
        r.x = acc[q * 4 + 0] * inv + bias[base + q * 4 + 0];
        r.y = acc[q * 4 + 1] * inv + bias[base + q * 4 + 1];
        r.z = acc[q * 4 + 2] * inv + bias[base + q * 4 + 2];
        r.w = acc[q * 4 + 3] * inv + bias[base + q * 4 + 3];
        if (ELU) {
            r.x = r.x > 0.f ? r.x : expm1f(r.x);
            r.y = r.y > 0.f ? r.y : expm1f(r.y);
            r.z = r.z > 0.f ? r.z : expm1f(r.z);
            r.w = r.w > 0.f ? r.w : expm1f(r.w);
        }
        if (sizeof(OutT) == 2) {
            __half2* oh = (__half2*)(od + q * 4);
            oh[0] = __floats2half2_rn(r.x, r.y);
            oh[1] = __floats2half2_rn(r.z, r.w);
        } else {
            *(float4*)((float*)od + q * 4) = r;
        }
    }
}

// ---------------- host orchestration ----------------
struct Bufs {
    __half *hh, *xph, *wh;
    float *s, *d;
    int *deg, *cur, *off, *bsum, *srcs;
};

static void prep_weights(const float* W, int K, int HCl, const Bufs& b) {
    dim3 tg(HCl / 32, K / 32);
    transpose_convert_kernel<<<tg, dim3(32, 8)>>>(W, b.wh, K, HCl);
}

static void launch_gemm(const __half* in, int K, int HCl, int Chead,
                        const float* a_src, const float* a_dst, const Bufs& b) {
    dim3 grid(HCl / 128, (N_NODES + 127) / 128);
    gemm_mma_kernel<<<grid, 256, GEMM_SMEM>>>(in, b.wh, b.xph,
                                              a_src, a_dst, b.s, b.d,
                                              N_NODES, HCl, K, Chead);
}

extern "C" void kernel_launch(void* const* d_in, const int* in_sizes, int n_in,
                              void* d_out, int out_size) {
    const float* x      = (const float*)d_in[0];
    const int*   ei     = (const int*)  d_in[1];
    const float* W0     = (const float*)d_in[2];
    const float* a_src0 = (const float*)d_in[3];
    const float* a_dst0 = (const float*)d_in[4];
    const float* b0     = (const float*)d_in[5];
    const float* W1     = (const float*)d_in[6];
    const float* a_src1 = (const float*)d_in[7];
    const float* a_dst1 = (const float*)d_in[8];
    const float* b1     = (const float*)d_in[9];
    const float* W2     = (const float*)d_in[10];
    const float* a_src2 = (const float*)d_in[11];
    const float* a_dst2 = (const float*)d_in[12];
    const float* b2     = (const float*)d_in[13];

    Bufs b;
    cudaGetSymbolAddress((void**)&b.hh,   g_hh);
    cudaGetSymbolAddress((void**)&b.xph,  g_xph);
    cudaGetSymbolAddress((void**)&b.wh,   g_wh);
    cudaGetSymbolAddress((void**)&b.s,    g_s);
    cudaGetSymbolAddress((void**)&b.d,    g_d);
    cudaGetSymbolAddress((void**)&b.deg,  g_deg);
    cudaGetSymbolAddress((void**)&b.cur,  g_cur);
    cudaGetSymbolAddress((void**)&b.off,  g_off);
    cudaGetSymbolAddress((void**)&b.bsum, g_bsum);
    cudaGetSymbolAddress((void**)&b.srcs, g_srcs);

    cudaFuncSetAttribute(gemm_mma_kernel, cudaFuncAttributeMaxDynamicSharedMemorySize,
                         GEMM_SMEM);

    const int nwarp_grid = (int)(((size_t)N_NODES * 32 + 255) / 256);

    // Launch order keeps gemm_mma at slot 4 for ncu.
    prep_weights(W0, 128, 256, b);                                     // 1
    csr_zero_kernel<<<(N_NODES + 255) / 256, 256>>>(b.deg, b.cur);     // 2
    conv_x_kernel<<<(N_NODES * 128 / 2 + 255) / 256, 256>>>(x, b.hh, N_NODES * 128 / 2); // 3
    launch_gemm(b.hh, 128, 256, 64, a_src0, a_dst0, b);                // 4 (profiled)
    csr_count_kernel<<<(E_TOT + 255) / 256, 256>>>(ei, b.deg);         // 5
    int nblk = (N_NODES + SCAN_B - 1) / SCAN_B;
    scan1_kernel<<<nblk, SCAN_B>>>(b.deg, b.off, b.bsum, N_NODES);     // 6
    scan2_kernel<<<1, 32>>>(b.bsum, nblk);                             // 7
    scan3_kernel<<<(N_NODES + 255) / 256, 256>>>(b.off, b.bsum, N_NODES);        // 8
    csr_scatter_kernel<<<(E_TOT + 255) / 256, 256>>>(ei, b.off, b.cur, b.srcs);  // 9

    // layer 0 aggregate -> fp16 hh
    agg_soft_kernel<4, 64, true, __half><<<nwarp_grid, 256>>>(b.off, b.srcs, b.xph,
                                                              b.s, b.d, b0, b.hh);
    // layer 1
    prep_weights(W1, 256, 256, b);
    launch_gemm(b.hh, 256, 256, 64, a_src1, a_dst1, b);
    agg_soft_kernel<4, 64, true, __half><<<nwarp_grid, 256>>>(b.off, b.srcs, b.xph,
                                                              b.s, b.d, b1, b.hh);
    // layer 2 (H=1, C=128 -> atomic score path needs zeroed s/d), fp32 out
    prep_weights(W2, 256, 128, b);
    init_sd_kernel<<<(N_NODES + 255) / 256, 256>>>(b.s, b.d, N_NODES);
    launch_gemm(b.hh, 256, 128, 128, a_src2, a_dst2, b);
    agg_soft_kernel<1, 128, false, float><<<nwarp_grid, 256>>>(b.off, b.srcs, b.xph,
                                                               b.s, b.d, b2, (float*)d_out);
}

// round 10
// speedup vs baseline: 9.5982x; 1.0080x over previous
#include <cuda_runtime.h>
#include <cuda_fp16.h>
#include <cstdint>

#define N_NODES 50000
#define E_RAW   800000
#define E_TOT   (E_RAW + N_NODES)   // 850000 with self loops
#define MAXH    4
#define MAXHC   256
#define SCAN_B  1024

// ---------------- device scratch (static, allocation-free) ----------------
// g_hh: fp16 layer input/output, padded by 128 rows so GEMM tiles can read
// past M without faulting (pad rows never written; contents irrelevant).
__device__ __half g_hh [(size_t)(N_NODES + 128) * MAXHC];
__device__ __half g_xph[(size_t)N_NODES * MAXHC];   // transformed features, fp16
__device__ __half g_wh [3 * MAXHC * MAXHC];         // W^T fp16, all 3 layers
__device__ float g_s [(size_t)N_NODES * MAXH];      // also holds [2][N] partials (layer2)
__device__ float g_d [(size_t)N_NODES * MAXH];
// CSR by destination
__device__ int g_deg [N_NODES];
__device__ int g_cur [N_NODES];
__device__ int g_off [N_NODES + 1];
__device__ int g_bsum[64];
__device__ int g_srcs[E_TOT];

// ---------------- small PTX helpers ----------------
__device__ __forceinline__ uint32_t smem_u32(const void* p) {
    uint32_t a;
    asm("{ .reg .u64 t; cvta.to.shared.u64 t, %1; cvt.u32.u64 %0, t; }" : "=r"(a) : "l"(p));
    return a;
}
__device__ __forceinline__ void ldm_x4(uint32_t& r0, uint32_t& r1, uint32_t& r2, uint32_t& r3,
                                       uint32_t addr) {
    asm volatile("ldmatrix.sync.aligned.m8n8.x4.shared.b16 {%0,%1,%2,%3}, [%4];"
                 : "=r"(r0), "=r"(r1), "=r"(r2), "=r"(r3) : "r"(addr));
}
__device__ __forceinline__ void mma_f16(float* d, const uint32_t* a, uint32_t b0, uint32_t b1) {
    asm volatile(
        "mma.sync.aligned.m16n8k16.row.col.f32.f16.f16.f32 "
        "{%0,%1,%2,%3}, {%4,%5,%6,%7}, {%8,%9}, {%0,%1,%2,%3};"
        : "+f"(d[0]), "+f"(d[1]), "+f"(d[2]), "+f"(d[3])
        : "r"(a[0]), "r"(a[1]), "r"(a[2]), "r"(a[3]), "r"(b0), "r"(b1));
}
__device__ __forceinline__ void cp_async16(uint32_t dst, const void* src) {
    asm volatile("cp.async.ca.shared.global [%0], [%1], 16;" :: "r"(dst), "l"(src));
}
#define CP_COMMIT()  asm volatile("cp.async.commit_group;")
#define CP_WAIT(n)   asm volatile("cp.async.wait_group %0;" :: "n"(n) : "memory")

// ---------------- all-layer weight transpose + fp16 convert ----------------
__global__ void prep_weights_all(const float* __restrict__ W0, const float* __restrict__ W1,
                                 const float* __restrict__ W2, __half* __restrict__ out) {
    __shared__ float t[32][33];
    int layer = blockIdx.z;
    const float* W; int K, N; __half* dst;
    if (layer == 0)      { W = W0; K = 128; N = 256; dst = out; }
    else if (layer == 1) { W = W1; K = 256; N = 256; dst = out + 65536; }
    else                 { W = W2; K = 256; N = 128; dst = out + 131072; }
    int bn = blockIdx.x * 32, bk = blockIdx.y * 32;
    if (bn >= N || bk >= K) return;
    int x = threadIdx.x, y = threadIdx.y;
    #pragma unroll
    for (int j = 0; j < 32; j += 8) t[y + j][x] = W[(size_t)(bk + y + j) * N + bn + x];
    __syncthreads();
    #pragma unroll
    for (int j = 0; j < 32; j += 8)
        dst[(size_t)(bn + y + j) * K + bk + x] = __float2half_rn(t[x][y + j]);
}

// ---------------- x (fp32) -> fp16 ----------------
__global__ void conv_x_kernel(const float* __restrict__ x, __half* __restrict__ out, int n2) {
    int i = blockIdx.x * blockDim.x + threadIdx.x;
    if (i < n2) {
        float2 v = *(const float2*)&x[i * 2];
        *(__half2*)&out[i * 2] = __floats2half2_rn(v.x, v.y);
    }
}

// ---------------- fp16 tensor GEMM, all-cp.async, 4-stage pipeline ----------------
// C[M,N](fp16) = A[M,K](fp16) @ Bt[N,K]^T (fp16). Fused score epilogue.
// Block tile 128x128, K-chunk 32. 8 warps (4Mx2N), warp tile 32x64.
#define PITCH    40                   // fp16 per smem row (32 + 8 pad) = 80 bytes
#define TILE_B   (128 * PITCH * 2)    // 10240 bytes per tile
#define NSTAGE   4
#define GEMM_SMEM (NSTAGE * 2 * TILE_B)

__global__ __launch_bounds__(256, 2) void gemm_mma_kernel(const __half* __restrict__ A,
                                                          const __half* __restrict__ Bt,
                                                          __half* __restrict__ C,
                                                          const float* __restrict__ Asrc,
                                                          const float* __restrict__ Adst,
                                                          float* __restrict__ sArr,
                                                          float* __restrict__ dArr,
                                                          int M, int N, int K, int Chead) {
    extern __shared__ __align__(16) char sm[];
    uint32_t base = smem_u32(sm);

    int tid = threadIdx.x, lane = tid & 31, wid = tid >> 5;
    int wm = (wid >> 1) * 32;
    int wn = (wid & 1) * 64;
    int brow = blockIdx.y * 128;
    int bcol = blockIdx.x * 128;

    float acc[2][8][4];
    #pragma unroll
    for (int i = 0; i < 2; i++)
        #pragma unroll
        for (int j = 0; j < 8; j++)
            #pragma unroll
            for (int q = 0; q < 4; q++) acc[i][j][q] = 0.f;

    int a_r = ((lane >> 3) & 1) * 8 + (lane & 7);
    int a_cb = (lane >> 4) * 16;
    int b_r = (lane >> 4) * 8 + (lane & 7);
    int b_cb = ((lane >> 3) & 1) * 16;

    int nch = K >> 5;

    auto loadAB = [&](int stage, int ch) {
        int k0 = ch << 5;
        uint32_t sbase = base + (uint32_t)(stage * 2 * TILE_B);
        #pragma unroll
        for (int j = 0; j < 2; j++) {
            int i = tid + j * 256;
            int seg = i & 3, row = i >> 2;
            uint32_t o = (uint32_t)(row * (PITCH * 2) + seg * 16);
            cp_async16(sbase + o, A + (size_t)(brow + row) * K + k0 + seg * 8);
            cp_async16(sbase + TILE_B + o, Bt + (size_t)(bcol + row) * K + k0 + seg * 8);
        }
    };

    #pragma unroll
    for (int s = 0; s < NSTAGE - 1; s++) {
        if (s < nch) loadAB(s, s);
        CP_COMMIT();
    }

    for (int ch = 0; ch < nch; ch++) {
        int cur = ch % NSTAGE;
        CP_WAIT(NSTAGE - 2);
        __syncthreads();                       // all warps done with stage (ch-1)%NSTAGE
        int nl = ch + NSTAGE - 1;
        if (nl < nch) loadAB(nl % NSTAGE, nl); // overwrites (ch-1)%NSTAGE — safe post-sync
        CP_COMMIT();
        uint32_t sA = base + (uint32_t)(cur * 2 * TILE_B);
        uint32_t sB = sA + TILE_B;
        #pragma unroll
        for (int ks = 0; ks < 2; ks++) {
            int kb = ks * 32;
            uint32_t ah[2][4];
            #pragma unroll
            for (int mt = 0; mt < 2; mt++) {
                uint32_t ro = (uint32_t)((wm + mt * 16 + a_r) * (PITCH * 2) + kb + a_cb);
                ldm_x4(ah[mt][0], ah[mt][1], ah[mt][2], ah[mt][3], sA + ro);
            }
            #pragma unroll
            for (int nt = 0; nt < 4; nt++) {
                uint32_t ro = (uint32_t)((wn + nt * 16 + b_r) * (PITCH * 2) + kb + b_cb);
                uint32_t bh[4];
                ldm_x4(bh[0], bh[1], bh[2], bh[3], sB + ro);
                #pragma unroll
                for (int mt = 0; mt < 2; mt++) {
                    mma_f16(acc[mt][nt * 2 + 0], ah[mt], bh[0], bh[1]);
                    mma_f16(acc[mt][nt * 2 + 1], ah[mt], bh[2], bh[3]);
                }
            }
        }
    }

    // ---- epilogue: write fp16 C + fused attention scores ----
    int er = lane >> 2, ec = (lane & 3) * 2;
    float ps0[2] = {0.f, 0.f}, ps1[2] = {0.f, 0.f};
    float pd0[2] = {0.f, 0.f}, pd1[2] = {0.f, 0.f};
    #pragma unroll
    for (int mt = 0; mt < 2; mt++) {
        int r0 = brow + wm + mt * 16 + er;
        #pragma unroll
        for (int nt = 0; nt < 8; nt++) {
            int gc = bcol + wn + nt * 8 + ec;
            float a0 = Asrc[gc], a1 = Asrc[gc + 1];
            float b0 = Adst[gc], b1 = Adst[gc + 1];
            ps0[mt] += acc[mt][nt][0] * a0 + acc[mt][nt][1] * a1;
            pd0[mt] += acc[mt][nt][0] * b0 + acc[mt][nt][1] * b1;
            ps1[mt] += acc[mt][nt][2] * a0 + acc[mt][nt][3] * a1;
            pd1[mt] += acc[mt][nt][2] * b0 + acc[mt][nt][3] * b1;
            if (r0 < M)
                *(__half2*)&C[(size_t)r0 * N + gc] =
                    __floats2half2_rn(acc[mt][nt][0], acc[mt][nt][1]);
            if (r0 + 8 < M)
                *(__half2*)&C[(size_t)(r0 + 8) * N + gc] =
                    __floats2half2_rn(acc[mt][nt][2], acc[mt][nt][3]);
        }
    }
    #pragma unroll
    for (int o = 1; o <= 2; o <<= 1) {
        #pragma unroll
        for (int mt = 0; mt < 2; mt++) {
            ps0[mt] += __shfl_xor_sync(0xffffffffu, ps0[mt], o);
            ps1[mt] += __shfl_xor_sync(0xffffffffu, ps1[mt], o);
            pd0[mt] += __shfl_xor_sync(0xffffffffu, pd0[mt], o);
            pd1[mt] += __shfl_xor_sync(0xffffffffu, pd1[mt], o);
        }
    }
    if ((lane & 3) == 0) {
        #pragma unroll
        for (int mt = 0; mt < 2; mt++) {
            int r0 = brow + wm + mt * 16 + er;
            if (Chead == 64) {                    // warp owns a full head: direct store
                int Hloc = N / 64;
                int head = (bcol + wn) / 64;
                if (r0 < M)     { sArr[r0 * Hloc + head] = ps0[mt]; dArr[r0 * Hloc + head] = pd0[mt]; }
                if (r0 + 8 < M) { sArr[(r0 + 8) * Hloc + head] = ps1[mt]; dArr[(r0 + 8) * Hloc + head] = pd1[mt]; }
            } else {                              // head spans 2 warps: per-part partials
                int part = (wn != 0);
                if (r0 < M)     { sArr[part * M + r0] = ps0[mt]; dArr[part * M + r0] = pd0[mt]; }
                if (r0 + 8 < M) { sArr[part * M + r0 + 8] = ps1[mt]; dArr[part * M + r0 + 8] = pd1[mt]; }
            }
        }
    }
}

// ---------------- CSR build ----------------
__device__ __forceinline__ void edge_endpoints(const int* __restrict__ ei, int e,
                                               int& src, int& dst) {
    if (e < E_RAW) { src = ei[e]; dst = ei[E_RAW + e]; }
    else           { src = dst = e - E_RAW; }
}
__global__ void csr_zero_kernel(int* __restrict__ deg, int* __restrict__ cur) {
    int i = blockIdx.x * blockDim.x + threadIdx.x;
    if (i < N_NODES) { deg[i] = 0; cur[i] = 0; }
}
__global__ void csr_count_kernel(const int* __restrict__ ei, int* __restrict__ deg) {
    int e = blockIdx.x * blockDim.x + threadIdx.x;
    if (e >= E_TOT) return;
    int dst = (e < E_RAW) ? ei[E_RAW + e] : e - E_RAW;
    atomicAdd(&deg[dst], 1);
}
__global__ void scan1_kernel(const int* __restrict__ deg, int* __restrict__ off,
                             int* __restrict__ bsum, int n) {
    __shared__ int sm[SCAN_B];
    int i = blockIdx.x * SCAN_B + threadIdx.x;
    int v = (i < n) ? deg[i] : 0;
    sm[threadIdx.x] = v;
    __syncthreads();
    for (int o = 1; o < SCAN_B; o <<= 1) {
        int t = (threadIdx.x >= o) ? sm[threadIdx.x - o] : 0;
        __syncthreads();
        sm[threadIdx.x] += t;
        __syncthreads();
    }
    if (i < n) off[i + 1] = sm[threadIdx.x];
    if (threadIdx.x == SCAN_B - 1) bsum[blockIdx.x] = sm[threadIdx.x];
}
__global__ void scan2_kernel(int* __restrict__ bsum, int nb) {
    if (threadIdx.x == 0) {
        int run = 0;
        for (int b = 0; b < nb; b++) { int t = bsum[b]; bsum[b] = run; run += t; }
    }
}
__global__ void scan3_kernel(int* __restrict__ off, const int* __restrict__ bsum, int n) {
    int i = blockIdx.x * blockDim.x + threadIdx.x;
    if (i == 0) off[0] = 0;
    if (i < n) off[i + 1] += bsum[i / SCAN_B];
}
__global__ void csr_scatter_kernel(const int* __restrict__ ei, const int* __restrict__ off,
                                   int* __restrict__ cur, int* __restrict__ srcs) {
    int e = blockIdx.x * blockDim.x + threadIdx.x;
    if (e >= E_TOT) return;
    int src, dst;
    edge_endpoints(ei, e, src, dst);
    int pos = atomicAdd(&cur[dst], 1);
    srcs[off[dst] + pos] = src;
}

// ---------------- fused aggregate: inline softmax, warp per dst node ----------------
template <int H, int C, bool ELU, typename OutT>
__global__ void agg_soft_kernel(const int* __restrict__ off,
                                const int* __restrict__ srcs,
                                const __half* __restrict__ xp,
                                const float* __restrict__ sArr,
                                const float* __restrict__ dArr,
                                const float* __restrict__ bias,
                                OutT* __restrict__ out) {
    constexpr int HC = H * C;
    constexpr int PER = HC / 32;
    int gw = (blockIdx.x * blockDim.x + threadIdx.x) >> 5;
    int lane = threadIdx.x & 31;
    if (gw >= N_NODES) return;
    int base = lane * PER;
    int head = (H == 1) ? 0 : (lane >> 3);
    float d4;
    if (H == 1)
        d4 = (lane == 0) ? dArr[gw] + dArr[N_NODES + gw] : 0.f;
    else
        d4 = (lane < H) ? dArr[gw * H + lane] : 0.f;
    int s0 = off[gw], s1 = off[gw + 1];
    float acc[PER];
    #pragma unroll
    for (int j = 0; j < PER; j++) acc[j] = 0.f;
    float z = 0.f;

    auto edge_p = [&](int src) {
        float sv;
        if (H == 1)
            sv = (lane == 0) ? sArr[src] + sArr[N_NODES + src] : 0.f;
        else
            sv = (lane < H) ? sArr[src * H + lane] : 0.f;
        float v = sv + d4;
        v = v > 0.f ? v : 0.2f * v;
        float p = __expf(fminf(v, 80.f));
        return __shfl_sync(0xffffffffu, p, head);
    };
    auto accum = [&](int src, float pw) {
        if (PER == 8) {
            uint4 u = *(const uint4*)(xp + (size_t)src * HC + base);
            float2 f0 = __half22float2(*(__half2*)&u.x);
            float2 f1 = __half22float2(*(__half2*)&u.y);
            float2 f2 = __half22float2(*(__half2*)&u.z);
            float2 f3 = __half22float2(*(__half2*)&u.w);
            acc[0] = fmaf(f0.x, pw, acc[0]); acc[1] = fmaf(f0.y, pw, acc[1]);
            acc[2] = fmaf(f1.x, pw, acc[2]); acc[3] = fmaf(f1.y, pw, acc[3]);
            acc[4] = fmaf(f2.x, pw, acc[4]); acc[5] = fmaf(f2.y, pw, acc[5]);
            acc[6] = fmaf(f3.x, pw, acc[6]); acc[7] = fmaf(f3.y, pw, acc[7]);
        } else {
            uint2 u = *(const uint2*)(xp + (size_t)src * HC + base);
            float2 f0 = __half22float2(*(__half2*)&u.x);
            float2 f1 = __half22float2(*(__half2*)&u.y);
            acc[0] = fmaf(f0.x, pw, acc[0]); acc[1] = fmaf(f0.y, pw, acc[1]);
            acc[PER > 2 ? 2 : 0] = fmaf(f1.x, pw, acc[PER > 2 ? 2 : 0]);
            acc[PER > 3 ? 3 : 0] = fmaf(f1.y, pw, acc[PER > 3 ? 3 : 0]);
        }
    };

    int t = s0;
    for (; t + 3 < s1; t += 4) {         // 4-edge unroll for MLP
        int sa = srcs[t], sb = srcs[t + 1], sc = srcs[t + 2], sd = srcs[t + 3];
        float pa = edge_p(sa), pb = edge_p(sb), pc = edge_p(sc), pd = edge_p(sd);
        z += (pa + pb) + (pc + pd);
        accum(sa, pa);
        accum(sb, pb);
        accum(sc, pc);
        accum(sd, pd);
    }
    for (; t < s1; t++) {
        int src = srcs[t];
        float pw = edge_p(src);
        z += pw;
        accum(src, pw);
    }

    float inv = 1.f / (z + 1e-16f);
    OutT* od = out + (size_t)gw * HC + base;
    #pragma unroll
    for (int q = 0; q < PER / 4; q++) {
        float4 r;
        r.x = acc[q * 4 + 0] * inv + bias[base + q * 4 + 0];
        r.y = acc[q * 4 + 1] * inv + bias[base + q * 4 + 1];
        r.z = acc[q * 4 + 2] * inv + bias[base + q * 4 + 2];
        r.w = acc[q * 4 + 3] * inv + bias[base + q * 4 + 3];
        if (ELU) {
            r.x = r.x > 0.f ? r.x : expm1f(r.x);
            r.y = r.y > 0.f ? r.y : expm1f(r.y);
            r.z = r.z > 0.f ? r.z : expm1f(r.z);
            r.w = r.w > 0.f ? r.w : expm1f(r.w);
        }
        if (sizeof(OutT) == 2) {
            __half2* oh = (__half2*)(od + q * 4);
            oh[0] = __floats2half2_rn(r.x, r.y);
            oh[1] = __floats2half2_rn(r.z, r.w);
        } else {
            *(float4*)((float*)od + q * 4) = r;
        }
    }
}

// ---------------- host orchestration ----------------
struct Bufs {
    __half *hh, *xph, *wh;
    float *s, *d;
    int *deg, *cur, *off, *bsum, *srcs;
};

static void launch_gemm(const __half* in, const __half* wh, int K, int HCl, int Chead,
                        const float* a_src, const float* a_dst, const Bufs& b) {
    dim3 grid(HCl / 128, (N_NODES + 127) / 128);
    gemm_mma_kernel<<<grid, 256, GEMM_SMEM>>>(in, wh, b.xph,
                                              a_src, a_dst, b.s, b.d,
                                              N_NODES, HCl, K, Chead);
}

extern "C" void kernel_launch(void* const* d_in, const int* in_sizes, int n_in,
                              void* d_out, int out_size) {
    const float* x      = (const float*)d_in[0];
    const int*   ei     = (const int*)  d_in[1];
    const float* W0     = (const float*)d_in[2];
    const float* a_src0 = (const float*)d_in[3];
    const float* a_dst0 = (const float*)d_in[4];
    const float* b0     = (const float*)d_in[5];
    const float* W1     = (const float*)d_in[6];
    const float* a_src1 = (const float*)d_in[7];
    const float* a_dst1 = (const float*)d_in[8];
    const float* b1     = (const float*)d_in[9];
    const float* W2     = (const float*)d_in[10];
    const float* a_src2 = (const float*)d_in[11];
    const float* a_dst2 = (const float*)d_in[12];
    const float* b2     = (const float*)d_in[13];

    Bufs b;
    cudaGetSymbolAddress((void**)&b.hh,   g_hh);
    cudaGetSymbolAddress((void**)&b.xph,  g_xph);
    cudaGetSymbolAddress((void**)&b.wh,   g_wh);
    cudaGetSymbolAddress((void**)&b.s,    g_s);
    cudaGetSymbolAddress((void**)&b.d,    g_d);
    cudaGetSymbolAddress((void**)&b.deg,  g_deg);
    cudaGetSymbolAddress((void**)&b.cur,  g_cur);
    cudaGetSymbolAddress((void**)&b.off,  g_off);
    cudaGetSymbolAddress((void**)&b.bsum, g_bsum);
    cudaGetSymbolAddress((void**)&b.srcs, g_srcs);

    cudaFuncSetAttribute(gemm_mma_kernel, cudaFuncAttributeMaxDynamicSharedMemorySize,
                         GEMM_SMEM);

    const int nwarp_grid = (int)(((size_t)N_NODES * 32 + 255) / 256);

    // Launch order keeps gemm_mma at slot 4 for ncu.
    prep_weights_all<<<dim3(8, 8, 3), dim3(32, 8)>>>(W0, W1, W2, b.wh);        // 1
    csr_zero_kernel<<<(N_NODES + 255) / 256, 256>>>(b.deg, b.cur);             // 2
    conv_x_kernel<<<(N_NODES * 64 + 255) / 256, 256>>>(x, b.hh, N_NODES * 64); // 3
    launch_gemm(b.hh, b.wh, 128, 256, 64, a_src0, a_dst0, b);                  // 4 (profiled)
    csr_count_kernel<<<(E_TOT + 255) / 256, 256>>>(ei, b.deg);                 // 5
    int nblk = (N_NODES + SCAN_B - 1) / SCAN_B;
    scan1_kernel<<<nblk, SCAN_B>>>(b.deg, b.off, b.bsum, N_NODES);             // 6
    scan2_kernel<<<1, 32>>>(b.bsum, nblk);                                     // 7
    scan3_kernel<<<(N_NODES + 255) / 256, 256>>>(b.off, b.bsum, N_NODES);      // 8
    csr_scatter_kernel<<<(E_TOT + 255) / 256, 256>>>(ei, b.off, b.cur, b.srcs);// 9

    // layer 0 aggregate -> fp16 hh
    agg_soft_kernel<4, 64, true, __half><<<nwarp_grid, 256>>>(b.off, b.srcs, b.xph,
                                                              b.s, b.d, b0, b.hh);
    // layer 1
    launch_gemm(b.hh, b.wh + 65536, 256, 256, 64, a_src1, a_dst1, b);
    agg_soft_kernel<4, 64, true, __half><<<nwarp_grid, 256>>>(b.off, b.srcs, b.xph,
                                                              b.s, b.d, b1, b.hh);
    // layer 2 (H=1, C=128): epilogue writes [2][N] partials, no init needed
    launch_gemm(b.hh, b.wh + 131072, 256, 128, 128, a_src2, a_dst2, b);
    agg_soft_kernel<1, 128, false, float><<<nwarp_grid, 256>>>(b.off, b.srcs, b.xph,
                                                               b.s, b.d, b2, (float*)d_out);
}